// round 7
// baseline (speedup 1.0000x reference)
#include <cuda_runtime.h>
#include <cuda_bf16.h>
#include <math.h>
#include <stdint.h>

#define SEQ    4096
#define HID    4096
#define NHEADS 32
#define NKV    8
#define HD     128

// ---------------- device scratch (allocation-free rule) ----------------
__device__ float g_Q[(size_t)NHEADS * SEQ * HD];  // [head][seq][128]
__device__ float g_K[(size_t)NKV    * SEQ * HD];
__device__ float g_V[(size_t)NKV    * SEQ * HD];
__device__ float g_A[(size_t)SEQ * HID];          // flash out (tf32-rounded)
__device__ float g_rH[(size_t)SEQ * HID];         // tf32-rounded operands
__device__ float g_rWq[(size_t)HID * HID];
__device__ float g_rWk[(size_t)NKV * HD * HID];
__device__ float g_rWv[(size_t)NKV * HD * HID];
__device__ float g_rWo[(size_t)HID * HID];
__device__ __nv_bfloat16 g_Khi[(size_t)NKV * SEQ * HD];  // split K (post-rope)
__device__ __nv_bfloat16 g_Klo[(size_t)NKV * SEQ * HD];
__device__ __nv_bfloat16 g_Vhi[(size_t)NKV * SEQ * HD];
__device__ __nv_bfloat16 g_Vlo[(size_t)NKV * SEQ * HD];

__device__ __forceinline__ unsigned f2tf32(float x) {
    unsigned r;
    asm("cvt.rna.tf32.f32 %0, %1;" : "=r"(r) : "f"(x));
    return r;
}
__device__ __forceinline__ void cp16(uint32_t dst, const void* src) {
    asm volatile("cp.async.cg.shared.global [%0], [%1], 16;"
                 :: "r"(dst), "l"(src) : "memory");
}
__device__ __forceinline__ void cp_commit() {
    asm volatile("cp.async.commit_group;" ::: "memory");
}
__device__ __forceinline__ void cvt_hl(float x, __nv_bfloat16& h, __nv_bfloat16& l) {
    h = __float2bfloat16(x);
    l = __float2bfloat16(x - __bfloat162float(h));
}

// ---------------------------------------------------------------------------
// Pre-round fp32 -> tf32 (rna)
// ---------------------------------------------------------------------------
__global__ __launch_bounds__(256) void round_tf32(const float4* __restrict__ in,
                                                  float4* __restrict__ out, int n4)
{
    int i = blockIdx.x * blockDim.x + threadIdx.x;
    if (i >= n4) return;
    float4 v = in[i];
    v.x = __uint_as_float(f2tf32(v.x));
    v.y = __uint_as_float(f2tf32(v.y));
    v.z = __uint_as_float(f2tf32(v.z));
    v.w = __uint_as_float(f2tf32(v.w));
    out[i] = v;
}

// ---------------------------------------------------------------------------
// fp32 -> (hi, lo) bf16 split (for V)
// ---------------------------------------------------------------------------
__global__ __launch_bounds__(256) void split_kernel(const float4* __restrict__ in,
                                                    __nv_bfloat162* __restrict__ hi,
                                                    __nv_bfloat162* __restrict__ lo,
                                                    int n4)
{
    int i = blockIdx.x * blockDim.x + threadIdx.x;
    if (i >= n4) return;
    float4 v = in[i];
    __nv_bfloat16 h0, l0, h1, l1, h2, l2, h3, l3;
    cvt_hl(v.x, h0, l0); cvt_hl(v.y, h1, l1);
    cvt_hl(v.z, h2, l2); cvt_hl(v.w, h3, l3);
    hi[2 * i]     = __nv_bfloat162(h0, h1);
    hi[2 * i + 1] = __nv_bfloat162(h2, h3);
    lo[2 * i]     = __nv_bfloat162(l0, l1);
    lo[2 * i + 1] = __nv_bfloat162(l2, l3);
}

// ---------------------------------------------------------------------------
// TF32 GEMM v3: 3-stage cp.async pipeline, one __syncthreads per K-iter.
// CTA 128x256, K-tile 32, 8 warps, warp tile 64x64.
// ---------------------------------------------------------------------------
#define GS_A   (128 * 36)
#define GS_B   (256 * 36)
#define GS_ST  (GS_A + GS_B)              // 13824 floats = 55296 B
#define G_SMEM (3 * GS_ST * 4)            // 165888 B

__device__ __forceinline__ void g_fill(uint32_t smb, int buf,
    const float* __restrict__ A, const float* __restrict__ B,
    int bm, int bn, int K, int kt, int tid)
{
    const uint32_t sa = smb + buf * (GS_ST * 4);
    const uint32_t sb = sa + GS_A * 4;
    const size_t kof = (size_t)kt << 5;
    for (int i = tid; i < 1024; i += 256) {
        int row = i >> 3, ch = (i & 7) << 4;
        cp16(sa + row * 144 + ch,
             (const char*)(A + (size_t)(bm + row) * K + kof) + ch);
    }
    for (int i = tid; i < 2048; i += 256) {
        int row = i >> 3, ch = (i & 7) << 4;
        cp16(sb + row * 144 + ch,
             (const char*)(B + (size_t)(bn + row) * K + kof) + ch);
    }
    cp_commit();
}

__global__ __launch_bounds__(256, 1) void gemm_tf32_v2(
    const float* __restrict__ A, const float* __restrict__ B,
    float* __restrict__ C, int M, int N, int K, int mode)
{
    extern __shared__ __align__(16) float sm[];
    const uint32_t smb = (uint32_t)__cvta_generic_to_shared(sm);

    const int tid  = threadIdx.x;
    const int warp = tid >> 5;
    const int lane = tid & 31;
    const int wm   = warp & 1;
    const int wn   = warp >> 1;
    const int g    = lane >> 2;
    const int t4   = lane & 3;
    const int bm   = blockIdx.y * 128;
    const int bn   = blockIdx.x * 256;

    float acc[4][8][4];
#pragma unroll
    for (int mt = 0; mt < 4; mt++)
#pragma unroll
        for (int nt = 0; nt < 8; nt++)
#pragma unroll
            for (int c = 0; c < 4; c++) acc[mt][nt][c] = 0.f;

    const int KT = K >> 5;
    g_fill(smb, 0, A, B, bm, bn, K, 0, tid);
    g_fill(smb, 1, A, B, bm, bn, K, 1, tid);

    int buf = 0;
    for (int kt = 0; kt < KT; kt++) {
        if (kt < KT - 1) {
            asm volatile("cp.async.wait_group 1;" ::: "memory");
        } else {
            asm volatile("cp.async.wait_group 0;" ::: "memory");
        }
        __syncthreads();
        if (kt + 2 < KT) {
            int nb = buf + 2; if (nb >= 3) nb -= 3;
            g_fill(smb, nb, A, B, bm, bn, K, kt + 2, tid);
        }

        const float* As = sm + buf * GS_ST;
        const float* Bs = As + GS_A;

#pragma unroll
        for (int ks = 0; ks < 4; ks++) {
            const int kk = ks * 8;
            unsigned af[4][4], bf[8][2];
#pragma unroll
            for (int mt = 0; mt < 4; mt++) {
                int r = wm * 64 + mt * 16;
                af[mt][0] = __float_as_uint(As[(r + g)     * 36 + kk + t4]);
                af[mt][1] = __float_as_uint(As[(r + g + 8) * 36 + kk + t4]);
                af[mt][2] = __float_as_uint(As[(r + g)     * 36 + kk + t4 + 4]);
                af[mt][3] = __float_as_uint(As[(r + g + 8) * 36 + kk + t4 + 4]);
            }
#pragma unroll
            for (int nt = 0; nt < 8; nt++) {
                int c = wn * 64 + nt * 8;
                bf[nt][0] = __float_as_uint(Bs[(c + g) * 36 + kk + t4]);
                bf[nt][1] = __float_as_uint(Bs[(c + g) * 36 + kk + t4 + 4]);
            }
#pragma unroll
            for (int mt = 0; mt < 4; mt++)
#pragma unroll
                for (int nt = 0; nt < 8; nt++) {
                    asm volatile(
                        "mma.sync.aligned.m16n8k8.row.col.f32.tf32.tf32.f32 "
                        "{%0,%1,%2,%3}, {%4,%5,%6,%7}, {%8,%9}, {%0,%1,%2,%3};"
                        : "+f"(acc[mt][nt][0]), "+f"(acc[mt][nt][1]),
                          "+f"(acc[mt][nt][2]), "+f"(acc[mt][nt][3])
                        : "r"(af[mt][0]), "r"(af[mt][1]),
                          "r"(af[mt][2]), "r"(af[mt][3]),
                          "r"(bf[nt][0]), "r"(bf[nt][1]));
                }
        }
        if (++buf == 3) buf = 0;
    }

#pragma unroll
    for (int mt = 0; mt < 4; mt++) {
#pragma unroll
        for (int nt = 0; nt < 8; nt++) {
            int row = bm + wm * 64 + mt * 16 + g;
            int col = bn + wn * 64 + nt * 8 + 2 * t4;
            if (mode == 0) {
                *(float2*)(C + (size_t)row * N + col) =
                    make_float2(acc[mt][nt][0], acc[mt][nt][1]);
                *(float2*)(C + (size_t)(row + 8) * N + col) =
                    make_float2(acc[mt][nt][2], acc[mt][nt][3]);
            } else {
                int h = col >> 7, d = col & 127;
                *(float2*)(C + ((size_t)h * M + row) * HD + d) =
                    make_float2(acc[mt][nt][0], acc[mt][nt][1]);
                *(float2*)(C + ((size_t)h * M + row + 8) * HD + d) =
                    make_float2(acc[mt][nt][2], acc[mt][nt][3]);
            }
        }
    }
}

// ---------------------------------------------------------------------------
// RoPE: Q in place (fp32); K -> split hi/lo bf16 global
// ---------------------------------------------------------------------------
__global__ __launch_bounds__(256) void rope_kernel(float* __restrict__ Q,
                                                   const float* __restrict__ Kc,
                                                   __nv_bfloat16* __restrict__ Khi,
                                                   __nv_bfloat16* __restrict__ Klo,
                                                   const int* __restrict__ pos)
{
    int idx = blockIdx.x * blockDim.x + threadIdx.x;
    int d = idx & 63;
    int s = (idx >> 6) & (SEQ - 1);
    int h = idx >> 18;

    double ang = (double)pos[s] * exp(-(double)d * (9.210340371976184 / 64.0));
    float c  = (float)cos(ang);
    float si = (float)sin(ang);

    if (h < NHEADS) {
        float* base = Q + ((size_t)h * SEQ + s) * HD;
        float x1 = base[d], x2 = base[d + 64];
        base[d]      = x1 * c - x2 * si;
        base[d + 64] = x2 * c + x1 * si;
    } else {
        size_t o = ((size_t)(h - NHEADS) * SEQ + s) * HD;
        float x1 = Kc[o + d], x2 = Kc[o + d + 64];
        float r1 = x1 * c - x2 * si;
        float r2 = x2 * c + x1 * si;
        __nv_bfloat16 hh, ll;
        cvt_hl(r1, hh, ll); Khi[o + d] = hh;       Klo[o + d] = ll;
        cvt_hl(r2, hh, ll); Khi[o + d + 64] = hh;  Klo[o + d + 64] = ll;
    }
}

// ---------------------------------------------------------------------------
// flash v3: q-tile 128, kv-tile 64, 256 thr, one sync per iter,
// base-2 online softmax (exp2f). bf16x3 mma.
// ---------------------------------------------------------------------------
#define LDB 136

__device__ __forceinline__ void ldsm4(uint32_t a[4], uint32_t addr) {
    asm volatile("ldmatrix.sync.aligned.m8n8.x4.shared.b16 {%0,%1,%2,%3}, [%4];"
        : "=r"(a[0]), "=r"(a[1]), "=r"(a[2]), "=r"(a[3]) : "r"(addr));
}
__device__ __forceinline__ void ldsm4t(uint32_t a[4], uint32_t addr) {
    asm volatile("ldmatrix.sync.aligned.m8n8.x4.trans.shared.b16 {%0,%1,%2,%3}, [%4];"
        : "=r"(a[0]), "=r"(a[1]), "=r"(a[2]), "=r"(a[3]) : "r"(addr));
}
__device__ __forceinline__ void mma_bf16(float c[4], const uint32_t a[4],
                                         uint32_t b0, uint32_t b1) {
    asm volatile(
        "mma.sync.aligned.m16n8k16.row.col.f32.bf16.bf16.f32 "
        "{%0,%1,%2,%3}, {%4,%5,%6,%7}, {%8,%9}, {%0,%1,%2,%3};"
        : "+f"(c[0]), "+f"(c[1]), "+f"(c[2]), "+f"(c[3])
        : "r"(a[0]), "r"(a[1]), "r"(a[2]), "r"(a[3]), "r"(b0), "r"(b1));
}
__device__ __forceinline__ uint32_t pack_bf16(float lo, float hi) {
    uint32_t r;
    asm("cvt.rn.bf16x2.f32 %0, %1, %2;" : "=r"(r) : "f"(hi), "f"(lo));
    return r;
}
__device__ __forceinline__ void split_pack(float x0, float x1,
                                           uint32_t& hi, uint32_t& lo) {
    __nv_bfloat16 h0 = __float2bfloat16(x0), h1 = __float2bfloat16(x1);
    hi = ((uint32_t)__bfloat16_as_ushort(h1) << 16) | __bfloat16_as_ushort(h0);
    lo = pack_bf16(x0 - __bfloat162float(h0), x1 - __bfloat162float(h1));
}

#define F_QT_B  (128 * LDB * 2)
#define F_KT_B  (64 * LDB * 2)
#define F_STG_B (4 * F_KT_B)
#define F_SMEM  (2 * F_QT_B + 2 * F_STG_B)   // 208896

__device__ __forceinline__ void f_fill(uint32_t stg,
    const __nv_bfloat16* Khi_g, const __nv_bfloat16* Klo_g,
    const __nv_bfloat16* Vhi_g, const __nv_bfloat16* Vlo_g,
    int kvh, int kb, int tid)
{
    const size_t gof = ((size_t)kvh * SEQ + (size_t)kb * 64) * HD;
    const char* kh = (const char*)(Khi_g + gof);
    const char* kl = (const char*)(Klo_g + gof);
    const char* vh = (const char*)(Vhi_g + gof);
    const char* vl = (const char*)(Vlo_g + gof);
    for (int i = tid; i < 1024; i += 256) {
        int row = i >> 4, ch = (i & 15) << 4;
        uint32_t dst = row * (LDB * 2) + ch;
        int src = row * 256 + ch;
        cp16(stg + dst,               kh + src);
        cp16(stg + F_KT_B + dst,      kl + src);
        cp16(stg + 2 * F_KT_B + dst,  vh + src);
        cp16(stg + 3 * F_KT_B + dst,  vl + src);
    }
    cp_commit();
}

__global__ __launch_bounds__(256, 1) void flash_v2(
    const float* __restrict__ Q,
    const __nv_bfloat16* __restrict__ Khi_g, const __nv_bfloat16* __restrict__ Klo_g,
    const __nv_bfloat16* __restrict__ Vhi_g, const __nv_bfloat16* __restrict__ Vlo_g,
    float* __restrict__ Out)
{
    extern __shared__ __align__(16) char smem_raw[];
    const uint32_t smb  = (uint32_t)__cvta_generic_to_shared(smem_raw);
    const uint32_t q_hi = smb, q_lo = smb + F_QT_B;
    const uint32_t stg0 = smb + 2 * F_QT_B;

    const int tid  = threadIdx.x;
    const int wid  = tid >> 5;
    const int lane = tid & 31;
    const int g    = lane >> 2;
    const int t    = lane & 3;
    const int qb   = gridDim.x - 1 - blockIdx.x;
    const int h    = blockIdx.y;
    const int kvh  = h >> 2;

    // ---- Q load + split into smem ----
    {
        const float4* Q4 = (const float4*)(Q + ((size_t)h * SEQ + (size_t)qb * 128) * HD);
        __nv_bfloat16* Qh = (__nv_bfloat16*)smem_raw;
        __nv_bfloat16* Ql = (__nv_bfloat16*)(smem_raw + F_QT_B);
        for (int f = tid; f < 4096; f += 256) {
            int row = f >> 5, d0 = (f & 31) << 2;
            float4 q = Q4[f];
            __nv_bfloat16 h0, l0, h1, l1, h2, l2, h3, l3;
            cvt_hl(q.x, h0, l0); cvt_hl(q.y, h1, l1);
            cvt_hl(q.z, h2, l2); cvt_hl(q.w, h3, l3);
            int o = row * LDB + d0;
            *(__nv_bfloat162*)&Qh[o]     = __nv_bfloat162(h0, h1);
            *(__nv_bfloat162*)&Qh[o + 2] = __nv_bfloat162(h2, h3);
            *(__nv_bfloat162*)&Ql[o]     = __nv_bfloat162(l0, l1);
            *(__nv_bfloat162*)&Ql[o + 2] = __nv_bfloat162(l2, l3);
        }
    }

    const int a_row = wid * 16 + (lane & 15);
    const int a_col = (lane >> 4) << 3;
    const int kb_row = (lane & 7) + (((lane >> 4) & 1) << 3);
    const int kb_col = ((lane >> 3) & 1) << 3;
    const int v_row  = (lane & 7) + (((lane >> 3) & 1) << 3);
    const int v_col  = (lane >> 4) << 3;

    float o_[16][4];
    float m0 = -INFINITY, m1 = -INFINITY, l0 = 0.f, l1 = 0.f;
#pragma unroll
    for (int j = 0; j < 16; j++)
#pragma unroll
        for (int c = 0; c < 4; c++) o_[j][c] = 0.f;

    // 1/sqrt(128) * log2(e): softmax runs in base-2 domain
    const float scale2 = 0.12751791437073365f;
    const int rl0 = wid * 16 + g;
    const int rl1 = rl0 + 8;

    const int nkb = 2 * qb + 2;
    f_fill(stg0, Khi_g, Klo_g, Vhi_g, Vlo_g, kvh, 0, tid);

    for (int kb = 0; kb < nkb; kb++) {
        const int buf = kb & 1;
        asm volatile("cp.async.wait_group 0;" ::: "memory");
        __syncthreads();
        if (kb + 1 < nkb)
            f_fill(stg0 + (buf ^ 1) * F_STG_B, Khi_g, Klo_g, Vhi_g, Vlo_g,
                   kvh, kb + 1, tid);

        const int kofs = kb * 64 - qb * 128;
        if (kofs <= wid * 16 + 15) {
            const uint32_t khi_s = stg0 + buf * F_STG_B;
            const uint32_t klo_s = khi_s + F_KT_B;
            const uint32_t vhi_s = khi_s + 2 * F_KT_B;
            const uint32_t vlo_s = khi_s + 3 * F_KT_B;

            float sc[8][4];
#pragma unroll
            for (int j = 0; j < 8; j++)
#pragma unroll
                for (int c = 0; c < 4; c++) sc[j][c] = 0.f;

#pragma unroll
            for (int ks = 0; ks < 8; ks++) {
                uint32_t ahf[4], alf[4];
                uint32_t aoff = ((a_row * LDB) + (ks * 16 + a_col)) * 2;
                ldsm4(ahf, q_hi + aoff);
                ldsm4(alf, q_lo + aoff);
#pragma unroll
                for (int jp = 0; jp < 4; jp++) {
                    uint32_t bh[4], bl[4];
                    uint32_t boff = (((jp * 16 + kb_row) * LDB)
                                     + (ks * 16 + kb_col)) * 2;
                    ldsm4(bh, khi_s + boff);
                    ldsm4(bl, klo_s + boff);
                    mma_bf16(sc[2 * jp],     ahf, bh[0], bh[1]);
                    mma_bf16(sc[2 * jp],     ahf, bl[0], bl[1]);
                    mma_bf16(sc[2 * jp],     alf, bh[0], bh[1]);
                    mma_bf16(sc[2 * jp + 1], ahf, bh[2], bh[3]);
                    mma_bf16(sc[2 * jp + 1], ahf, bl[2], bl[3]);
                    mma_bf16(sc[2 * jp + 1], alf, bh[2], bh[3]);
                }
            }

            const bool diag = (kofs + 63 > rl0);
            float tm0 = -INFINITY, tm1 = -INFINITY;
#pragma unroll
            for (int j = 0; j < 8; j++) {
                float v0 = sc[j][0] * scale2, v1 = sc[j][1] * scale2;
                float v2 = sc[j][2] * scale2, v3 = sc[j][3] * scale2;
                if (diag) {
                    int c0 = kofs + 8 * j + 2 * t;
                    if (c0     > rl0) v0 = -INFINITY;
                    if (c0 + 1 > rl0) v1 = -INFINITY;
                    if (c0     > rl1) v2 = -INFINITY;
                    if (c0 + 1 > rl1) v3 = -INFINITY;
                }
                sc[j][0] = v0; sc[j][1] = v1; sc[j][2] = v2; sc[j][3] = v3;
                tm0 = fmaxf(tm0, fmaxf(v0, v1));
                tm1 = fmaxf(tm1, fmaxf(v2, v3));
            }
            tm0 = fmaxf(tm0, __shfl_xor_sync(0xffffffffu, tm0, 1));
            tm0 = fmaxf(tm0, __shfl_xor_sync(0xffffffffu, tm0, 2));
            tm1 = fmaxf(tm1, __shfl_xor_sync(0xffffffffu, tm1, 1));
            tm1 = fmaxf(tm1, __shfl_xor_sync(0xffffffffu, tm1, 2));

            float mn0 = fmaxf(m0, tm0), mn1 = fmaxf(m1, tm1);
            float al0 = exp2f(m0 - mn0), al1 = exp2f(m1 - mn1);
            m0 = mn0; m1 = mn1;

            float rs0 = 0.f, rs1 = 0.f;
#pragma unroll
            for (int j = 0; j < 8; j++) {
                sc[j][0] = exp2f(sc[j][0] - mn0);
                sc[j][1] = exp2f(sc[j][1] - mn0);
                sc[j][2] = exp2f(sc[j][2] - mn1);
                sc[j][3] = exp2f(sc[j][3] - mn1);
                rs0 += sc[j][0] + sc[j][1];
                rs1 += sc[j][2] + sc[j][3];
            }
            rs0 += __shfl_xor_sync(0xffffffffu, rs0, 1);
            rs0 += __shfl_xor_sync(0xffffffffu, rs0, 2);
            rs1 += __shfl_xor_sync(0xffffffffu, rs1, 1);
            rs1 += __shfl_xor_sync(0xffffffffu, rs1, 2);
            l0 = l0 * al0 + rs0;
            l1 = l1 * al1 + rs1;

#pragma unroll
            for (int j = 0; j < 16; j++) {
                o_[j][0] *= al0; o_[j][1] *= al0;
                o_[j][2] *= al1; o_[j][3] *= al1;
            }

            uint32_t pah[4][4], pal[4][4];
#pragma unroll
            for (int kc = 0; kc < 4; kc++) {
                int j0 = 2 * kc, j1 = j0 + 1;
                split_pack(sc[j0][0], sc[j0][1], pah[kc][0], pal[kc][0]);
                split_pack(sc[j0][2], sc[j0][3], pah[kc][1], pal[kc][1]);
                split_pack(sc[j1][0], sc[j1][1], pah[kc][2], pal[kc][2]);
                split_pack(sc[j1][2], sc[j1][3], pah[kc][3], pal[kc][3]);
            }

#pragma unroll
            for (int kc = 0; kc < 4; kc++) {
#pragma unroll
                for (int jp = 0; jp < 8; jp++) {
                    uint32_t vh[4], vl[4];
                    uint32_t voff = (((kc * 16 + v_row) * LDB)
                                     + (jp * 16 + v_col)) * 2;
                    ldsm4t(vh, vhi_s + voff);
                    ldsm4t(vl, vlo_s + voff);
                    mma_bf16(o_[2 * jp],     pah[kc], vh[0], vh[1]);
                    mma_bf16(o_[2 * jp],     pah[kc], vl[0], vl[1]);
                    mma_bf16(o_[2 * jp],     pal[kc], vh[0], vh[1]);
                    mma_bf16(o_[2 * jp + 1], pah[kc], vh[2], vh[3]);
                    mma_bf16(o_[2 * jp + 1], pah[kc], vl[2], vl[3]);
                    mma_bf16(o_[2 * jp + 1], pal[kc], vh[2], vh[3]);
                }
            }
        }
    }

    float inv0 = 1.f / l0, inv1 = 1.f / l1;
    size_t r0 = (size_t)qb * 128 + wid * 16 + g;
    float* base0 = Out + r0 * HID + (size_t)h * HD;
    float* base1 = base0 + (size_t)8 * HID;
#pragma unroll
    for (int j = 0; j < 16; j++) {
        int col = 8 * j + 2 * t;
        *(float2*)(base0 + col) = make_float2(
            __uint_as_float(f2tf32(o_[j][0] * inv0)),
            __uint_as_float(f2tf32(o_[j][1] * inv0)));
        *(float2*)(base1 + col) = make_float2(
            __uint_as_float(f2tf32(o_[j][2] * inv1)),
            __uint_as_float(f2tf32(o_[j][3] * inv1)));
    }
}

// ---------------------------------------------------------------------------
extern "C" void kernel_launch(void* const* d_in, const int* in_sizes, int n_in,
                              void* d_out, int out_size)
{
    const float* Hs = (const float*)d_in[0];
    const float* Wq = (const float*)d_in[1];
    const float* Wk = (const float*)d_in[2];
    const float* Wv = (const float*)d_in[3];
    const float* Wo = (const float*)d_in[4];
    const int*  pos = (const int*)d_in[5];
    float* out = (float*)d_out;

    float *Qp, *Kp, *Vp, *Ap, *rH, *rWq, *rWk, *rWv, *rWo;
    __nv_bfloat16 *Khi, *Klo, *Vhi, *Vlo;
    cudaGetSymbolAddress((void**)&Qp,  g_Q);
    cudaGetSymbolAddress((void**)&Kp,  g_K);
    cudaGetSymbolAddress((void**)&Vp,  g_V);
    cudaGetSymbolAddress((void**)&Ap,  g_A);
    cudaGetSymbolAddress((void**)&rH,  g_rH);
    cudaGetSymbolAddress((void**)&rWq, g_rWq);
    cudaGetSymbolAddress((void**)&rWk, g_rWk);
    cudaGetSymbolAddress((void**)&rWv, g_rWv);
    cudaGetSymbolAddress((void**)&rWo, g_rWo);
    cudaGetSymbolAddress((void**)&Khi, g_Khi);
    cudaGetSymbolAddress((void**)&Klo, g_Klo);
    cudaGetSymbolAddress((void**)&Vhi, g_Vhi);
    cudaGetSymbolAddress((void**)&Vlo, g_Vlo);

    cudaFuncSetAttribute(flash_v2, cudaFuncAttributeMaxDynamicSharedMemorySize,
                         F_SMEM);
    cudaFuncSetAttribute(gemm_tf32_v2, cudaFuncAttributeMaxDynamicSharedMemorySize,
                         G_SMEM);

    const int nH4 = SEQ * HID / 4, nW4 = HID * HID / 4, nKV4 = NKV * HD * HID / 4;
    round_tf32<<<nH4 / 256, 256>>>((const float4*)Hs, (float4*)rH, nH4);
    round_tf32<<<nW4 / 256, 256>>>((const float4*)Wq, (float4*)rWq, nW4);
    round_tf32<<<nKV4 / 256, 256>>>((const float4*)Wk, (float4*)rWk, nKV4);
    round_tf32<<<nKV4 / 256, 256>>>((const float4*)Wv, (float4*)rWv, nKV4);
    round_tf32<<<nW4 / 256, 256>>>((const float4*)Wo, (float4*)rWo, nW4);

    gemm_tf32_v2<<<dim3(HID / 256, SEQ / 128), 256, G_SMEM>>>(rH, rWq, Qp,
                                                              SEQ, HID, HID, 1);
    gemm_tf32_v2<<<dim3(NKV * HD / 256, SEQ / 128), 256, G_SMEM>>>(rH, rWk, Kp,
                                                                   SEQ, NKV * HD, HID, 1);
    gemm_tf32_v2<<<dim3(NKV * HD / 256, SEQ / 128), 256, G_SMEM>>>(rH, rWv, Vp,
                                                                   SEQ, NKV * HD, HID, 1);

    rope_kernel<<<((NHEADS + NKV) * SEQ * 64) / 256, 256>>>(Qp, Kp, Khi, Klo, pos);

    const int nV4 = NKV * SEQ * HD / 4;
    split_kernel<<<nV4 / 256, 256>>>((const float4*)Vp,
        (__nv_bfloat162*)Vhi, (__nv_bfloat162*)Vlo, nV4);

    flash_v2<<<dim3(SEQ / 128, NHEADS), 256, F_SMEM>>>(Qp, Khi, Klo, Vhi, Vlo, Ap);

    gemm_tf32_v2<<<dim3(HID / 256, SEQ / 128), 256, G_SMEM>>>(Ap, rWo, out,
                                                              SEQ, HID, HID, 0);
}

// round 8
// speedup vs baseline: 1.0013x; 1.0013x over previous
#include <cuda_runtime.h>
#include <cuda_bf16.h>
#include <math.h>
#include <stdint.h>

#define SEQ    4096
#define HID    4096
#define NHEADS 32
#define NKV    8
#define HD     128

// ---------------- device scratch (allocation-free rule) ----------------
__device__ float g_Q[(size_t)NHEADS * SEQ * HD];      // [head][seq][128]
__device__ float g_KV[(size_t)2 * NKV * SEQ * HD];    // K heads 0-7, V heads 8-15
__device__ float g_A[(size_t)SEQ * HID];              // flash out (tf32-rounded)
__device__ float g_rH[(size_t)SEQ * HID];             // tf32-rounded operands
__device__ float g_rWq[(size_t)HID * HID];
__device__ float g_rWkv[(size_t)2 * NKV * HD * HID];  // Wk rows 0-1023, Wv 1024-2047
__device__ float g_rWo[(size_t)HID * HID];
__device__ __nv_bfloat16 g_Khi[(size_t)NKV * SEQ * HD];  // split K (post-rope)
__device__ __nv_bfloat16 g_Klo[(size_t)NKV * SEQ * HD];
__device__ __nv_bfloat16 g_Vhi[(size_t)NKV * SEQ * HD];
__device__ __nv_bfloat16 g_Vlo[(size_t)NKV * SEQ * HD];

__device__ __forceinline__ unsigned f2tf32(float x) {
    unsigned r;
    asm("cvt.rna.tf32.f32 %0, %1;" : "=r"(r) : "f"(x));
    return r;
}
__device__ __forceinline__ float ex2a(float x) {          // guaranteed MUFU
    float y;
    asm("ex2.approx.f32 %0, %1;" : "=f"(y) : "f"(x));
    return y;
}
__device__ __forceinline__ float rcpa(float x) {
    float y;
    asm("rcp.approx.f32 %0, %1;" : "=f"(y) : "f"(x));
    return y;
}
__device__ __forceinline__ void cp16(uint32_t dst, const void* src) {
    asm volatile("cp.async.cg.shared.global [%0], [%1], 16;"
                 :: "r"(dst), "l"(src) : "memory");
}
__device__ __forceinline__ void cp_commit() {
    asm volatile("cp.async.commit_group;" ::: "memory");
}
__device__ __forceinline__ void cvt_hl(float x, __nv_bfloat16& h, __nv_bfloat16& l) {
    h = __float2bfloat16(x);
    l = __float2bfloat16(x - __bfloat162float(h));
}

// ---------------------------------------------------------------------------
// Pre-round fp32 -> tf32 (rna)
// ---------------------------------------------------------------------------
__global__ __launch_bounds__(256) void round_tf32(const float4* __restrict__ in,
                                                  float4* __restrict__ out, int n4)
{
    int i = blockIdx.x * blockDim.x + threadIdx.x;
    if (i >= n4) return;
    float4 v = in[i];
    v.x = __uint_as_float(f2tf32(v.x));
    v.y = __uint_as_float(f2tf32(v.y));
    v.z = __uint_as_float(f2tf32(v.z));
    v.w = __uint_as_float(f2tf32(v.w));
    out[i] = v;
}

// ---------------------------------------------------------------------------
// fp32 -> (hi, lo) bf16 split (for V)
// ---------------------------------------------------------------------------
__global__ __launch_bounds__(256) void split_kernel(const float4* __restrict__ in,
                                                    __nv_bfloat162* __restrict__ hi,
                                                    __nv_bfloat162* __restrict__ lo,
                                                    int n4)
{
    int i = blockIdx.x * blockDim.x + threadIdx.x;
    if (i >= n4) return;
    float4 v = in[i];
    __nv_bfloat16 h0, l0, h1, l1, h2, l2, h3, l3;
    cvt_hl(v.x, h0, l0); cvt_hl(v.y, h1, l1);
    cvt_hl(v.z, h2, l2); cvt_hl(v.w, h3, l3);
    hi[2 * i]     = __nv_bfloat162(h0, h1);
    hi[2 * i + 1] = __nv_bfloat162(h2, h3);
    lo[2 * i]     = __nv_bfloat162(l0, l1);
    lo[2 * i + 1] = __nv_bfloat162(l2, l3);
}

// ---------------------------------------------------------------------------
// TF32 GEMM: 3-stage cp.async pipeline, one __syncthreads per K-iter.
// CTA 128x256, K-tile 32, 8 warps, warp tile 64x64.
// mode 0: C[row*N+col] ; mode 1: head scatter C[((col>>7)*M+row)*128+(col&127)]
// ---------------------------------------------------------------------------
#define GS_A   (128 * 36)
#define GS_B   (256 * 36)
#define GS_ST  (GS_A + GS_B)              // 13824 floats = 55296 B
#define G_SMEM (3 * GS_ST * 4)            // 165888 B

__device__ __forceinline__ void g_fill(uint32_t smb, int buf,
    const float* __restrict__ A, const float* __restrict__ B,
    int bm, int bn, int K, int kt, int tid)
{
    const uint32_t sa = smb + buf * (GS_ST * 4);
    const uint32_t sb = sa + GS_A * 4;
    const size_t kof = (size_t)kt << 5;
    for (int i = tid; i < 1024; i += 256) {
        int row = i >> 3, ch = (i & 7) << 4;
        cp16(sa + row * 144 + ch,
             (const char*)(A + (size_t)(bm + row) * K + kof) + ch);
    }
    for (int i = tid; i < 2048; i += 256) {
        int row = i >> 3, ch = (i & 7) << 4;
        cp16(sb + row * 144 + ch,
             (const char*)(B + (size_t)(bn + row) * K + kof) + ch);
    }
    cp_commit();
}

__global__ __launch_bounds__(256, 1) void gemm_tf32_v2(
    const float* __restrict__ A, const float* __restrict__ B,
    float* __restrict__ C, int M, int N, int K, int mode)
{
    extern __shared__ __align__(16) float sm[];
    const uint32_t smb = (uint32_t)__cvta_generic_to_shared(sm);

    const int tid  = threadIdx.x;
    const int warp = tid >> 5;
    const int lane = tid & 31;
    const int wm   = warp & 1;
    const int wn   = warp >> 1;
    const int g    = lane >> 2;
    const int t4   = lane & 3;
    const int bm   = blockIdx.y * 128;
    const int bn   = blockIdx.x * 256;

    float acc[4][8][4];
#pragma unroll
    for (int mt = 0; mt < 4; mt++)
#pragma unroll
        for (int nt = 0; nt < 8; nt++)
#pragma unroll
            for (int c = 0; c < 4; c++) acc[mt][nt][c] = 0.f;

    const int KT = K >> 5;
    g_fill(smb, 0, A, B, bm, bn, K, 0, tid);
    g_fill(smb, 1, A, B, bm, bn, K, 1, tid);

    int buf = 0;
    for (int kt = 0; kt < KT; kt++) {
        if (kt < KT - 1) {
            asm volatile("cp.async.wait_group 1;" ::: "memory");
        } else {
            asm volatile("cp.async.wait_group 0;" ::: "memory");
        }
        __syncthreads();
        if (kt + 2 < KT) {
            int nb = buf + 2; if (nb >= 3) nb -= 3;
            g_fill(smb, nb, A, B, bm, bn, K, kt + 2, tid);
        }

        const float* As = sm + buf * GS_ST;
        const float* Bs = As + GS_A;

#pragma unroll
        for (int ks = 0; ks < 4; ks++) {
            const int kk = ks * 8;
            unsigned af[4][4], bf[8][2];
#pragma unroll
            for (int mt = 0; mt < 4; mt++) {
                int r = wm * 64 + mt * 16;
                af[mt][0] = __float_as_uint(As[(r + g)     * 36 + kk + t4]);
                af[mt][1] = __float_as_uint(As[(r + g + 8) * 36 + kk + t4]);
                af[mt][2] = __float_as_uint(As[(r + g)     * 36 + kk + t4 + 4]);
                af[mt][3] = __float_as_uint(As[(r + g + 8) * 36 + kk + t4 + 4]);
            }
#pragma unroll
            for (int nt = 0; nt < 8; nt++) {
                int c = wn * 64 + nt * 8;
                bf[nt][0] = __float_as_uint(Bs[(c + g) * 36 + kk + t4]);
                bf[nt][1] = __float_as_uint(Bs[(c + g) * 36 + kk + t4 + 4]);
            }
#pragma unroll
            for (int mt = 0; mt < 4; mt++)
#pragma unroll
                for (int nt = 0; nt < 8; nt++) {
                    asm volatile(
                        "mma.sync.aligned.m16n8k8.row.col.f32.tf32.tf32.f32 "
                        "{%0,%1,%2,%3}, {%4,%5,%6,%7}, {%8,%9}, {%0,%1,%2,%3};"
                        : "+f"(acc[mt][nt][0]), "+f"(acc[mt][nt][1]),
                          "+f"(acc[mt][nt][2]), "+f"(acc[mt][nt][3])
                        : "r"(af[mt][0]), "r"(af[mt][1]),
                          "r"(af[mt][2]), "r"(af[mt][3]),
                          "r"(bf[nt][0]), "r"(bf[nt][1]));
                }
        }
        if (++buf == 3) buf = 0;
    }

#pragma unroll
    for (int mt = 0; mt < 4; mt++) {
#pragma unroll
        for (int nt = 0; nt < 8; nt++) {
            int row = bm + wm * 64 + mt * 16 + g;
            int col = bn + wn * 64 + nt * 8 + 2 * t4;
            if (mode == 0) {
                *(float2*)(C + (size_t)row * N + col) =
                    make_float2(acc[mt][nt][0], acc[mt][nt][1]);
                *(float2*)(C + (size_t)(row + 8) * N + col) =
                    make_float2(acc[mt][nt][2], acc[mt][nt][3]);
            } else {
                int h = col >> 7, d = col & 127;
                *(float2*)(C + ((size_t)h * M + row) * HD + d) =
                    make_float2(acc[mt][nt][0], acc[mt][nt][1]);
                *(float2*)(C + ((size_t)h * M + row + 8) * HD + d) =
                    make_float2(acc[mt][nt][2], acc[mt][nt][3]);
            }
        }
    }
}

// ---------------------------------------------------------------------------
// RoPE: Q in place (fp32); K -> split hi/lo bf16 global
// ---------------------------------------------------------------------------
__global__ __launch_bounds__(256) void rope_kernel(float* __restrict__ Q,
                                                   const float* __restrict__ Kc,
                                                   __nv_bfloat16* __restrict__ Khi,
                                                   __nv_bfloat16* __restrict__ Klo,
                                                   const int* __restrict__ pos)
{
    int idx = blockIdx.x * blockDim.x + threadIdx.x;
    int d = idx & 63;
    int s = (idx >> 6) & (SEQ - 1);
    int h = idx >> 18;

    double ang = (double)pos[s] * exp(-(double)d * (9.210340371976184 / 64.0));
    float c  = (float)cos(ang);
    float si = (float)sin(ang);

    if (h < NHEADS) {
        float* base = Q + ((size_t)h * SEQ + s) * HD;
        float x1 = base[d], x2 = base[d + 64];
        base[d]      = x1 * c - x2 * si;
        base[d + 64] = x2 * c + x1 * si;
    } else {
        size_t o = ((size_t)(h - NHEADS) * SEQ + s) * HD;
        float x1 = Kc[o + d], x2 = Kc[o + d + 64];
        float r1 = x1 * c - x2 * si;
        float r2 = x2 * c + x1 * si;
        __nv_bfloat16 hh, ll;
        cvt_hl(r1, hh, ll); Khi[o + d] = hh;       Klo[o + d] = ll;
        cvt_hl(r2, hh, ll); Khi[o + d + 64] = hh;  Klo[o + d + 64] = ll;
    }
}

// ---------------------------------------------------------------------------
// flash: q-tile 128, kv-tile 64, 256 thr, one sync per iter,
// base-2 online softmax via ex2.approx. bf16x3 mma.
// ---------------------------------------------------------------------------
#define LDB 136

__device__ __forceinline__ void ldsm4(uint32_t a[4], uint32_t addr) {
    asm volatile("ldmatrix.sync.aligned.m8n8.x4.shared.b16 {%0,%1,%2,%3}, [%4];"
        : "=r"(a[0]), "=r"(a[1]), "=r"(a[2]), "=r"(a[3]) : "r"(addr));
}
__device__ __forceinline__ void ldsm4t(uint32_t a[4], uint32_t addr) {
    asm volatile("ldmatrix.sync.aligned.m8n8.x4.trans.shared.b16 {%0,%1,%2,%3}, [%4];"
        : "=r"(a[0]), "=r"(a[1]), "=r"(a[2]), "=r"(a[3]) : "r"(addr));
}
__device__ __forceinline__ void mma_bf16(float c[4], const uint32_t a[4],
                                         uint32_t b0, uint32_t b1) {
    asm volatile(
        "mma.sync.aligned.m16n8k16.row.col.f32.bf16.bf16.f32 "
        "{%0,%1,%2,%3}, {%4,%5,%6,%7}, {%8,%9}, {%0,%1,%2,%3};"
        : "+f"(c[0]), "+f"(c[1]), "+f"(c[2]), "+f"(c[3])
        : "r"(a[0]), "r"(a[1]), "r"(a[2]), "r"(a[3]), "r"(b0), "r"(b1));
}
__device__ __forceinline__ uint32_t pack_bf16(float lo, float hi) {
    uint32_t r;
    asm("cvt.rn.bf16x2.f32 %0, %1, %2;" : "=r"(r) : "f"(hi), "f"(lo));
    return r;
}
__device__ __forceinline__ void split_pack(float x0, float x1,
                                           uint32_t& hi, uint32_t& lo) {
    __nv_bfloat16 h0 = __float2bfloat16(x0), h1 = __float2bfloat16(x1);
    hi = ((uint32_t)__bfloat16_as_ushort(h1) << 16) | __bfloat16_as_ushort(h0);
    lo = pack_bf16(x0 - __bfloat162float(h0), x1 - __bfloat162float(h1));
}

#define F_QT_B  (128 * LDB * 2)
#define F_KT_B  (64 * LDB * 2)
#define F_STG_B (4 * F_KT_B)
#define F_SMEM  (2 * F_QT_B + 2 * F_STG_B)   // 208896

__device__ __forceinline__ void f_fill(uint32_t stg,
    const __nv_bfloat16* Khi_g, const __nv_bfloat16* Klo_g,
    const __nv_bfloat16* Vhi_g, const __nv_bfloat16* Vlo_g,
    int kvh, int kb, int tid)
{
    const size_t gof = ((size_t)kvh * SEQ + (size_t)kb * 64) * HD;
    const char* kh = (const char*)(Khi_g + gof);
    const char* kl = (const char*)(Klo_g + gof);
    const char* vh = (const char*)(Vhi_g + gof);
    const char* vl = (const char*)(Vlo_g + gof);
    for (int i = tid; i < 1024; i += 256) {
        int row = i >> 4, ch = (i & 15) << 4;
        uint32_t dst = row * (LDB * 2) + ch;
        int src = row * 256 + ch;
        cp16(stg + dst,               kh + src);
        cp16(stg + F_KT_B + dst,      kl + src);
        cp16(stg + 2 * F_KT_B + dst,  vh + src);
        cp16(stg + 3 * F_KT_B + dst,  vl + src);
    }
    cp_commit();
}

__global__ __launch_bounds__(256, 1) void flash_v2(
    const float* __restrict__ Q,
    const __nv_bfloat16* __restrict__ Khi_g, const __nv_bfloat16* __restrict__ Klo_g,
    const __nv_bfloat16* __restrict__ Vhi_g, const __nv_bfloat16* __restrict__ Vlo_g,
    float* __restrict__ Out)
{
    extern __shared__ __align__(16) char smem_raw[];
    const uint32_t smb  = (uint32_t)__cvta_generic_to_shared(smem_raw);
    const uint32_t q_hi = smb, q_lo = smb + F_QT_B;
    const uint32_t stg0 = smb + 2 * F_QT_B;

    const int tid  = threadIdx.x;
    const int wid  = tid >> 5;
    const int lane = tid & 31;
    const int g    = lane >> 2;
    const int t    = lane & 3;
    const int qb   = gridDim.x - 1 - blockIdx.x;
    const int h    = blockIdx.y;
    const int kvh  = h >> 2;

    // ---- Q load + split into smem ----
    {
        const float4* Q4 = (const float4*)(Q + ((size_t)h * SEQ + (size_t)qb * 128) * HD);
        __nv_bfloat16* Qh = (__nv_bfloat16*)smem_raw;
        __nv_bfloat16* Ql = (__nv_bfloat16*)(smem_raw + F_QT_B);
        for (int f = tid; f < 4096; f += 256) {
            int row = f >> 5, d0 = (f & 31) << 2;
            float4 q = Q4[f];
            __nv_bfloat16 h0, l0, h1, l1, h2, l2, h3, l3;
            cvt_hl(q.x, h0, l0); cvt_hl(q.y, h1, l1);
            cvt_hl(q.z, h2, l2); cvt_hl(q.w, h3, l3);
            int o = row * LDB + d0;
            *(__nv_bfloat162*)&Qh[o]     = __nv_bfloat162(h0, h1);
            *(__nv_bfloat162*)&Qh[o + 2] = __nv_bfloat162(h2, h3);
            *(__nv_bfloat162*)&Ql[o]     = __nv_bfloat162(l0, l1);
            *(__nv_bfloat162*)&Ql[o + 2] = __nv_bfloat162(l2, l3);
        }
    }

    const int a_row = wid * 16 + (lane & 15);
    const int a_col = (lane >> 4) << 3;
    const int kb_row = (lane & 7) + (((lane >> 4) & 1) << 3);
    const int kb_col = ((lane >> 3) & 1) << 3;
    const int v_row  = (lane & 7) + (((lane >> 3) & 1) << 3);
    const int v_col  = (lane >> 4) << 3;

    float o_[16][4];
    float m0 = -INFINITY, m1 = -INFINITY, l0 = 0.f, l1 = 0.f;
#pragma unroll
    for (int j = 0; j < 16; j++)
#pragma unroll
        for (int c = 0; c < 4; c++) o_[j][c] = 0.f;

    // 1/sqrt(128) * log2(e): softmax runs in base-2 domain
    const float scale2 = 0.12751791437073365f;
    const int rl0 = wid * 16 + g;
    const int rl1 = rl0 + 8;

    const int nkb = 2 * qb + 2;
    f_fill(stg0, Khi_g, Klo_g, Vhi_g, Vlo_g, kvh, 0, tid);

    for (int kb = 0; kb < nkb; kb++) {
        const int buf = kb & 1;
        asm volatile("cp.async.wait_group 0;" ::: "memory");
        __syncthreads();
        if (kb + 1 < nkb)
            f_fill(stg0 + (buf ^ 1) * F_STG_B, Khi_g, Klo_g, Vhi_g, Vlo_g,
                   kvh, kb + 1, tid);

        const int kofs = kb * 64 - qb * 128;
        if (kofs <= wid * 16 + 15) {
            const uint32_t khi_s = stg0 + buf * F_STG_B;
            const uint32_t klo_s = khi_s + F_KT_B;
            const uint32_t vhi_s = khi_s + 2 * F_KT_B;
            const uint32_t vlo_s = khi_s + 3 * F_KT_B;

            float sc[8][4];
#pragma unroll
            for (int j = 0; j < 8; j++)
#pragma unroll
                for (int c = 0; c < 4; c++) sc[j][c] = 0.f;

#pragma unroll
            for (int ks = 0; ks < 8; ks++) {
                uint32_t ahf[4], alf[4];
                uint32_t aoff = ((a_row * LDB) + (ks * 16 + a_col)) * 2;
                ldsm4(ahf, q_hi + aoff);
                ldsm4(alf, q_lo + aoff);
#pragma unroll
                for (int jp = 0; jp < 4; jp++) {
                    uint32_t bh[4], bl[4];
                    uint32_t boff = (((jp * 16 + kb_row) * LDB)
                                     + (ks * 16 + kb_col)) * 2;
                    ldsm4(bh, khi_s + boff);
                    ldsm4(bl, klo_s + boff);
                    mma_bf16(sc[2 * jp],     ahf, bh[0], bh[1]);
                    mma_bf16(sc[2 * jp],     ahf, bl[0], bl[1]);
                    mma_bf16(sc[2 * jp],     alf, bh[0], bh[1]);
                    mma_bf16(sc[2 * jp + 1], ahf, bh[2], bh[3]);
                    mma_bf16(sc[2 * jp + 1], ahf, bl[2], bl[3]);
                    mma_bf16(sc[2 * jp + 1], alf, bh[2], bh[3]);
                }
            }

            const bool diag = (kofs + 63 > rl0);
            float tm0 = -INFINITY, tm1 = -INFINITY;
#pragma unroll
            for (int j = 0; j < 8; j++) {
                float v0 = sc[j][0] * scale2, v1 = sc[j][1] * scale2;
                float v2 = sc[j][2] * scale2, v3 = sc[j][3] * scale2;
                if (diag) {
                    int c0 = kofs + 8 * j + 2 * t;
                    if (c0     > rl0) v0 = -INFINITY;
                    if (c0 + 1 > rl0) v1 = -INFINITY;
                    if (c0     > rl1) v2 = -INFINITY;
                    if (c0 + 1 > rl1) v3 = -INFINITY;
                }
                sc[j][0] = v0; sc[j][1] = v1; sc[j][2] = v2; sc[j][3] = v3;
                tm0 = fmaxf(tm0, fmaxf(v0, v1));
                tm1 = fmaxf(tm1, fmaxf(v2, v3));
            }
            tm0 = fmaxf(tm0, __shfl_xor_sync(0xffffffffu, tm0, 1));
            tm0 = fmaxf(tm0, __shfl_xor_sync(0xffffffffu, tm0, 2));
            tm1 = fmaxf(tm1, __shfl_xor_sync(0xffffffffu, tm1, 1));
            tm1 = fmaxf(tm1, __shfl_xor_sync(0xffffffffu, tm1, 2));

            float mn0 = fmaxf(m0, tm0), mn1 = fmaxf(m1, tm1);
            float al0 = ex2a(m0 - mn0), al1 = ex2a(m1 - mn1);
            m0 = mn0; m1 = mn1;

            float rs0 = 0.f, rs1 = 0.f;
#pragma unroll
            for (int j = 0; j < 8; j++) {
                sc[j][0] = ex2a(sc[j][0] - mn0);
                sc[j][1] = ex2a(sc[j][1] - mn0);
                sc[j][2] = ex2a(sc[j][2] - mn1);
                sc[j][3] = ex2a(sc[j][3] - mn1);
                rs0 += sc[j][0] + sc[j][1];
                rs1 += sc[j][2] + sc[j][3];
            }
            rs0 += __shfl_xor_sync(0xffffffffu, rs0, 1);
            rs0 += __shfl_xor_sync(0xffffffffu, rs0, 2);
            rs1 += __shfl_xor_sync(0xffffffffu, rs1, 1);
            rs1 += __shfl_xor_sync(0xffffffffu, rs1, 2);
            l0 = l0 * al0 + rs0;
            l1 = l1 * al1 + rs1;

#pragma unroll
            for (int j = 0; j < 16; j++) {
                o_[j][0] *= al0; o_[j][1] *= al0;
                o_[j][2] *= al1; o_[j][3] *= al1;
            }

            uint32_t pah[4][4], pal[4][4];
#pragma unroll
            for (int kc = 0; kc < 4; kc++) {
                int j0 = 2 * kc, j1 = j0 + 1;
                split_pack(sc[j0][0], sc[j0][1], pah[kc][0], pal[kc][0]);
                split_pack(sc[j0][2], sc[j0][3], pah[kc][1], pal[kc][1]);
                split_pack(sc[j1][0], sc[j1][1], pah[kc][2], pal[kc][2]);
                split_pack(sc[j1][2], sc[j1][3], pah[kc][3], pal[kc][3]);
            }

#pragma unroll
            for (int kc = 0; kc < 4; kc++) {
#pragma unroll
                for (int jp = 0; jp < 8; jp++) {
                    uint32_t vh[4], vl[4];
                    uint32_t voff = (((kc * 16 + v_row) * LDB)
                                     + (jp * 16 + v_col)) * 2;
                    ldsm4t(vh, vhi_s + voff);
                    ldsm4t(vl, vlo_s + voff);
                    mma_bf16(o_[2 * jp],     pah[kc], vh[0], vh[1]);
                    mma_bf16(o_[2 * jp],     pah[kc], vl[0], vl[1]);
                    mma_bf16(o_[2 * jp],     pal[kc], vh[0], vh[1]);
                    mma_bf16(o_[2 * jp + 1], pah[kc], vh[2], vh[3]);
                    mma_bf16(o_[2 * jp + 1], pah[kc], vl[2], vl[3]);
                    mma_bf16(o_[2 * jp + 1], pal[kc], vh[2], vh[3]);
                }
            }
        }
    }

    float inv0 = rcpa(l0), inv1 = rcpa(l1);
    size_t r0 = (size_t)qb * 128 + wid * 16 + g;
    float* base0 = Out + r0 * HID + (size_t)h * HD;
    float* base1 = base0 + (size_t)8 * HID;
#pragma unroll
    for (int j = 0; j < 16; j++) {
        int col = 8 * j + 2 * t;
        *(float2*)(base0 + col) = make_float2(
            __uint_as_float(f2tf32(o_[j][0] * inv0)),
            __uint_as_float(f2tf32(o_[j][1] * inv0)));
        *(float2*)(base1 + col) = make_float2(
            __uint_as_float(f2tf32(o_[j][2] * inv1)),
            __uint_as_float(f2tf32(o_[j][3] * inv1)));
    }
}

// ---------------------------------------------------------------------------
extern "C" void kernel_launch(void* const* d_in, const int* in_sizes, int n_in,
                              void* d_out, int out_size)
{
    const float* Hs = (const float*)d_in[0];
    const float* Wq = (const float*)d_in[1];
    const float* Wk = (const float*)d_in[2];
    const float* Wv = (const float*)d_in[3];
    const float* Wo = (const float*)d_in[4];
    const int*  pos = (const int*)d_in[5];
    float* out = (float*)d_out;

    float *Qp, *KVp, *Ap, *rH, *rWq, *rWkv, *rWo;
    __nv_bfloat16 *Khi, *Klo, *Vhi, *Vlo;
    cudaGetSymbolAddress((void**)&Qp,   g_Q);
    cudaGetSymbolAddress((void**)&KVp,  g_KV);
    cudaGetSymbolAddress((void**)&Ap,   g_A);
    cudaGetSymbolAddress((void**)&rH,   g_rH);
    cudaGetSymbolAddress((void**)&rWq,  g_rWq);
    cudaGetSymbolAddress((void**)&rWkv, g_rWkv);
    cudaGetSymbolAddress((void**)&rWo,  g_rWo);
    cudaGetSymbolAddress((void**)&Khi, g_Khi);
    cudaGetSymbolAddress((void**)&Klo, g_Klo);
    cudaGetSymbolAddress((void**)&Vhi, g_Vhi);
    cudaGetSymbolAddress((void**)&Vlo, g_Vlo);

    float* Kp = KVp;                                   // K heads 0-7
    float* Vp = KVp + (size_t)NKV * SEQ * HD;          // V heads (8-15 in merged idx)

    cudaFuncSetAttribute(flash_v2, cudaFuncAttributeMaxDynamicSharedMemorySize,
                         F_SMEM);
    cudaFuncSetAttribute(gemm_tf32_v2, cudaFuncAttributeMaxDynamicSharedMemorySize,
                         G_SMEM);

    const int nH4 = SEQ * HID / 4, nW4 = HID * HID / 4, nKV4 = NKV * HD * HID / 4;
    round_tf32<<<nH4 / 256, 256>>>((const float4*)Hs, (float4*)rH, nH4);
    round_tf32<<<nW4 / 256, 256>>>((const float4*)Wq, (float4*)rWq, nW4);
    round_tf32<<<nKV4 / 256, 256>>>((const float4*)Wk, (float4*)rWkv, nKV4);
    round_tf32<<<nKV4 / 256, 256>>>((const float4*)Wv,
                                    (float4*)(rWkv + (size_t)NKV * HD * HID), nKV4);
    round_tf32<<<nW4 / 256, 256>>>((const float4*)Wo, (float4*)rWo, nW4);

    // Q projection (512 CTAs), merged K+V projection (256 CTAs = one wave)
    gemm_tf32_v2<<<dim3(HID / 256, SEQ / 128), 256, G_SMEM>>>(rH, rWq, Qp,
                                                              SEQ, HID, HID, 1);
    gemm_tf32_v2<<<dim3(2 * NKV * HD / 256, SEQ / 128), 256, G_SMEM>>>(
        rH, rWkv, KVp, SEQ, 2 * NKV * HD, HID, 1);

    rope_kernel<<<((NHEADS + NKV) * SEQ * 64) / 256, 256>>>(Qp, Kp, Khi, Klo, pos);

    const int nV4 = NKV * SEQ * HD / 4;
    split_kernel<<<nV4 / 256, 256>>>((const float4*)Vp,
        (__nv_bfloat162*)Vhi, (__nv_bfloat162*)Vlo, nV4);

    flash_v2<<<dim3(SEQ / 128, NHEADS), 256, F_SMEM>>>(Qp, Khi, Klo, Vhi, Vlo, Ap);

    gemm_tf32_v2<<<dim3(HID / 256, SEQ / 128), 256, G_SMEM>>>(Ap, rWo, out,
                                                              SEQ, HID, HID, 0);
}

// round 9
// speedup vs baseline: 1.0647x; 1.0634x over previous
#include <cuda_runtime.h>
#include <cuda_bf16.h>
#include <cuda_fp16.h>
#include <math.h>
#include <stdint.h>

#define SEQ    4096
#define HID    4096
#define NHEADS 32
#define NKV    8
#define HD     128

// ---------------- device scratch (allocation-free rule) ----------------
__device__ float g_Q[(size_t)NHEADS * SEQ * HD];      // [head][seq][128]
__device__ float g_KV[(size_t)2 * NKV * SEQ * HD];    // K heads 0-7, V heads 8-15
__device__ float g_A[(size_t)SEQ * HID];              // flash out (tf32-rounded)
__device__ float g_rH[(size_t)SEQ * HID];             // tf32-rounded operands
__device__ float g_rWq[(size_t)HID * HID];
__device__ float g_rWkv[(size_t)2 * NKV * HD * HID];  // Wk rows 0-1023, Wv 1024-2047
__device__ float g_rWo[(size_t)HID * HID];
__device__ __half g_Khi[(size_t)NKV * SEQ * HD];      // split K (post-rope), fp16
__device__ __half g_Klo[(size_t)NKV * SEQ * HD];
__device__ __half g_Vhi[(size_t)NKV * SEQ * HD];
__device__ __half g_Vlo[(size_t)NKV * SEQ * HD];

__device__ __forceinline__ unsigned f2tf32(float x) {
    unsigned r;
    asm("cvt.rna.tf32.f32 %0, %1;" : "=r"(r) : "f"(x));
    return r;
}
__device__ __forceinline__ float ex2a(float x) {
    float y;
    asm("ex2.approx.f32 %0, %1;" : "=f"(y) : "f"(x));
    return y;
}
__device__ __forceinline__ float rcpa(float x) {
    float y;
    asm("rcp.approx.f32 %0, %1;" : "=f"(y) : "f"(x));
    return y;
}
__device__ __forceinline__ void cp16(uint32_t dst, const void* src) {
    asm volatile("cp.async.cg.shared.global [%0], [%1], 16;"
                 :: "r"(dst), "l"(src) : "memory");
}
__device__ __forceinline__ void cp_commit() {
    asm volatile("cp.async.commit_group;" ::: "memory");
}
__device__ __forceinline__ void cvt_hl_h(float x, __half& h, __half& l) {
    h = __float2half_rn(x);
    l = __float2half_rn(x - __half2float(h));
}

// ---------------------------------------------------------------------------
// Pre-round fp32 -> tf32 (rna)
// ---------------------------------------------------------------------------
__global__ __launch_bounds__(256) void round_tf32(const float4* __restrict__ in,
                                                  float4* __restrict__ out, int n4)
{
    int i = blockIdx.x * blockDim.x + threadIdx.x;
    if (i >= n4) return;
    float4 v = in[i];
    v.x = __uint_as_float(f2tf32(v.x));
    v.y = __uint_as_float(f2tf32(v.y));
    v.z = __uint_as_float(f2tf32(v.z));
    v.w = __uint_as_float(f2tf32(v.w));
    out[i] = v;
}

// ---------------------------------------------------------------------------
// fp32 -> (hi, lo) fp16 split (for V)
// ---------------------------------------------------------------------------
__global__ __launch_bounds__(256) void split_kernel(const float4* __restrict__ in,
                                                    __half2* __restrict__ hi,
                                                    __half2* __restrict__ lo,
                                                    int n4)
{
    int i = blockIdx.x * blockDim.x + threadIdx.x;
    if (i >= n4) return;
    float4 v = in[i];
    __half h0, l0, h1, l1, h2, l2, h3, l3;
    cvt_hl_h(v.x, h0, l0); cvt_hl_h(v.y, h1, l1);
    cvt_hl_h(v.z, h2, l2); cvt_hl_h(v.w, h3, l3);
    hi[2 * i]     = __halves2half2(h0, h1);
    hi[2 * i + 1] = __halves2half2(h2, h3);
    lo[2 * i]     = __halves2half2(l0, l1);
    lo[2 * i + 1] = __halves2half2(l2, l3);
}

// ---------------------------------------------------------------------------
// TF32 GEMM: 3-stage cp.async pipeline, one __syncthreads per K-iter.
// CTA 128x256, K-tile 32, 8 warps, warp tile 64x64.
// ---------------------------------------------------------------------------
#define GS_A   (128 * 36)
#define GS_B   (256 * 36)
#define GS_ST  (GS_A + GS_B)
#define G_SMEM (3 * GS_ST * 4)

__device__ __forceinline__ void g_fill(uint32_t smb, int buf,
    const float* __restrict__ A, const float* __restrict__ B,
    int bm, int bn, int K, int kt, int tid)
{
    const uint32_t sa = smb + buf * (GS_ST * 4);
    const uint32_t sb = sa + GS_A * 4;
    const size_t kof = (size_t)kt << 5;
    for (int i = tid; i < 1024; i += 256) {
        int row = i >> 3, ch = (i & 7) << 4;
        cp16(sa + row * 144 + ch,
             (const char*)(A + (size_t)(bm + row) * K + kof) + ch);
    }
    for (int i = tid; i < 2048; i += 256) {
        int row = i >> 3, ch = (i & 7) << 4;
        cp16(sb + row * 144 + ch,
             (const char*)(B + (size_t)(bn + row) * K + kof) + ch);
    }
    cp_commit();
}

__global__ __launch_bounds__(256, 1) void gemm_tf32_v2(
    const float* __restrict__ A, const float* __restrict__ B,
    float* __restrict__ C, int M, int N, int K, int mode)
{
    extern __shared__ __align__(16) float sm[];
    const uint32_t smb = (uint32_t)__cvta_generic_to_shared(sm);

    const int tid  = threadIdx.x;
    const int warp = tid >> 5;
    const int lane = tid & 31;
    const int wm   = warp & 1;
    const int wn   = warp >> 1;
    const int g    = lane >> 2;
    const int t4   = lane & 3;
    const int bm   = blockIdx.y * 128;
    const int bn   = blockIdx.x * 256;

    float acc[4][8][4];
#pragma unroll
    for (int mt = 0; mt < 4; mt++)
#pragma unroll
        for (int nt = 0; nt < 8; nt++)
#pragma unroll
            for (int c = 0; c < 4; c++) acc[mt][nt][c] = 0.f;

    const int KT = K >> 5;
    g_fill(smb, 0, A, B, bm, bn, K, 0, tid);
    g_fill(smb, 1, A, B, bm, bn, K, 1, tid);

    int buf = 0;
    for (int kt = 0; kt < KT; kt++) {
        if (kt < KT - 1) {
            asm volatile("cp.async.wait_group 1;" ::: "memory");
        } else {
            asm volatile("cp.async.wait_group 0;" ::: "memory");
        }
        __syncthreads();
        if (kt + 2 < KT) {
            int nb = buf + 2; if (nb >= 3) nb -= 3;
            g_fill(smb, nb, A, B, bm, bn, K, kt + 2, tid);
        }

        const float* As = sm + buf * GS_ST;
        const float* Bs = As + GS_A;

#pragma unroll
        for (int ks = 0; ks < 4; ks++) {
            const int kk = ks * 8;
            unsigned af[4][4], bf[8][2];
#pragma unroll
            for (int mt = 0; mt < 4; mt++) {
                int r = wm * 64 + mt * 16;
                af[mt][0] = __float_as_uint(As[(r + g)     * 36 + kk + t4]);
                af[mt][1] = __float_as_uint(As[(r + g + 8) * 36 + kk + t4]);
                af[mt][2] = __float_as_uint(As[(r + g)     * 36 + kk + t4 + 4]);
                af[mt][3] = __float_as_uint(As[(r + g + 8) * 36 + kk + t4 + 4]);
            }
#pragma unroll
            for (int nt = 0; nt < 8; nt++) {
                int c = wn * 64 + nt * 8;
                bf[nt][0] = __float_as_uint(Bs[(c + g) * 36 + kk + t4]);
                bf[nt][1] = __float_as_uint(Bs[(c + g) * 36 + kk + t4 + 4]);
            }
#pragma unroll
            for (int mt = 0; mt < 4; mt++)
#pragma unroll
                for (int nt = 0; nt < 8; nt++) {
                    asm volatile(
                        "mma.sync.aligned.m16n8k8.row.col.f32.tf32.tf32.f32 "
                        "{%0,%1,%2,%3}, {%4,%5,%6,%7}, {%8,%9}, {%0,%1,%2,%3};"
                        : "+f"(acc[mt][nt][0]), "+f"(acc[mt][nt][1]),
                          "+f"(acc[mt][nt][2]), "+f"(acc[mt][nt][3])
                        : "r"(af[mt][0]), "r"(af[mt][1]),
                          "r"(af[mt][2]), "r"(af[mt][3]),
                          "r"(bf[nt][0]), "r"(bf[nt][1]));
                }
        }
        if (++buf == 3) buf = 0;
    }

#pragma unroll
    for (int mt = 0; mt < 4; mt++) {
#pragma unroll
        for (int nt = 0; nt < 8; nt++) {
            int row = bm + wm * 64 + mt * 16 + g;
            int col = bn + wn * 64 + nt * 8 + 2 * t4;
            if (mode == 0) {
                *(float2*)(C + (size_t)row * N + col) =
                    make_float2(acc[mt][nt][0], acc[mt][nt][1]);
                *(float2*)(C + (size_t)(row + 8) * N + col) =
                    make_float2(acc[mt][nt][2], acc[mt][nt][3]);
            } else {
                int h = col >> 7, d = col & 127;
                *(float2*)(C + ((size_t)h * M + row) * HD + d) =
                    make_float2(acc[mt][nt][0], acc[mt][nt][1]);
                *(float2*)(C + ((size_t)h * M + row + 8) * HD + d) =
                    make_float2(acc[mt][nt][2], acc[mt][nt][3]);
            }
        }
    }
}

// ---------------------------------------------------------------------------
// RoPE: Q in place (fp32); K -> split hi/lo fp16 global
// ---------------------------------------------------------------------------
__global__ __launch_bounds__(256) void rope_kernel(float* __restrict__ Q,
                                                   const float* __restrict__ Kc,
                                                   __half* __restrict__ Khi,
                                                   __half* __restrict__ Klo,
                                                   const int* __restrict__ pos)
{
    int idx = blockIdx.x * blockDim.x + threadIdx.x;
    int d = idx & 63;
    int s = (idx >> 6) & (SEQ - 1);
    int h = idx >> 18;

    double ang = (double)pos[s] * exp(-(double)d * (9.210340371976184 / 64.0));
    float c  = (float)cos(ang);
    float si = (float)sin(ang);

    if (h < NHEADS) {
        float* base = Q + ((size_t)h * SEQ + s) * HD;
        float x1 = base[d], x2 = base[d + 64];
        base[d]      = x1 * c - x2 * si;
        base[d + 64] = x2 * c + x1 * si;
    } else {
        size_t o = ((size_t)(h - NHEADS) * SEQ + s) * HD;
        float x1 = Kc[o + d], x2 = Kc[o + d + 64];
        float r1 = x1 * c - x2 * si;
        float r2 = x2 * c + x1 * si;
        __half hh, ll;
        cvt_hl_h(r1, hh, ll); Khi[o + d] = hh;       Klo[o + d] = ll;
        cvt_hl_h(r2, hh, ll); Khi[o + d + 64] = hh;  Klo[o + d + 64] = ll;
    }
}

// ---------------------------------------------------------------------------
// flash fp16x2: q-tile 128, kv-tile 64, 256 thr, one sync per iter.
// S = Qh*(Khi+Klo)  (2 mma/term-pair), O += Ph*(Vhi+Vlo).
// Error: (Q-Qh)*K and (P-Ph)*V only, ~2-3e-4 on probs.
// ---------------------------------------------------------------------------
#define LDB 136

__device__ __forceinline__ void ldsm4(uint32_t a[4], uint32_t addr) {
    asm volatile("ldmatrix.sync.aligned.m8n8.x4.shared.b16 {%0,%1,%2,%3}, [%4];"
        : "=r"(a[0]), "=r"(a[1]), "=r"(a[2]), "=r"(a[3]) : "r"(addr));
}
__device__ __forceinline__ void ldsm4t(uint32_t a[4], uint32_t addr) {
    asm volatile("ldmatrix.sync.aligned.m8n8.x4.trans.shared.b16 {%0,%1,%2,%3}, [%4];"
        : "=r"(a[0]), "=r"(a[1]), "=r"(a[2]), "=r"(a[3]) : "r"(addr));
}
__device__ __forceinline__ void mma_f16(float c[4], const uint32_t a[4],
                                        uint32_t b0, uint32_t b1) {
    asm volatile(
        "mma.sync.aligned.m16n8k16.row.col.f32.f16.f16.f32 "
        "{%0,%1,%2,%3}, {%4,%5,%6,%7}, {%8,%9}, {%0,%1,%2,%3};"
        : "+f"(c[0]), "+f"(c[1]), "+f"(c[2]), "+f"(c[3])
        : "r"(a[0]), "r"(a[1]), "r"(a[2]), "r"(a[3]), "r"(b0), "r"(b1));
}
// pack two fp32 -> f16x2: first arg -> low half, second -> high half
__device__ __forceinline__ uint32_t pack_f16(float lo, float hi) {
    uint32_t r;
    asm("cvt.rn.f16x2.f32 %0, %1, %2;" : "=r"(r) : "f"(hi), "f"(lo));
    return r;
}

#define F_QT_B  (128 * LDB * 2)          // 34816 (Q fp16 tile, hi only)
#define F_KT_B  (64 * LDB * 2)           // 17408
#define F_STG_B (4 * F_KT_B)             // 69632 (Khi,Klo,Vhi,Vlo)
#define F_SMEM  (F_QT_B + 2 * F_STG_B)   // 174080

__device__ __forceinline__ void f_fill(uint32_t stg,
    const __half* Khi_g, const __half* Klo_g,
    const __half* Vhi_g, const __half* Vlo_g,
    int kvh, int kb, int tid)
{
    const size_t gof = ((size_t)kvh * SEQ + (size_t)kb * 64) * HD;
    const char* kh = (const char*)(Khi_g + gof);
    const char* kl = (const char*)(Klo_g + gof);
    const char* vh = (const char*)(Vhi_g + gof);
    const char* vl = (const char*)(Vlo_g + gof);
    for (int i = tid; i < 1024; i += 256) {
        int row = i >> 4, ch = (i & 15) << 4;
        uint32_t dst = row * (LDB * 2) + ch;
        int src = row * 256 + ch;
        cp16(stg + dst,               kh + src);
        cp16(stg + F_KT_B + dst,      kl + src);
        cp16(stg + 2 * F_KT_B + dst,  vh + src);
        cp16(stg + 3 * F_KT_B + dst,  vl + src);
    }
    cp_commit();
}

__global__ __launch_bounds__(256, 1) void flash_v2(
    const float* __restrict__ Q,
    const __half* __restrict__ Khi_g, const __half* __restrict__ Klo_g,
    const __half* __restrict__ Vhi_g, const __half* __restrict__ Vlo_g,
    float* __restrict__ Out)
{
    extern __shared__ __align__(16) char smem_raw[];
    const uint32_t smb  = (uint32_t)__cvta_generic_to_shared(smem_raw);
    const uint32_t q_h  = smb;
    const uint32_t stg0 = smb + F_QT_B;

    const int tid  = threadIdx.x;
    const int wid  = tid >> 5;
    const int lane = tid & 31;
    const int g    = lane >> 2;
    const int t    = lane & 3;
    const int qb   = gridDim.x - 1 - blockIdx.x;
    const int h    = blockIdx.y;
    const int kvh  = h >> 2;

    // ---- Q load, round to fp16, into smem ----
    {
        const float4* Q4 = (const float4*)(Q + ((size_t)h * SEQ + (size_t)qb * 128) * HD);
        __half* Qh = (__half*)smem_raw;
        for (int f = tid; f < 4096; f += 256) {
            int row = f >> 5, d0 = (f & 31) << 2;
            float4 q = Q4[f];
            int o = row * LDB + d0;
            *(__half2*)&Qh[o]     = __halves2half2(__float2half_rn(q.x),
                                                   __float2half_rn(q.y));
            *(__half2*)&Qh[o + 2] = __halves2half2(__float2half_rn(q.z),
                                                   __float2half_rn(q.w));
        }
    }

    const int a_row = wid * 16 + (lane & 15);
    const int a_col = (lane >> 4) << 3;
    const int kb_row = (lane & 7) + (((lane >> 4) & 1) << 3);
    const int kb_col = ((lane >> 3) & 1) << 3;
    const int v_row  = (lane & 7) + (((lane >> 3) & 1) << 3);
    const int v_col  = (lane >> 4) << 3;

    float o_[16][4];
    float m0 = -INFINITY, m1 = -INFINITY, l0 = 0.f, l1 = 0.f;
#pragma unroll
    for (int j = 0; j < 16; j++)
#pragma unroll
        for (int c = 0; c < 4; c++) o_[j][c] = 0.f;

    // 1/sqrt(128) * log2(e): softmax in base-2 domain
    const float scale2 = 0.12751791437073365f;
    const int rl0 = wid * 16 + g;
    const int rl1 = rl0 + 8;

    const int nkb = 2 * qb + 2;
    f_fill(stg0, Khi_g, Klo_g, Vhi_g, Vlo_g, kvh, 0, tid);

    for (int kb = 0; kb < nkb; kb++) {
        const int buf = kb & 1;
        asm volatile("cp.async.wait_group 0;" ::: "memory");
        __syncthreads();
        if (kb + 1 < nkb)
            f_fill(stg0 + (buf ^ 1) * F_STG_B, Khi_g, Klo_g, Vhi_g, Vlo_g,
                   kvh, kb + 1, tid);

        const int kofs = kb * 64 - qb * 128;
        if (kofs <= wid * 16 + 15) {
            const uint32_t khi_s = stg0 + buf * F_STG_B;
            const uint32_t klo_s = khi_s + F_KT_B;
            const uint32_t vhi_s = khi_s + 2 * F_KT_B;
            const uint32_t vlo_s = khi_s + 3 * F_KT_B;

            float sc[8][4];
#pragma unroll
            for (int j = 0; j < 8; j++)
#pragma unroll
                for (int c = 0; c < 4; c++) sc[j][c] = 0.f;

#pragma unroll
            for (int ks = 0; ks < 8; ks++) {
                uint32_t ahf[4];
                uint32_t aoff = ((a_row * LDB) + (ks * 16 + a_col)) * 2;
                ldsm4(ahf, q_h + aoff);
#pragma unroll
                for (int jp = 0; jp < 4; jp++) {
                    uint32_t bh[4], bl[4];
                    uint32_t boff = (((jp * 16 + kb_row) * LDB)
                                     + (ks * 16 + kb_col)) * 2;
                    ldsm4(bh, khi_s + boff);
                    ldsm4(bl, klo_s + boff);
                    mma_f16(sc[2 * jp],     ahf, bh[0], bh[1]);
                    mma_f16(sc[2 * jp],     ahf, bl[0], bl[1]);
                    mma_f16(sc[2 * jp + 1], ahf, bh[2], bh[3]);
                    mma_f16(sc[2 * jp + 1], ahf, bl[2], bl[3]);
                }
            }

            const bool diag = (kofs + 63 > rl0);
            float tm0 = -INFINITY, tm1 = -INFINITY;
#pragma unroll
            for (int j = 0; j < 8; j++) {
                float v0 = sc[j][0] * scale2, v1 = sc[j][1] * scale2;
                float v2 = sc[j][2] * scale2, v3 = sc[j][3] * scale2;
                if (diag) {
                    int c0 = kofs + 8 * j + 2 * t;
                    if (c0     > rl0) v0 = -INFINITY;
                    if (c0 + 1 > rl0) v1 = -INFINITY;
                    if (c0     > rl1) v2 = -INFINITY;
                    if (c0 + 1 > rl1) v3 = -INFINITY;
                }
                sc[j][0] = v0; sc[j][1] = v1; sc[j][2] = v2; sc[j][3] = v3;
                tm0 = fmaxf(tm0, fmaxf(v0, v1));
                tm1 = fmaxf(tm1, fmaxf(v2, v3));
            }
            tm0 = fmaxf(tm0, __shfl_xor_sync(0xffffffffu, tm0, 1));
            tm0 = fmaxf(tm0, __shfl_xor_sync(0xffffffffu, tm0, 2));
            tm1 = fmaxf(tm1, __shfl_xor_sync(0xffffffffu, tm1, 1));
            tm1 = fmaxf(tm1, __shfl_xor_sync(0xffffffffu, tm1, 2));

            float mn0 = fmaxf(m0, tm0), mn1 = fmaxf(m1, tm1);
            float al0 = ex2a(m0 - mn0), al1 = ex2a(m1 - mn1);
            m0 = mn0; m1 = mn1;

            float rs0 = 0.f, rs1 = 0.f;
#pragma unroll
            for (int j = 0; j < 8; j++) {
                sc[j][0] = ex2a(sc[j][0] - mn0);
                sc[j][1] = ex2a(sc[j][1] - mn0);
                sc[j][2] = ex2a(sc[j][2] - mn1);
                sc[j][3] = ex2a(sc[j][3] - mn1);
                rs0 += sc[j][0] + sc[j][1];
                rs1 += sc[j][2] + sc[j][3];
            }
            rs0 += __shfl_xor_sync(0xffffffffu, rs0, 1);
            rs0 += __shfl_xor_sync(0xffffffffu, rs0, 2);
            rs1 += __shfl_xor_sync(0xffffffffu, rs1, 1);
            rs1 += __shfl_xor_sync(0xffffffffu, rs1, 2);
            l0 = l0 * al0 + rs0;
            l1 = l1 * al1 + rs1;

#pragma unroll
            for (int j = 0; j < 16; j++) {
                o_[j][0] *= al0; o_[j][1] *= al0;
                o_[j][2] *= al1; o_[j][3] *= al1;
            }

            // P rounded to fp16 (single term)
            uint32_t pa[4][4];
#pragma unroll
            for (int kc = 0; kc < 4; kc++) {
                int j0 = 2 * kc, j1 = j0 + 1;
                pa[kc][0] = pack_f16(sc[j0][0], sc[j0][1]);
                pa[kc][1] = pack_f16(sc[j0][2], sc[j0][3]);
                pa[kc][2] = pack_f16(sc[j1][0], sc[j1][1]);
                pa[kc][3] = pack_f16(sc[j1][2], sc[j1][3]);
            }

#pragma unroll
            for (int kc = 0; kc < 4; kc++) {
#pragma unroll
                for (int jp = 0; jp < 8; jp++) {
                    uint32_t vh[4], vl[4];
                    uint32_t voff = (((kc * 16 + v_row) * LDB)
                                     + (jp * 16 + v_col)) * 2;
                    ldsm4t(vh, vhi_s + voff);
                    ldsm4t(vl, vlo_s + voff);
                    mma_f16(o_[2 * jp],     pa[kc], vh[0], vh[1]);
                    mma_f16(o_[2 * jp],     pa[kc], vl[0], vl[1]);
                    mma_f16(o_[2 * jp + 1], pa[kc], vh[2], vh[3]);
                    mma_f16(o_[2 * jp + 1], pa[kc], vl[2], vl[3]);
                }
            }
        }
    }

    float inv0 = rcpa(l0), inv1 = rcpa(l1);
    size_t r0 = (size_t)qb * 128 + wid * 16 + g;
    float* base0 = Out + r0 * HID + (size_t)h * HD;
    float* base1 = base0 + (size_t)8 * HID;
#pragma unroll
    for (int j = 0; j < 16; j++) {
        int col = 8 * j + 2 * t;
        *(float2*)(base0 + col) = make_float2(
            __uint_as_float(f2tf32(o_[j][0] * inv0)),
            __uint_as_float(f2tf32(o_[j][1] * inv0)));
        *(float2*)(base1 + col) = make_float2(
            __uint_as_float(f2tf32(o_[j][2] * inv1)),
            __uint_as_float(f2tf32(o_[j][3] * inv1)));
    }
}

// ---------------------------------------------------------------------------
extern "C" void kernel_launch(void* const* d_in, const int* in_sizes, int n_in,
                              void* d_out, int out_size)
{
    const float* Hs = (const float*)d_in[0];
    const float* Wq = (const float*)d_in[1];
    const float* Wk = (const float*)d_in[2];
    const float* Wv = (const float*)d_in[3];
    const float* Wo = (const float*)d_in[4];
    const int*  pos = (const int*)d_in[5];
    float* out = (float*)d_out;

    float *Qp, *KVp, *Ap, *rH, *rWq, *rWkv, *rWo;
    __half *Khi, *Klo, *Vhi, *Vlo;
    cudaGetSymbolAddress((void**)&Qp,   g_Q);
    cudaGetSymbolAddress((void**)&KVp,  g_KV);
    cudaGetSymbolAddress((void**)&Ap,   g_A);
    cudaGetSymbolAddress((void**)&rH,   g_rH);
    cudaGetSymbolAddress((void**)&rWq,  g_rWq);
    cudaGetSymbolAddress((void**)&rWkv, g_rWkv);
    cudaGetSymbolAddress((void**)&rWo,  g_rWo);
    cudaGetSymbolAddress((void**)&Khi, g_Khi);
    cudaGetSymbolAddress((void**)&Klo, g_Klo);
    cudaGetSymbolAddress((void**)&Vhi, g_Vhi);
    cudaGetSymbolAddress((void**)&Vlo, g_Vlo);

    float* Kp = KVp;
    float* Vp = KVp + (size_t)NKV * SEQ * HD;

    cudaFuncSetAttribute(flash_v2, cudaFuncAttributeMaxDynamicSharedMemorySize,
                         F_SMEM);
    cudaFuncSetAttribute(gemm_tf32_v2, cudaFuncAttributeMaxDynamicSharedMemorySize,
                         G_SMEM);

    const int nH4 = SEQ * HID / 4, nW4 = HID * HID / 4, nKV4 = NKV * HD * HID / 4;
    round_tf32<<<nH4 / 256, 256>>>((const float4*)Hs, (float4*)rH, nH4);
    round_tf32<<<nW4 / 256, 256>>>((const float4*)Wq, (float4*)rWq, nW4);
    round_tf32<<<nKV4 / 256, 256>>>((const float4*)Wk, (float4*)rWkv, nKV4);
    round_tf32<<<nKV4 / 256, 256>>>((const float4*)Wv,
                                    (float4*)(rWkv + (size_t)NKV * HD * HID), nKV4);
    round_tf32<<<nW4 / 256, 256>>>((const float4*)Wo, (float4*)rWo, nW4);

    gemm_tf32_v2<<<dim3(HID / 256, SEQ / 128), 256, G_SMEM>>>(rH, rWq, Qp,
                                                              SEQ, HID, HID, 1);
    gemm_tf32_v2<<<dim3(2 * NKV * HD / 256, SEQ / 128), 256, G_SMEM>>>(
        rH, rWkv, KVp, SEQ, 2 * NKV * HD, HID, 1);

    rope_kernel<<<((NHEADS + NKV) * SEQ * 64) / 256, 256>>>(Qp, Kp, Khi, Klo, pos);

    const int nV4 = NKV * SEQ * HD / 4;
    split_kernel<<<nV4 / 256, 256>>>((const float4*)Vp,
        (__half2*)Vhi, (__half2*)Vlo, nV4);

    flash_v2<<<dim3(SEQ / 128, NHEADS), 256, F_SMEM>>>(Qp, Khi, Klo, Vhi, Vlo, Ap);

    gemm_tf32_v2<<<dim3(HID / 256, SEQ / 128), 256, G_SMEM>>>(Ap, rWo, out,
                                                              SEQ, HID, HID, 0);
}

// round 12
// speedup vs baseline: 1.4064x; 1.3209x over previous
#include <cuda_runtime.h>
#include <cuda_bf16.h>
#include <cuda_fp16.h>
#include <math.h>
#include <stdint.h>

#define SEQ    4096
#define HID    4096
#define NHEADS 32
#define NKV    8
#define HD     128

// ---------------- device scratch (allocation-free rule) ----------------
__device__ float  g_Q[(size_t)NHEADS * SEQ * HD];     // [head][seq][128]
__device__ float  g_KV[(size_t)2 * NKV * SEQ * HD];   // K heads 0-7, V heads 8-15
__device__ __half g_Ah[(size_t)SEQ * HID];            // flash out (fp16)
__device__ __half g_hH[(size_t)SEQ * HID];            // fp16-rounded operands
__device__ __half g_hWq[(size_t)HID * HID];
__device__ __half g_hWkv[(size_t)2 * NKV * HD * HID]; // Wk rows 0-1023, Wv 1024-2047
__device__ __half g_hWo[(size_t)HID * HID];
__device__ __half g_Khi[(size_t)NKV * SEQ * HD];      // split K (post-rope), fp16
__device__ __half g_Klo[(size_t)NKV * SEQ * HD];
__device__ __half g_Vhi[(size_t)NKV * SEQ * HD];
__device__ __half g_Vlo[(size_t)NKV * SEQ * HD];

__device__ __forceinline__ float ex2a(float x) {
    float y;
    asm("ex2.approx.f32 %0, %1;" : "=f"(y) : "f"(x));
    return y;
}
__device__ __forceinline__ float rcpa(float x) {
    float y;
    asm("rcp.approx.f32 %0, %1;" : "=f"(y) : "f"(x));
    return y;
}
__device__ __forceinline__ void cp16(uint32_t dst, const void* src) {
    asm volatile("cp.async.cg.shared.global [%0], [%1], 16;"
                 :: "r"(dst), "l"(src) : "memory");
}
__device__ __forceinline__ void cp_commit() {
    asm volatile("cp.async.commit_group;" ::: "memory");
}
__device__ __forceinline__ void cvt_hl_h(float x, __half& h, __half& l) {
    h = __float2half_rn(x);
    l = __float2half_rn(x - __half2float(h));
}

// ---------------------------------------------------------------------------
// Pre-round fp32 -> fp16 (rn)
// ---------------------------------------------------------------------------
__global__ __launch_bounds__(256) void round_f16(const float4* __restrict__ in,
                                                 __half2* __restrict__ out, int n4)
{
    int i = blockIdx.x * blockDim.x + threadIdx.x;
    if (i >= n4) return;
    float4 v = in[i];
    out[2 * i]     = __halves2half2(__float2half_rn(v.x), __float2half_rn(v.y));
    out[2 * i + 1] = __halves2half2(__float2half_rn(v.z), __float2half_rn(v.w));
}

// ---------------------------------------------------------------------------
// fp32 -> (hi, lo) fp16 split (for V)
// ---------------------------------------------------------------------------
__global__ __launch_bounds__(256) void split_kernel(const float4* __restrict__ in,
                                                    __half2* __restrict__ hi,
                                                    __half2* __restrict__ lo,
                                                    int n4)
{
    int i = blockIdx.x * blockDim.x + threadIdx.x;
    if (i >= n4) return;
    float4 v = in[i];
    __half h0, l0, h1, l1, h2, l2, h3, l3;
    cvt_hl_h(v.x, h0, l0); cvt_hl_h(v.y, h1, l1);
    cvt_hl_h(v.z, h2, l2); cvt_hl_h(v.w, h3, l3);
    hi[2 * i]     = __halves2half2(h0, h1);
    hi[2 * i + 1] = __halves2half2(h2, h3);
    lo[2 * i]     = __halves2half2(l0, l1);
    lo[2 * i + 1] = __halves2half2(l2, l3);
}

// ---------------------------------------------------------------------------
// ldmatrix / mma helpers (shared by GEMM and flash)
// ---------------------------------------------------------------------------
__device__ __forceinline__ void ldsm4(uint32_t a[4], uint32_t addr) {
    asm volatile("ldmatrix.sync.aligned.m8n8.x4.shared.b16 {%0,%1,%2,%3}, [%4];"
        : "=r"(a[0]), "=r"(a[1]), "=r"(a[2]), "=r"(a[3]) : "r"(addr));
}
__device__ __forceinline__ void ldsm4t(uint32_t a[4], uint32_t addr) {
    asm volatile("ldmatrix.sync.aligned.m8n8.x4.trans.shared.b16 {%0,%1,%2,%3}, [%4];"
        : "=r"(a[0]), "=r"(a[1]), "=r"(a[2]), "=r"(a[3]) : "r"(addr));
}
__device__ __forceinline__ void mma_f16(float c[4], const uint32_t a[4],
                                        uint32_t b0, uint32_t b1) {
    asm volatile(
        "mma.sync.aligned.m16n8k16.row.col.f32.f16.f16.f32 "
        "{%0,%1,%2,%3}, {%4,%5,%6,%7}, {%8,%9}, {%0,%1,%2,%3};"
        : "+f"(c[0]), "+f"(c[1]), "+f"(c[2]), "+f"(c[3])
        : "r"(a[0]), "r"(a[1]), "r"(a[2]), "r"(a[3]), "r"(b0), "r"(b1));
}
__device__ __forceinline__ uint32_t pack_f16(float lo, float hi) {
    uint32_t r;
    asm("cvt.rn.f16x2.f32 %0, %1, %2;" : "=r"(r) : "f"(hi), "f"(lo));
    return r;
}

// ---------------------------------------------------------------------------
// FP16 GEMM: C = A(MxK) * B(NxK)^T, fp16 operands, fp32 accum.
// CTA 128x256, K-tile 64 (4 x k16), 3-stage cp.async, one sync per iter.
// 8 warps, warp tile 64x64, all fragments via ldmatrix.
// Smem rows padded to 72 halves (144B == 16 mod 128: conflict-free ldsm).
// mode 0: C[row*N+col] ; mode 1: head scatter C[((col>>7)*M+row)*128+(col&127)]
// ---------------------------------------------------------------------------
#define GH_A_B  (128 * 144)               // A stage bytes (128 rows x 72 halves)
#define GH_B_B  (256 * 144)
#define GH_ST   (GH_A_B + GH_B_B)         // 55296 B
#define G_SMEM  (3 * GH_ST)               // 165888 B

__device__ __forceinline__ void g_fill_h(uint32_t smb, int buf,
    const __half* __restrict__ A, const __half* __restrict__ B,
    int bm, int bn, int K, int kt, int tid)
{
    const uint32_t sa = smb + buf * GH_ST;
    const uint32_t sb = sa + GH_A_B;
    const size_t kof = (size_t)kt << 6;          // 64 halves
    for (int i = tid; i < 1024; i += 256) {      // A: 128 rows x 8 chunks(16B)
        int row = i >> 3, ch = (i & 7) << 4;
        cp16(sa + row * 144 + ch,
             (const char*)(A + (size_t)(bm + row) * K + kof) + ch);
    }
    for (int i = tid; i < 2048; i += 256) {      // B: 256 rows x 8 chunks
        int row = i >> 3, ch = (i & 7) << 4;
        cp16(sb + row * 144 + ch,
             (const char*)(B + (size_t)(bn + row) * K + kof) + ch);
    }
    cp_commit();
}

__global__ __launch_bounds__(256, 1) void gemm_f16(
    const __half* __restrict__ A, const __half* __restrict__ B,
    float* __restrict__ C, int M, int N, int K, int mode)
{
    extern __shared__ __align__(16) char sm[];
    const uint32_t smb = (uint32_t)__cvta_generic_to_shared(sm);

    const int tid  = threadIdx.x;
    const int warp = tid >> 5;
    const int lane = tid & 31;
    const int wm   = warp & 1;        // 2 -> 64-row half
    const int wn   = warp >> 1;       // 4 -> 64-col slice
    const int g    = lane >> 2;
    const int t4   = lane & 3;
    const int bm   = blockIdx.y * 128;
    const int bn   = blockIdx.x * 256;

    // ldmatrix lane addressing
    const int a_rl  = lane & 15;                     // row within 16
    const int a_cl  = (lane >> 4) << 3;              // 0 or 8
    const int b_rl  = (lane & 7) + (((lane >> 4) & 1) << 3);
    const int b_cl  = ((lane >> 3) & 1) << 3;

    float acc[4][8][4];
#pragma unroll
    for (int mt = 0; mt < 4; mt++)
#pragma unroll
        for (int nt = 0; nt < 8; nt++)
#pragma unroll
            for (int c = 0; c < 4; c++) acc[mt][nt][c] = 0.f;

    const int KT = K >> 6;
    g_fill_h(smb, 0, A, B, bm, bn, K, 0, tid);
    g_fill_h(smb, 1, A, B, bm, bn, K, 1, tid);

    int buf = 0;
    for (int kt = 0; kt < KT; kt++) {
        if (kt < KT - 1) {
            asm volatile("cp.async.wait_group 1;" ::: "memory");
        } else {
            asm volatile("cp.async.wait_group 0;" ::: "memory");
        }
        __syncthreads();
        if (kt + 2 < KT) {
            int nb = buf + 2; if (nb >= 3) nb -= 3;
            g_fill_h(smb, nb, A, B, bm, bn, K, kt + 2, tid);
        }

        const uint32_t sa = smb + buf * GH_ST;
        const uint32_t sb = sa + GH_A_B;

#pragma unroll
        for (int ks = 0; ks < 4; ks++) {
            uint32_t af[4][4];
#pragma unroll
            for (int mt = 0; mt < 4; mt++) {
                uint32_t r = wm * 64 + mt * 16 + a_rl;
                ldsm4(af[mt], sa + (r * 72 + ks * 16 + a_cl) * 2);
            }
#pragma unroll
            for (int jp = 0; jp < 4; jp++) {
                uint32_t bf[4];
                uint32_t r = wn * 64 + jp * 16 + b_rl;
                ldsm4(bf, sb + (r * 72 + ks * 16 + b_cl) * 2);
#pragma unroll
                for (int mt = 0; mt < 4; mt++) {
                    mma_f16(acc[mt][2 * jp],     af[mt], bf[0], bf[1]);
                    mma_f16(acc[mt][2 * jp + 1], af[mt], bf[2], bf[3]);
                }
            }
        }
        if (++buf == 3) buf = 0;
    }

#pragma unroll
    for (int mt = 0; mt < 4; mt++) {
#pragma unroll
        for (int nt = 0; nt < 8; nt++) {
            int row = bm + wm * 64 + mt * 16 + g;
            int col = bn + wn * 64 + nt * 8 + 2 * t4;
            if (mode == 0) {
                *(float2*)(C + (size_t)row * N + col) =
                    make_float2(acc[mt][nt][0], acc[mt][nt][1]);
                *(float2*)(C + (size_t)(row + 8) * N + col) =
                    make_float2(acc[mt][nt][2], acc[mt][nt][3]);
            } else {
                int h = col >> 7, d = col & 127;
                *(float2*)(C + ((size_t)h * M + row) * HD + d) =
                    make_float2(acc[mt][nt][0], acc[mt][nt][1]);
                *(float2*)(C + ((size_t)h * M + row + 8) * HD + d) =
                    make_float2(acc[mt][nt][2], acc[mt][nt][3]);
            }
        }
    }
}

// ---------------------------------------------------------------------------
// RoPE: Q in place (fp32); K -> split hi/lo fp16 global
// ---------------------------------------------------------------------------
__global__ __launch_bounds__(256) void rope_kernel(float* __restrict__ Q,
                                                   const float* __restrict__ Kc,
                                                   __half* __restrict__ Khi,
                                                   __half* __restrict__ Klo,
                                                   const int* __restrict__ pos)
{
    int idx = blockIdx.x * blockDim.x + threadIdx.x;
    int d = idx & 63;
    int s = (idx >> 6) & (SEQ - 1);
    int h = idx >> 18;

    double ang = (double)pos[s] * exp(-(double)d * (9.210340371976184 / 64.0));
    float c  = (float)cos(ang);
    float si = (float)sin(ang);

    if (h < NHEADS) {
        float* base = Q + ((size_t)h * SEQ + s) * HD;
        float x1 = base[d], x2 = base[d + 64];
        base[d]      = x1 * c - x2 * si;
        base[d + 64] = x2 * c + x1 * si;
    } else {
        size_t o = ((size_t)(h - NHEADS) * SEQ + s) * HD;
        float x1 = Kc[o + d], x2 = Kc[o + d + 64];
        float r1 = x1 * c - x2 * si;
        float r2 = x2 * c + x1 * si;
        __half hh, ll;
        cvt_hl_h(r1, hh, ll); Khi[o + d] = hh;       Klo[o + d] = ll;
        cvt_hl_h(r2, hh, ll); Khi[o + d + 64] = hh;  Klo[o + d + 64] = ll;
    }
}

// ---------------------------------------------------------------------------
// flash fp16x2 (unchanged from R9 except epilogue writes fp16 for O-proj)
// ---------------------------------------------------------------------------
#define LDB 136

#define F_QT_B  (128 * LDB * 2)
#define F_KT_B  (64 * LDB * 2)
#define F_STG_B (4 * F_KT_B)
#define F_SMEM  (F_QT_B + 2 * F_STG_B)   // 174080

__device__ __forceinline__ void f_fill(uint32_t stg,
    const __half* Khi_g, const __half* Klo_g,
    const __half* Vhi_g, const __half* Vlo_g,
    int kvh, int kb, int tid)
{
    const size_t gof = ((size_t)kvh * SEQ + (size_t)kb * 64) * HD;
    const char* kh = (const char*)(Khi_g + gof);
    const char* kl = (const char*)(Klo_g + gof);
    const char* vh = (const char*)(Vhi_g + gof);
    const char* vl = (const char*)(Vlo_g + gof);
    for (int i = tid; i < 1024; i += 256) {
        int row = i >> 4, ch = (i & 15) << 4;
        uint32_t dst = row * (LDB * 2) + ch;
        int src = row * 256 + ch;
        cp16(stg + dst,               kh + src);
        cp16(stg + F_KT_B + dst,      kl + src);
        cp16(stg + 2 * F_KT_B + dst,  vh + src);
        cp16(stg + 3 * F_KT_B + dst,  vl + src);
    }
    cp_commit();
}

__global__ __launch_bounds__(256, 1) void flash_v2(
    const float* __restrict__ Q,
    const __half* __restrict__ Khi_g, const __half* __restrict__ Klo_g,
    const __half* __restrict__ Vhi_g, const __half* __restrict__ Vlo_g,
    __half* __restrict__ Out)
{
    extern __shared__ __align__(16) char smem_raw[];
    const uint32_t smb  = (uint32_t)__cvta_generic_to_shared(smem_raw);
    const uint32_t q_h  = smb;
    const uint32_t stg0 = smb + F_QT_B;

    const int tid  = threadIdx.x;
    const int wid  = tid >> 5;
    const int lane = tid & 31;
    const int g    = lane >> 2;
    const int t    = lane & 3;
    const int qb   = gridDim.x - 1 - blockIdx.x;
    const int h    = blockIdx.y;
    const int kvh  = h >> 2;

    {
        const float4* Q4 = (const float4*)(Q + ((size_t)h * SEQ + (size_t)qb * 128) * HD);
        __half* Qh = (__half*)smem_raw;
        for (int f = tid; f < 4096; f += 256) {
            int row = f >> 5, d0 = (f & 31) << 2;
            float4 q = Q4[f];
            int o = row * LDB + d0;
            *(__half2*)&Qh[o]     = __halves2half2(__float2half_rn(q.x),
                                                   __float2half_rn(q.y));
            *(__half2*)&Qh[o + 2] = __halves2half2(__float2half_rn(q.z),
                                                   __float2half_rn(q.w));
        }
    }

    const int a_row = wid * 16 + (lane & 15);
    const int a_col = (lane >> 4) << 3;
    const int kb_row = (lane & 7) + (((lane >> 4) & 1) << 3);
    const int kb_col = ((lane >> 3) & 1) << 3;
    const int v_row  = (lane & 7) + (((lane >> 3) & 1) << 3);
    const int v_col  = (lane >> 4) << 3;

    float o_[16][4];
    float m0 = -INFINITY, m1 = -INFINITY, l0 = 0.f, l1 = 0.f;
#pragma unroll
    for (int j = 0; j < 16; j++)
#pragma unroll
        for (int c = 0; c < 4; c++) o_[j][c] = 0.f;

    const float scale2 = 0.12751791437073365f;   // 1/sqrt(128) * log2(e)
    const int rl0 = wid * 16 + g;
    const int rl1 = rl0 + 8;

    const int nkb = 2 * qb + 2;
    f_fill(stg0, Khi_g, Klo_g, Vhi_g, Vlo_g, kvh, 0, tid);

    for (int kb = 0; kb < nkb; kb++) {
        const int buf = kb & 1;
        asm volatile("cp.async.wait_group 0;" ::: "memory");
        __syncthreads();
        if (kb + 1 < nkb)
            f_fill(stg0 + (buf ^ 1) * F_STG_B, Khi_g, Klo_g, Vhi_g, Vlo_g,
                   kvh, kb + 1, tid);

        const int kofs = kb * 64 - qb * 128;
        if (kofs <= wid * 16 + 15) {
            const uint32_t khi_s = stg0 + buf * F_STG_B;
            const uint32_t klo_s = khi_s + F_KT_B;
            const uint32_t vhi_s = khi_s + 2 * F_KT_B;
            const uint32_t vlo_s = khi_s + 3 * F_KT_B;

            float sc[8][4];
#pragma unroll
            for (int j = 0; j < 8; j++)
#pragma unroll
                for (int c = 0; c < 4; c++) sc[j][c] = 0.f;

#pragma unroll
            for (int ks = 0; ks < 8; ks++) {
                uint32_t ahf[4];
                uint32_t aoff = ((a_row * LDB) + (ks * 16 + a_col)) * 2;
                ldsm4(ahf, q_h + aoff);
#pragma unroll
                for (int jp = 0; jp < 4; jp++) {
                    uint32_t bh[4], bl[4];
                    uint32_t boff = (((jp * 16 + kb_row) * LDB)
                                     + (ks * 16 + kb_col)) * 2;
                    ldsm4(bh, khi_s + boff);
                    ldsm4(bl, klo_s + boff);
                    mma_f16(sc[2 * jp],     ahf, bh[0], bh[1]);
                    mma_f16(sc[2 * jp],     ahf, bl[0], bl[1]);
                    mma_f16(sc[2 * jp + 1], ahf, bh[2], bh[3]);
                    mma_f16(sc[2 * jp + 1], ahf, bl[2], bl[3]);
                }
            }

            const bool diag = (kofs + 63 > rl0);
            float tm0 = -INFINITY, tm1 = -INFINITY;
#pragma unroll
            for (int j = 0; j < 8; j++) {
                float v0 = sc[j][0] * scale2, v1 = sc[j][1] * scale2;
                float v2 = sc[j][2] * scale2, v3 = sc[j][3] * scale2;
                if (diag) {
                    int c0 = kofs + 8 * j + 2 * t;
                    if (c0     > rl0) v0 = -INFINITY;
                    if (c0 + 1 > rl0) v1 = -INFINITY;
                    if (c0     > rl1) v2 = -INFINITY;
                    if (c0 + 1 > rl1) v3 = -INFINITY;
                }
                sc[j][0] = v0; sc[j][1] = v1; sc[j][2] = v2; sc[j][3] = v3;
                tm0 = fmaxf(tm0, fmaxf(v0, v1));
                tm1 = fmaxf(tm1, fmaxf(v2, v3));
            }
            tm0 = fmaxf(tm0, __shfl_xor_sync(0xffffffffu, tm0, 1));
            tm0 = fmaxf(tm0, __shfl_xor_sync(0xffffffffu, tm0, 2));
            tm1 = fmaxf(tm1, __shfl_xor_sync(0xffffffffu, tm1, 1));
            tm1 = fmaxf(tm1, __shfl_xor_sync(0xffffffffu, tm1, 2));

            float mn0 = fmaxf(m0, tm0), mn1 = fmaxf(m1, tm1);
            float al0 = ex2a(m0 - mn0), al1 = ex2a(m1 - mn1);
            m0 = mn0; m1 = mn1;

            float rs0 = 0.f, rs1 = 0.f;
#pragma unroll
            for (int j = 0; j < 8; j++) {
                sc[j][0] = ex2a(sc[j][0] - mn0);
                sc[j][1] = ex2a(sc[j][1] - mn0);
                sc[j][2] = ex2a(sc[j][2] - mn1);
                sc[j][3] = ex2a(sc[j][3] - mn1);
                rs0 += sc[j][0] + sc[j][1];
                rs1 += sc[j][2] + sc[j][3];
            }
            rs0 += __shfl_xor_sync(0xffffffffu, rs0, 1);
            rs0 += __shfl_xor_sync(0xffffffffu, rs0, 2);
            rs1 += __shfl_xor_sync(0xffffffffu, rs1, 1);
            rs1 += __shfl_xor_sync(0xffffffffu, rs1, 2);
            l0 = l0 * al0 + rs0;
            l1 = l1 * al1 + rs1;

#pragma unroll
            for (int j = 0; j < 16; j++) {
                o_[j][0] *= al0; o_[j][1] *= al0;
                o_[j][2] *= al1; o_[j][3] *= al1;
            }

            uint32_t pa[4][4];
#pragma unroll
            for (int kc = 0; kc < 4; kc++) {
                int j0 = 2 * kc, j1 = j0 + 1;
                pa[kc][0] = pack_f16(sc[j0][0], sc[j0][1]);
                pa[kc][1] = pack_f16(sc[j0][2], sc[j0][3]);
                pa[kc][2] = pack_f16(sc[j1][0], sc[j1][1]);
                pa[kc][3] = pack_f16(sc[j1][2], sc[j1][3]);
            }

#pragma unroll
            for (int kc = 0; kc < 4; kc++) {
#pragma unroll
                for (int jp = 0; jp < 8; jp++) {
                    uint32_t vh[4], vl[4];
                    uint32_t voff = (((kc * 16 + v_row) * LDB)
                                     + (jp * 16 + v_col)) * 2;
                    ldsm4t(vh, vhi_s + voff);
                    ldsm4t(vl, vlo_s + voff);
                    mma_f16(o_[2 * jp],     pa[kc], vh[0], vh[1]);
                    mma_f16(o_[2 * jp],     pa[kc], vl[0], vl[1]);
                    mma_f16(o_[2 * jp + 1], pa[kc], vh[2], vh[3]);
                    mma_f16(o_[2 * jp + 1], pa[kc], vl[2], vl[3]);
                }
            }
        }
    }

    // write out as fp16 (consumed by fp16 O-proj)
    float inv0 = rcpa(l0), inv1 = rcpa(l1);
    size_t r0 = (size_t)qb * 128 + wid * 16 + g;
    __half* base0 = Out + r0 * HID + (size_t)h * HD;
    __half* base1 = base0 + (size_t)8 * HID;
#pragma unroll
    for (int j = 0; j < 16; j++) {
        int col = 8 * j + 2 * t;
        *(__half2*)(base0 + col) =
            __halves2half2(__float2half_rn(o_[j][0] * inv0),
                           __float2half_rn(o_[j][1] * inv0));
        *(__half2*)(base1 + col) =
            __halves2half2(__float2half_rn(o_[j][2] * inv1),
                           __float2half_rn(o_[j][3] * inv1));
    }
}

// ---------------------------------------------------------------------------
extern "C" void kernel_launch(void* const* d_in, const int* in_sizes, int n_in,
                              void* d_out, int out_size)
{
    const float* Hs = (const float*)d_in[0];
    const float* Wq = (const float*)d_in[1];
    const float* Wk = (const float*)d_in[2];
    const float* Wv = (const float*)d_in[3];
    const float* Wo = (const float*)d_in[4];
    const int*  pos = (const int*)d_in[5];
    float* out = (float*)d_out;

    float *Qp, *KVp;
    __half *Ah, *hH, *hWq, *hWkv, *hWo, *Khi, *Klo, *Vhi, *Vlo;
    cudaGetSymbolAddress((void**)&Qp,   g_Q);
    cudaGetSymbolAddress((void**)&KVp,  g_KV);
    cudaGetSymbolAddress((void**)&Ah,   g_Ah);
    cudaGetSymbolAddress((void**)&hH,   g_hH);
    cudaGetSymbolAddress((void**)&hWq,  g_hWq);
    cudaGetSymbolAddress((void**)&hWkv, g_hWkv);
    cudaGetSymbolAddress((void**)&hWo,  g_hWo);
    cudaGetSymbolAddress((void**)&Khi, g_Khi);
    cudaGetSymbolAddress((void**)&Klo, g_Klo);
    cudaGetSymbolAddress((void**)&Vhi, g_Vhi);
    cudaGetSymbolAddress((void**)&Vlo, g_Vlo);

    float* Kp = KVp;
    float* Vp = KVp + (size_t)NKV * SEQ * HD;

    cudaFuncSetAttribute(flash_v2, cudaFuncAttributeMaxDynamicSharedMemorySize,
                         F_SMEM);
    cudaFuncSetAttribute(gemm_f16, cudaFuncAttributeMaxDynamicSharedMemorySize,
                         G_SMEM);

    // fp16 pre-rounding
    const int nH4 = SEQ * HID / 4, nW4 = HID * HID / 4, nKV4 = NKV * HD * HID / 4;
    round_f16<<<nH4 / 256, 256>>>((const float4*)Hs, (__half2*)hH, nH4);
    round_f16<<<nW4 / 256, 256>>>((const float4*)Wq, (__half2*)hWq, nW4);
    round_f16<<<nKV4 / 256, 256>>>((const float4*)Wk, (__half2*)hWkv, nKV4);
    round_f16<<<nKV4 / 256, 256>>>((const float4*)Wv,
                                   (__half2*)(hWkv + (size_t)NKV * HD * HID), nKV4);
    round_f16<<<nW4 / 256, 256>>>((const float4*)Wo, (__half2*)hWo, nW4);

    // projections (fp16 mma), head-major scatter
    gemm_f16<<<dim3(HID / 256, SEQ / 128), 256, G_SMEM>>>(hH, hWq, Qp,
                                                          SEQ, HID, HID, 1);
    gemm_f16<<<dim3(2 * NKV * HD / 256, SEQ / 128), 256, G_SMEM>>>(
        hH, hWkv, KVp, SEQ, 2 * NKV * HD, HID, 1);

    rope_kernel<<<((NHEADS + NKV) * SEQ * 64) / 256, 256>>>(Qp, Kp, Khi, Klo, pos);

    const int nV4 = NKV * SEQ * HD / 4;
    split_kernel<<<nV4 / 256, 256>>>((const float4*)Vp,
        (__half2*)Vhi, (__half2*)Vlo, nV4);

    flash_v2<<<dim3(SEQ / 128, NHEADS), 256, F_SMEM>>>(Qp, Khi, Klo, Vhi, Vlo, Ah);

    gemm_f16<<<dim3(HID / 256, SEQ / 128), 256, G_SMEM>>>(Ah, hWo, out,
                                                          SEQ, HID, HID, 0);
}

// round 13
// speedup vs baseline: 1.4655x; 1.0421x over previous
#include <cuda_runtime.h>
#include <cuda_bf16.h>
#include <cuda_fp16.h>
#include <math.h>
#include <stdint.h>

#define SEQ    4096
#define HID    4096
#define NHEADS 32
#define NKV    8
#define HD     128

// ---------------- device scratch (allocation-free rule) ----------------
__device__ float  g_Q[(size_t)NHEADS * SEQ * HD];     // [head][seq][128]
__device__ float  g_KV[(size_t)2 * NKV * SEQ * HD];   // K heads 0-7, V heads 8-15
__device__ __half g_Ah[(size_t)SEQ * HID];            // flash out (fp16)
__device__ __half g_hH[(size_t)SEQ * HID];            // fp16-rounded operands
__device__ __half g_hWq[(size_t)HID * HID];
__device__ __half g_hWkv[(size_t)2 * NKV * HD * HID]; // Wk rows 0-1023, Wv 1024-2047
__device__ __half g_hWo[(size_t)HID * HID];
__device__ __half g_Khi[(size_t)NKV * SEQ * HD];      // split K (post-rope), fp16
__device__ __half g_Klo[(size_t)NKV * SEQ * HD];
__device__ __half g_Vhi[(size_t)NKV * SEQ * HD];
__device__ __half g_Vlo[(size_t)NKV * SEQ * HD];

__device__ __forceinline__ float ex2a(float x) {
    float y;
    asm("ex2.approx.f32 %0, %1;" : "=f"(y) : "f"(x));
    return y;
}
__device__ __forceinline__ float rcpa(float x) {
    float y;
    asm("rcp.approx.f32 %0, %1;" : "=f"(y) : "f"(x));
    return y;
}
__device__ __forceinline__ void cp16(uint32_t dst, const void* src) {
    asm volatile("cp.async.cg.shared.global [%0], [%1], 16;"
                 :: "r"(dst), "l"(src) : "memory");
}
__device__ __forceinline__ void cp_commit() {
    asm volatile("cp.async.commit_group;" ::: "memory");
}
__device__ __forceinline__ void cvt_hl_h(float x, __half& h, __half& l) {
    h = __float2half_rn(x);
    l = __float2half_rn(x - __half2float(h));
}

// ---------------------------------------------------------------------------
// Pre-round fp32 -> fp16 (rn)
// ---------------------------------------------------------------------------
__global__ __launch_bounds__(256) void round_f16(const float4* __restrict__ in,
                                                 __half2* __restrict__ out, int n4)
{
    int i = blockIdx.x * blockDim.x + threadIdx.x;
    if (i >= n4) return;
    float4 v = in[i];
    out[2 * i]     = __halves2half2(__float2half_rn(v.x), __float2half_rn(v.y));
    out[2 * i + 1] = __halves2half2(__float2half_rn(v.z), __float2half_rn(v.w));
}

// ---------------------------------------------------------------------------
// fp32 -> (hi, lo) fp16 split (for V)
// ---------------------------------------------------------------------------
__global__ __launch_bounds__(256) void split_kernel(const float4* __restrict__ in,
                                                    __half2* __restrict__ hi,
                                                    __half2* __restrict__ lo,
                                                    int n4)
{
    int i = blockIdx.x * blockDim.x + threadIdx.x;
    if (i >= n4) return;
    float4 v = in[i];
    __half h0, l0, h1, l1, h2, l2, h3, l3;
    cvt_hl_h(v.x, h0, l0); cvt_hl_h(v.y, h1, l1);
    cvt_hl_h(v.z, h2, l2); cvt_hl_h(v.w, h3, l3);
    hi[2 * i]     = __halves2half2(h0, h1);
    hi[2 * i + 1] = __halves2half2(h2, h3);
    lo[2 * i]     = __halves2half2(l0, l1);
    lo[2 * i + 1] = __halves2half2(l2, l3);
}

// ---------------------------------------------------------------------------
// ldmatrix / mma helpers (shared by GEMM and flash)
// ---------------------------------------------------------------------------
__device__ __forceinline__ void ldsm4(uint32_t a[4], uint32_t addr) {
    asm volatile("ldmatrix.sync.aligned.m8n8.x4.shared.b16 {%0,%1,%2,%3}, [%4];"
        : "=r"(a[0]), "=r"(a[1]), "=r"(a[2]), "=r"(a[3]) : "r"(addr));
}
__device__ __forceinline__ void ldsm4t(uint32_t a[4], uint32_t addr) {
    asm volatile("ldmatrix.sync.aligned.m8n8.x4.trans.shared.b16 {%0,%1,%2,%3}, [%4];"
        : "=r"(a[0]), "=r"(a[1]), "=r"(a[2]), "=r"(a[3]) : "r"(addr));
}
__device__ __forceinline__ void mma_f16(float c[4], const uint32_t a[4],
                                        uint32_t b0, uint32_t b1) {
    asm volatile(
        "mma.sync.aligned.m16n8k16.row.col.f32.f16.f16.f32 "
        "{%0,%1,%2,%3}, {%4,%5,%6,%7}, {%8,%9}, {%0,%1,%2,%3};"
        : "+f"(c[0]), "+f"(c[1]), "+f"(c[2]), "+f"(c[3])
        : "r"(a[0]), "r"(a[1]), "r"(a[2]), "r"(a[3]), "r"(b0), "r"(b1));
}
__device__ __forceinline__ uint32_t pack_f16(float lo, float hi) {
    uint32_t r;
    asm("cvt.rn.f16x2.f32 %0, %1, %2;" : "=r"(r) : "f"(hi), "f"(lo));
    return r;
}

// ---------------------------------------------------------------------------
// FP16 GEMM (unchanged from R12): C = A(MxK) * B(NxK)^T, fp32 accum.
// CTA 128x256, K-tile 64 (4 x k16), 3-stage cp.async, one sync per iter.
// ---------------------------------------------------------------------------
#define GH_A_B  (128 * 144)
#define GH_B_B  (256 * 144)
#define GH_ST   (GH_A_B + GH_B_B)         // 55296 B
#define G_SMEM  (3 * GH_ST)               // 165888 B

__device__ __forceinline__ void g_fill_h(uint32_t smb, int buf,
    const __half* __restrict__ A, const __half* __restrict__ B,
    int bm, int bn, int K, int kt, int tid)
{
    const uint32_t sa = smb + buf * GH_ST;
    const uint32_t sb = sa + GH_A_B;
    const size_t kof = (size_t)kt << 6;
    for (int i = tid; i < 1024; i += 256) {
        int row = i >> 3, ch = (i & 7) << 4;
        cp16(sa + row * 144 + ch,
             (const char*)(A + (size_t)(bm + row) * K + kof) + ch);
    }
    for (int i = tid; i < 2048; i += 256) {
        int row = i >> 3, ch = (i & 7) << 4;
        cp16(sb + row * 144 + ch,
             (const char*)(B + (size_t)(bn + row) * K + kof) + ch);
    }
    cp_commit();
}

__global__ __launch_bounds__(256, 1) void gemm_f16(
    const __half* __restrict__ A, const __half* __restrict__ B,
    float* __restrict__ C, int M, int N, int K, int mode)
{
    extern __shared__ __align__(16) char sm[];
    const uint32_t smb = (uint32_t)__cvta_generic_to_shared(sm);

    const int tid  = threadIdx.x;
    const int warp = tid >> 5;
    const int lane = tid & 31;
    const int wm   = warp & 1;
    const int wn   = warp >> 1;
    const int g    = lane >> 2;
    const int t4   = lane & 3;
    const int bm   = blockIdx.y * 128;
    const int bn   = blockIdx.x * 256;

    const int a_rl  = lane & 15;
    const int a_cl  = (lane >> 4) << 3;
    const int b_rl  = (lane & 7) + (((lane >> 4) & 1) << 3);
    const int b_cl  = ((lane >> 3) & 1) << 3;

    float acc[4][8][4];
#pragma unroll
    for (int mt = 0; mt < 4; mt++)
#pragma unroll
        for (int nt = 0; nt < 8; nt++)
#pragma unroll
            for (int c = 0; c < 4; c++) acc[mt][nt][c] = 0.f;

    const int KT = K >> 6;
    g_fill_h(smb, 0, A, B, bm, bn, K, 0, tid);
    g_fill_h(smb, 1, A, B, bm, bn, K, 1, tid);

    int buf = 0;
    for (int kt = 0; kt < KT; kt++) {
        if (kt < KT - 1) {
            asm volatile("cp.async.wait_group 1;" ::: "memory");
        } else {
            asm volatile("cp.async.wait_group 0;" ::: "memory");
        }
        __syncthreads();
        if (kt + 2 < KT) {
            int nb = buf + 2; if (nb >= 3) nb -= 3;
            g_fill_h(smb, nb, A, B, bm, bn, K, kt + 2, tid);
        }

        const uint32_t sa = smb + buf * GH_ST;
        const uint32_t sb = sa + GH_A_B;

#pragma unroll
        for (int ks = 0; ks < 4; ks++) {
            uint32_t af[4][4];
#pragma unroll
            for (int mt = 0; mt < 4; mt++) {
                uint32_t r = wm * 64 + mt * 16 + a_rl;
                ldsm4(af[mt], sa + (r * 72 + ks * 16 + a_cl) * 2);
            }
#pragma unroll
            for (int jp = 0; jp < 4; jp++) {
                uint32_t bf[4];
                uint32_t r = wn * 64 + jp * 16 + b_rl;
                ldsm4(bf, sb + (r * 72 + ks * 16 + b_cl) * 2);
#pragma unroll
                for (int mt = 0; mt < 4; mt++) {
                    mma_f16(acc[mt][2 * jp],     af[mt], bf[0], bf[1]);
                    mma_f16(acc[mt][2 * jp + 1], af[mt], bf[2], bf[3]);
                }
            }
        }
        if (++buf == 3) buf = 0;
    }

#pragma unroll
    for (int mt = 0; mt < 4; mt++) {
#pragma unroll
        for (int nt = 0; nt < 8; nt++) {
            int row = bm + wm * 64 + mt * 16 + g;
            int col = bn + wn * 64 + nt * 8 + 2 * t4;
            if (mode == 0) {
                *(float2*)(C + (size_t)row * N + col) =
                    make_float2(acc[mt][nt][0], acc[mt][nt][1]);
                *(float2*)(C + (size_t)(row + 8) * N + col) =
                    make_float2(acc[mt][nt][2], acc[mt][nt][3]);
            } else {
                int h = col >> 7, d = col & 127;
                *(float2*)(C + ((size_t)h * M + row) * HD + d) =
                    make_float2(acc[mt][nt][0], acc[mt][nt][1]);
                *(float2*)(C + ((size_t)h * M + row + 8) * HD + d) =
                    make_float2(acc[mt][nt][2], acc[mt][nt][3]);
            }
        }
    }
}

// ---------------------------------------------------------------------------
// RoPE: Q in place (fp32); K -> split hi/lo fp16 global
// ---------------------------------------------------------------------------
__global__ __launch_bounds__(256) void rope_kernel(float* __restrict__ Q,
                                                   const float* __restrict__ Kc,
                                                   __half* __restrict__ Khi,
                                                   __half* __restrict__ Klo,
                                                   const int* __restrict__ pos)
{
    int idx = blockIdx.x * blockDim.x + threadIdx.x;
    int d = idx & 63;
    int s = (idx >> 6) & (SEQ - 1);
    int h = idx >> 18;

    double ang = (double)pos[s] * exp(-(double)d * (9.210340371976184 / 64.0));
    float c  = (float)cos(ang);
    float si = (float)sin(ang);

    if (h < NHEADS) {
        float* base = Q + ((size_t)h * SEQ + s) * HD;
        float x1 = base[d], x2 = base[d + 64];
        base[d]      = x1 * c - x2 * si;
        base[d + 64] = x2 * c + x1 * si;
    } else {
        size_t o = ((size_t)(h - NHEADS) * SEQ + s) * HD;
        float x1 = Kc[o + d], x2 = Kc[o + d + 64];
        float r1 = x1 * c - x2 * si;
        float r2 = x2 * c + x1 * si;
        __half hh, ll;
        cvt_hl_h(r1, hh, ll); Khi[o + d] = hh;       Klo[o + d] = ll;
        cvt_hl_h(r2, hh, ll); Khi[o + d + 64] = hh;  Klo[o + d + 64] = ll;
    }
}

// ---------------------------------------------------------------------------
// flash fp16x2, SINGLE-buffered KV stage -> 104448 B smem -> 2 CTAs/SM
// (4 warps/SMSP). Cross-CTA overlap replaces intra-CTA double buffering.
// ---------------------------------------------------------------------------
#define LDB 136

#define F_QT_B  (128 * LDB * 2)          // 34816
#define F_KT_B  (64 * LDB * 2)           // 17408
#define F_STG_B (4 * F_KT_B)             // 69632
#define F_SMEM  (F_QT_B + F_STG_B)       // 104448 -> 2 CTAs/SM

__device__ __forceinline__ void f_fill(uint32_t stg,
    const __half* Khi_g, const __half* Klo_g,
    const __half* Vhi_g, const __half* Vlo_g,
    int kvh, int kb, int tid)
{
    const size_t gof = ((size_t)kvh * SEQ + (size_t)kb * 64) * HD;
    const char* kh = (const char*)(Khi_g + gof);
    const char* kl = (const char*)(Klo_g + gof);
    const char* vh = (const char*)(Vhi_g + gof);
    const char* vl = (const char*)(Vlo_g + gof);
    for (int i = tid; i < 1024; i += 256) {
        int row = i >> 4, ch = (i & 15) << 4;
        uint32_t dst = row * (LDB * 2) + ch;
        int src = row * 256 + ch;
        cp16(stg + dst,               kh + src);
        cp16(stg + F_KT_B + dst,      kl + src);
        cp16(stg + 2 * F_KT_B + dst,  vh + src);
        cp16(stg + 3 * F_KT_B + dst,  vl + src);
    }
    cp_commit();
}

__global__ __launch_bounds__(256, 2) void flash_v2(
    const float* __restrict__ Q,
    const __half* __restrict__ Khi_g, const __half* __restrict__ Klo_g,
    const __half* __restrict__ Vhi_g, const __half* __restrict__ Vlo_g,
    __half* __restrict__ Out)
{
    extern __shared__ __align__(16) char smem_raw[];
    const uint32_t smb  = (uint32_t)__cvta_generic_to_shared(smem_raw);
    const uint32_t q_h  = smb;
    const uint32_t stg0 = smb + F_QT_B;

    const int tid  = threadIdx.x;
    const int wid  = tid >> 5;
    const int lane = tid & 31;
    const int g    = lane >> 2;
    const int t    = lane & 3;
    const int qb   = gridDim.x - 1 - blockIdx.x;
    const int h    = blockIdx.y;
    const int kvh  = h >> 2;

    // issue KV fill for tile 0 first (cp.async), then split Q while it flies
    const int nkb = 2 * qb + 2;
    f_fill(stg0, Khi_g, Klo_g, Vhi_g, Vlo_g, kvh, 0, tid);

    {
        const float4* Q4 = (const float4*)(Q + ((size_t)h * SEQ + (size_t)qb * 128) * HD);
        __half* Qh = (__half*)smem_raw;
        for (int f = tid; f < 4096; f += 256) {
            int row = f >> 5, d0 = (f & 31) << 2;
            float4 q = Q4[f];
            int o = row * LDB + d0;
            *(__half2*)&Qh[o]     = __halves2half2(__float2half_rn(q.x),
                                                   __float2half_rn(q.y));
            *(__half2*)&Qh[o + 2] = __halves2half2(__float2half_rn(q.z),
                                                   __float2half_rn(q.w));
        }
    }

    const int a_row = wid * 16 + (lane & 15);
    const int a_col = (lane >> 4) << 3;
    const int kb_row = (lane & 7) + (((lane >> 4) & 1) << 3);
    const int kb_col = ((lane >> 3) & 1) << 3;
    const int v_row  = (lane & 7) + (((lane >> 3) & 1) << 3);
    const int v_col  = (lane >> 4) << 3;

    float o_[16][4];
    float m0 = -INFINITY, m1 = -INFINITY, l0 = 0.f, l1 = 0.f;
#pragma unroll
    for (int j = 0; j < 16; j++)
#pragma unroll
        for (int c = 0; c < 4; c++) o_[j][c] = 0.f;

    const float scale2 = 0.12751791437073365f;   // 1/sqrt(128) * log2(e)
    const int rl0 = wid * 16 + g;
    const int rl1 = rl0 + 8;

    for (int kb = 0; kb < nkb; kb++) {
        asm volatile("cp.async.wait_group 0;" ::: "memory");
        __syncthreads();                 // fill(kb) visible to all

        const int kofs = kb * 64 - qb * 128;
        if (kofs <= wid * 16 + 15) {
            const uint32_t khi_s = stg0;
            const uint32_t klo_s = stg0 + F_KT_B;
            const uint32_t vhi_s = stg0 + 2 * F_KT_B;
            const uint32_t vlo_s = stg0 + 3 * F_KT_B;

            float sc[8][4];
#pragma unroll
            for (int j = 0; j < 8; j++)
#pragma unroll
                for (int c = 0; c < 4; c++) sc[j][c] = 0.f;

#pragma unroll
            for (int ks = 0; ks < 8; ks++) {
                uint32_t ahf[4];
                uint32_t aoff = ((a_row * LDB) + (ks * 16 + a_col)) * 2;
                ldsm4(ahf, q_h + aoff);
#pragma unroll
                for (int jp = 0; jp < 4; jp++) {
                    uint32_t bh[4], bl[4];
                    uint32_t boff = (((jp * 16 + kb_row) * LDB)
                                     + (ks * 16 + kb_col)) * 2;
                    ldsm4(bh, khi_s + boff);
                    ldsm4(bl, klo_s + boff);
                    mma_f16(sc[2 * jp],     ahf, bh[0], bh[1]);
                    mma_f16(sc[2 * jp],     ahf, bl[0], bl[1]);
                    mma_f16(sc[2 * jp + 1], ahf, bh[2], bh[3]);
                    mma_f16(sc[2 * jp + 1], ahf, bl[2], bl[3]);
                }
            }

            const bool diag = (kofs + 63 > rl0);
            float tm0 = -INFINITY, tm1 = -INFINITY;
#pragma unroll
            for (int j = 0; j < 8; j++) {
                float v0 = sc[j][0] * scale2, v1 = sc[j][1] * scale2;
                float v2 = sc[j][2] * scale2, v3 = sc[j][3] * scale2;
                if (diag) {
                    int c0 = kofs + 8 * j + 2 * t;
                    if (c0     > rl0) v0 = -INFINITY;
                    if (c0 + 1 > rl0) v1 = -INFINITY;
                    if (c0     > rl1) v2 = -INFINITY;
                    if (c0 + 1 > rl1) v3 = -INFINITY;
                }
                sc[j][0] = v0; sc[j][1] = v1; sc[j][2] = v2; sc[j][3] = v3;
                tm0 = fmaxf(tm0, fmaxf(v0, v1));
                tm1 = fmaxf(tm1, fmaxf(v2, v3));
            }
            tm0 = fmaxf(tm0, __shfl_xor_sync(0xffffffffu, tm0, 1));
            tm0 = fmaxf(tm0, __shfl_xor_sync(0xffffffffu, tm0, 2));
            tm1 = fmaxf(tm1, __shfl_xor_sync(0xffffffffu, tm1, 1));
            tm1 = fmaxf(tm1, __shfl_xor_sync(0xffffffffu, tm1, 2));

            float mn0 = fmaxf(m0, tm0), mn1 = fmaxf(m1, tm1);
            float al0 = ex2a(m0 - mn0), al1 = ex2a(m1 - mn1);
            m0 = mn0; m1 = mn1;

            float rs0 = 0.f, rs1 = 0.f;
#pragma unroll
            for (int j = 0; j < 8; j++) {
                sc[j][0] = ex2a(sc[j][0] - mn0);
                sc[j][1] = ex2a(sc[j][1] - mn0);
                sc[j][2] = ex2a(sc[j][2] - mn1);
                sc[j][3] = ex2a(sc[j][3] - mn1);
                rs0 += sc[j][0] + sc[j][1];
                rs1 += sc[j][2] + sc[j][3];
            }
            rs0 += __shfl_xor_sync(0xffffffffu, rs0, 1);
            rs0 += __shfl_xor_sync(0xffffffffu, rs0, 2);
            rs1 += __shfl_xor_sync(0xffffffffu, rs1, 1);
            rs1 += __shfl_xor_sync(0xffffffffu, rs1, 2);
            l0 = l0 * al0 + rs0;
            l1 = l1 * al1 + rs1;

#pragma unroll
            for (int j = 0; j < 16; j++) {
                o_[j][0] *= al0; o_[j][1] *= al0;
                o_[j][2] *= al1; o_[j][3] *= al1;
            }

            uint32_t pa[4][4];
#pragma unroll
            for (int kc = 0; kc < 4; kc++) {
                int j0 = 2 * kc, j1 = j0 + 1;
                pa[kc][0] = pack_f16(sc[j0][0], sc[j0][1]);
                pa[kc][1] = pack_f16(sc[j0][2], sc[j0][3]);
                pa[kc][2] = pack_f16(sc[j1][0], sc[j1][1]);
                pa[kc][3] = pack_f16(sc[j1][2], sc[j1][3]);
            }

#pragma unroll
            for (int kc = 0; kc < 4; kc++) {
#pragma unroll
                for (int jp = 0; jp < 8; jp++) {
                    uint32_t vh[4], vl[4];
                    uint32_t voff = (((kc * 16 + v_row) * LDB)
                                     + (jp * 16 + v_col)) * 2;
                    ldsm4t(vh, vhi_s + voff);
                    ldsm4t(vl, vlo_s + voff);
                    mma_f16(o_[2 * jp],     pa[kc], vh[0], vh[1]);
                    mma_f16(o_[2 * jp],     pa[kc], vl[0], vl[1]);
                    mma_f16(o_[2 * jp + 1], pa[kc], vh[2], vh[3]);
                    mma_f16(o_[2 * jp + 1], pa[kc], vl[2], vl[3]);
                }
            }
        }

        __syncthreads();                 // compute done before refill
        if (kb + 1 < nkb)
            f_fill(stg0, Khi_g, Klo_g, Vhi_g, Vlo_g, kvh, kb + 1, tid);
    }

    // write out as fp16 (consumed by fp16 O-proj)
    float inv0 = rcpa(l0), inv1 = rcpa(l1);
    size_t r0 = (size_t)qb * 128 + wid * 16 + g;
    __half* base0 = Out + r0 * HID + (size_t)h * HD;
    __half* base1 = base0 + (size_t)8 * HID;
#pragma unroll
    for (int j = 0; j < 16; j++) {
        int col = 8 * j + 2 * t;
        *(__half2*)(base0 + col) =
            __halves2half2(__float2half_rn(o_[j][0] * inv0),
                           __float2half_rn(o_[j][1] * inv0));
        *(__half2*)(base1 + col) =
            __halves2half2(__float2half_rn(o_[j][2] * inv1),
                           __float2half_rn(o_[j][3] * inv1));
    }
}

// ---------------------------------------------------------------------------
extern "C" void kernel_launch(void* const* d_in, const int* in_sizes, int n_in,
                              void* d_out, int out_size)
{
    const float* Hs = (const float*)d_in[0];
    const float* Wq = (const float*)d_in[1];
    const float* Wk = (const float*)d_in[2];
    const float* Wv = (const float*)d_in[3];
    const float* Wo = (const float*)d_in[4];
    const int*  pos = (const int*)d_in[5];
    float* out = (float*)d_out;

    float *Qp, *KVp;
    __half *Ah, *hH, *hWq, *hWkv, *hWo, *Khi, *Klo, *Vhi, *Vlo;
    cudaGetSymbolAddress((void**)&Qp,   g_Q);
    cudaGetSymbolAddress((void**)&KVp,  g_KV);
    cudaGetSymbolAddress((void**)&Ah,   g_Ah);
    cudaGetSymbolAddress((void**)&hH,   g_hH);
    cudaGetSymbolAddress((void**)&hWq,  g_hWq);
    cudaGetSymbolAddress((void**)&hWkv, g_hWkv);
    cudaGetSymbolAddress((void**)&hWo,  g_hWo);
    cudaGetSymbolAddress((void**)&Khi, g_Khi);
    cudaGetSymbolAddress((void**)&Klo, g_Klo);
    cudaGetSymbolAddress((void**)&Vhi, g_Vhi);
    cudaGetSymbolAddress((void**)&Vlo, g_Vlo);

    float* Kp = KVp;
    float* Vp = KVp + (size_t)NKV * SEQ * HD;

    cudaFuncSetAttribute(flash_v2, cudaFuncAttributeMaxDynamicSharedMemorySize,
                         F_SMEM);
    cudaFuncSetAttribute(gemm_f16, cudaFuncAttributeMaxDynamicSharedMemorySize,
                         G_SMEM);

    // fp16 pre-rounding
    const int nH4 = SEQ * HID / 4, nW4 = HID * HID / 4, nKV4 = NKV * HD * HID / 4;
    round_f16<<<nH4 / 256, 256>>>((const float4*)Hs, (__half2*)hH, nH4);
    round_f16<<<nW4 / 256, 256>>>((const float4*)Wq, (__half2*)hWq, nW4);
    round_f16<<<nKV4 / 256, 256>>>((const float4*)Wk, (__half2*)hWkv, nKV4);
    round_f16<<<nKV4 / 256, 256>>>((const float4*)Wv,
                                   (__half2*)(hWkv + (size_t)NKV * HD * HID), nKV4);
    round_f16<<<nW4 / 256, 256>>>((const float4*)Wo, (__half2*)hWo, nW4);

    // projections (fp16 mma), head-major scatter
    gemm_f16<<<dim3(HID / 256, SEQ / 128), 256, G_SMEM>>>(hH, hWq, Qp,
                                                          SEQ, HID, HID, 1);
    gemm_f16<<<dim3(2 * NKV * HD / 256, SEQ / 128), 256, G_SMEM>>>(
        hH, hWkv, KVp, SEQ, 2 * NKV * HD, HID, 1);

    rope_kernel<<<((NHEADS + NKV) * SEQ * 64) / 256, 256>>>(Qp, Kp, Khi, Klo, pos);

    const int nV4 = NKV * SEQ * HD / 4;
    split_kernel<<<nV4 / 256, 256>>>((const float4*)Vp,
        (__half2*)Vhi, (__half2*)Vlo, nV4);

    flash_v2<<<dim3(SEQ / 128, NHEADS), 256, F_SMEM>>>(Qp, Khi, Klo, Vhi, Vlo, Ah);

    gemm_f16<<<dim3(HID / 256, SEQ / 128), 256, G_SMEM>>>(Ah, hWo, out,
                                                          SEQ, HID, HID, 0);
}

// round 14
// speedup vs baseline: 1.5489x; 1.0569x over previous
#include <cuda_runtime.h>
#include <cuda_bf16.h>
#include <cuda_fp16.h>
#include <math.h>
#include <stdint.h>

#define SEQ    4096
#define HID    4096
#define NHEADS 32
#define NKV    8
#define HD     128

// ---------------- device scratch (allocation-free rule) ----------------
__device__ float  g_Q[(size_t)NHEADS * SEQ * HD];     // [head][seq][128]
__device__ float  g_KV[(size_t)2 * NKV * SEQ * HD];   // K heads 0-7, V heads 8-15
__device__ __half g_Ah[(size_t)SEQ * HID];            // flash out (fp16)
__device__ __half g_hH[(size_t)SEQ * HID];            // fp16-rounded operands
__device__ __half g_hWq[(size_t)HID * HID];
__device__ __half g_hWkv[(size_t)2 * NKV * HD * HID]; // Wk rows 0-1023, Wv 1024-2047
__device__ __half g_hWo[(size_t)HID * HID];
__device__ __half g_Khi[(size_t)NKV * SEQ * HD];      // split K (post-rope), fp16
__device__ __half g_Klo[(size_t)NKV * SEQ * HD];
__device__ __half g_Vh[(size_t)NKV * SEQ * HD];       // V fp16 (single term)

__device__ __forceinline__ float ex2a(float x) {
    float y;
    asm("ex2.approx.f32 %0, %1;" : "=f"(y) : "f"(x));
    return y;
}
__device__ __forceinline__ float rcpa(float x) {
    float y;
    asm("rcp.approx.f32 %0, %1;" : "=f"(y) : "f"(x));
    return y;
}
__device__ __forceinline__ void cp16(uint32_t dst, const void* src) {
    asm volatile("cp.async.cg.shared.global [%0], [%1], 16;"
                 :: "r"(dst), "l"(src) : "memory");
}
__device__ __forceinline__ void cp_commit() {
    asm volatile("cp.async.commit_group;" ::: "memory");
}
__device__ __forceinline__ void cvt_hl_h(float x, __half& h, __half& l) {
    h = __float2half_rn(x);
    l = __float2half_rn(x - __half2float(h));
}

// ---------------------------------------------------------------------------
// Pre-round fp32 -> fp16 (rn)
// ---------------------------------------------------------------------------
__global__ __launch_bounds__(256) void round_f16(const float4* __restrict__ in,
                                                 __half2* __restrict__ out, int n4)
{
    int i = blockIdx.x * blockDim.x + threadIdx.x;
    if (i >= n4) return;
    float4 v = in[i];
    out[2 * i]     = __halves2half2(__float2half_rn(v.x), __float2half_rn(v.y));
    out[2 * i + 1] = __halves2half2(__float2half_rn(v.z), __float2half_rn(v.w));
}

// ---------------------------------------------------------------------------
// ldmatrix / mma helpers (shared by GEMM and flash)
// ---------------------------------------------------------------------------
__device__ __forceinline__ void ldsm4(uint32_t a[4], uint32_t addr) {
    asm volatile("ldmatrix.sync.aligned.m8n8.x4.shared.b16 {%0,%1,%2,%3}, [%4];"
        : "=r"(a[0]), "=r"(a[1]), "=r"(a[2]), "=r"(a[3]) : "r"(addr));
}
__device__ __forceinline__ void ldsm4t(uint32_t a[4], uint32_t addr) {
    asm volatile("ldmatrix.sync.aligned.m8n8.x4.trans.shared.b16 {%0,%1,%2,%3}, [%4];"
        : "=r"(a[0]), "=r"(a[1]), "=r"(a[2]), "=r"(a[3]) : "r"(addr));
}
__device__ __forceinline__ void mma_f16(float c[4], const uint32_t a[4],
                                        uint32_t b0, uint32_t b1) {
    asm volatile(
        "mma.sync.aligned.m16n8k16.row.col.f32.f16.f16.f32 "
        "{%0,%1,%2,%3}, {%4,%5,%6,%7}, {%8,%9}, {%0,%1,%2,%3};"
        : "+f"(c[0]), "+f"(c[1]), "+f"(c[2]), "+f"(c[3])
        : "r"(a[0]), "r"(a[1]), "r"(a[2]), "r"(a[3]), "r"(b0), "r"(b1));
}
__device__ __forceinline__ uint32_t pack_f16(float lo, float hi) {
    uint32_t r;
    asm("cvt.rn.f16x2.f32 %0, %1, %2;" : "=r"(r) : "f"(hi), "f"(lo));
    return r;
}

// ---------------------------------------------------------------------------
// FP16 GEMM (unchanged from R12): C = A(MxK) * B(NxK)^T, fp32 accum.
// CTA 128x256, K-tile 64 (4 x k16), 3-stage cp.async, one sync per iter.
// ---------------------------------------------------------------------------
#define GH_A_B  (128 * 144)
#define GH_B_B  (256 * 144)
#define GH_ST   (GH_A_B + GH_B_B)         // 55296 B
#define G_SMEM  (3 * GH_ST)               // 165888 B

__device__ __forceinline__ void g_fill_h(uint32_t smb, int buf,
    const __half* __restrict__ A, const __half* __restrict__ B,
    int bm, int bn, int K, int kt, int tid)
{
    const uint32_t sa = smb + buf * GH_ST;
    const uint32_t sb = sa + GH_A_B;
    const size_t kof = (size_t)kt << 6;
    for (int i = tid; i < 1024; i += 256) {
        int row = i >> 3, ch = (i & 7) << 4;
        cp16(sa + row * 144 + ch,
             (const char*)(A + (size_t)(bm + row) * K + kof) + ch);
    }
    for (int i = tid; i < 2048; i += 256) {
        int row = i >> 3, ch = (i & 7) << 4;
        cp16(sb + row * 144 + ch,
             (const char*)(B + (size_t)(bn + row) * K + kof) + ch);
    }
    cp_commit();
}

__global__ __launch_bounds__(256, 1) void gemm_f16(
    const __half* __restrict__ A, const __half* __restrict__ B,
    float* __restrict__ C, int M, int N, int K, int mode)
{
    extern __shared__ __align__(16) char sm[];
    const uint32_t smb = (uint32_t)__cvta_generic_to_shared(sm);

    const int tid  = threadIdx.x;
    const int warp = tid >> 5;
    const int lane = tid & 31;
    const int wm   = warp & 1;
    const int wn   = warp >> 1;
    const int g    = lane >> 2;
    const int t4   = lane & 3;
    const int bm   = blockIdx.y * 128;
    const int bn   = blockIdx.x * 256;

    const int a_rl  = lane & 15;
    const int a_cl  = (lane >> 4) << 3;
    const int b_rl  = (lane & 7) + (((lane >> 4) & 1) << 3);
    const int b_cl  = ((lane >> 3) & 1) << 3;

    float acc[4][8][4];
#pragma unroll
    for (int mt = 0; mt < 4; mt++)
#pragma unroll
        for (int nt = 0; nt < 8; nt++)
#pragma unroll
            for (int c = 0; c < 4; c++) acc[mt][nt][c] = 0.f;

    const int KT = K >> 6;
    g_fill_h(smb, 0, A, B, bm, bn, K, 0, tid);
    g_fill_h(smb, 1, A, B, bm, bn, K, 1, tid);

    int buf = 0;
    for (int kt = 0; kt < KT; kt++) {
        if (kt < KT - 1) {
            asm volatile("cp.async.wait_group 1;" ::: "memory");
        } else {
            asm volatile("cp.async.wait_group 0;" ::: "memory");
        }
        __syncthreads();
        if (kt + 2 < KT) {
            int nb = buf + 2; if (nb >= 3) nb -= 3;
            g_fill_h(smb, nb, A, B, bm, bn, K, kt + 2, tid);
        }

        const uint32_t sa = smb + buf * GH_ST;
        const uint32_t sb = sa + GH_A_B;

#pragma unroll
        for (int ks = 0; ks < 4; ks++) {
            uint32_t af[4][4];
#pragma unroll
            for (int mt = 0; mt < 4; mt++) {
                uint32_t r = wm * 64 + mt * 16 + a_rl;
                ldsm4(af[mt], sa + (r * 72 + ks * 16 + a_cl) * 2);
            }
#pragma unroll
            for (int jp = 0; jp < 4; jp++) {
                uint32_t bf[4];
                uint32_t r = wn * 64 + jp * 16 + b_rl;
                ldsm4(bf, sb + (r * 72 + ks * 16 + b_cl) * 2);
#pragma unroll
                for (int mt = 0; mt < 4; mt++) {
                    mma_f16(acc[mt][2 * jp],     af[mt], bf[0], bf[1]);
                    mma_f16(acc[mt][2 * jp + 1], af[mt], bf[2], bf[3]);
                }
            }
        }
        if (++buf == 3) buf = 0;
    }

#pragma unroll
    for (int mt = 0; mt < 4; mt++) {
#pragma unroll
        for (int nt = 0; nt < 8; nt++) {
            int row = bm + wm * 64 + mt * 16 + g;
            int col = bn + wn * 64 + nt * 8 + 2 * t4;
            if (mode == 0) {
                *(float2*)(C + (size_t)row * N + col) =
                    make_float2(acc[mt][nt][0], acc[mt][nt][1]);
                *(float2*)(C + (size_t)(row + 8) * N + col) =
                    make_float2(acc[mt][nt][2], acc[mt][nt][3]);
            } else {
                int h = col >> 7, d = col & 127;
                *(float2*)(C + ((size_t)h * M + row) * HD + d) =
                    make_float2(acc[mt][nt][0], acc[mt][nt][1]);
                *(float2*)(C + ((size_t)h * M + row + 8) * HD + d) =
                    make_float2(acc[mt][nt][2], acc[mt][nt][3]);
            }
        }
    }
}

// ---------------------------------------------------------------------------
// RoPE: Q in place (fp32); K -> split hi/lo fp16 global
// ---------------------------------------------------------------------------
__global__ __launch_bounds__(256) void rope_kernel(float* __restrict__ Q,
                                                   const float* __restrict__ Kc,
                                                   __half* __restrict__ Khi,
                                                   __half* __restrict__ Klo,
                                                   const int* __restrict__ pos)
{
    int idx = blockIdx.x * blockDim.x + threadIdx.x;
    int d = idx & 63;
    int s = (idx >> 6) & (SEQ - 1);
    int h = idx >> 18;

    double ang = (double)pos[s] * exp(-(double)d * (9.210340371976184 / 64.0));
    float c  = (float)cos(ang);
    float si = (float)sin(ang);

    if (h < NHEADS) {
        float* base = Q + ((size_t)h * SEQ + s) * HD;
        float x1 = base[d], x2 = base[d + 64];
        base[d]      = x1 * c - x2 * si;
        base[d + 64] = x2 * c + x1 * si;
    } else {
        size_t o = ((size_t)(h - NHEADS) * SEQ + s) * HD;
        float x1 = Kc[o + d], x2 = Kc[o + d + 64];
        float r1 = x1 * c - x2 * si;
        float r2 = x2 * c + x1 * si;
        __half hh, ll;
        cvt_hl_h(r1, hh, ll); Khi[o + d] = hh;       Klo[o + d] = ll;
        cvt_hl_h(r2, hh, ll); Khi[o + d + 64] = hh;  Klo[o + d + 64] = ll;
    }
}

// ---------------------------------------------------------------------------
// flash: q-tile 128, kv-tile 64, 256 thr, 2 CTAs/SM.
// S = Qh*(Khi+Klo) (2-term), O += Ph*Vh (single term, V error ~2.8e-4).
// KV stage = Khi,Klo,Vh (3 tiles, 52224 B) -> F_SMEM 87040.
// ---------------------------------------------------------------------------
#define LDB 136

#define F_QT_B  (128 * LDB * 2)          // 34816
#define F_KT_B  (64 * LDB * 2)           // 17408
#define F_STG_B (3 * F_KT_B)             // 52224 (Khi,Klo,Vh)
#define F_SMEM  (F_QT_B + F_STG_B)       // 87040 -> 2 CTAs/SM

__device__ __forceinline__ void f_fill(uint32_t stg,
    const __half* Khi_g, const __half* Klo_g, const __half* Vh_g,
    int kvh, int kb, int tid)
{
    const size_t gof = ((size_t)kvh * SEQ + (size_t)kb * 64) * HD;
    const char* kh = (const char*)(Khi_g + gof);
    const char* kl = (const char*)(Klo_g + gof);
    const char* vh = (const char*)(Vh_g + gof);
    for (int i = tid; i < 1024; i += 256) {
        int row = i >> 4, ch = (i & 15) << 4;
        uint32_t dst = row * (LDB * 2) + ch;
        int src = row * 256 + ch;
        cp16(stg + dst,               kh + src);
        cp16(stg + F_KT_B + dst,      kl + src);
        cp16(stg + 2 * F_KT_B + dst,  vh + src);
    }
    cp_commit();
}

__global__ __launch_bounds__(256, 2) void flash_v2(
    const float* __restrict__ Q,
    const __half* __restrict__ Khi_g, const __half* __restrict__ Klo_g,
    const __half* __restrict__ Vh_g,
    __half* __restrict__ Out)
{
    extern __shared__ __align__(16) char smem_raw[];
    const uint32_t smb  = (uint32_t)__cvta_generic_to_shared(smem_raw);
    const uint32_t q_h  = smb;
    const uint32_t stg0 = smb + F_QT_B;

    const int tid  = threadIdx.x;
    const int wid  = tid >> 5;
    const int lane = tid & 31;
    const int g    = lane >> 2;
    const int t    = lane & 3;
    const int qb   = gridDim.x - 1 - blockIdx.x;
    const int h    = blockIdx.y;
    const int kvh  = h >> 2;

    const int nkb = 2 * qb + 2;
    f_fill(stg0, Khi_g, Klo_g, Vh_g, kvh, 0, tid);

    {
        const float4* Q4 = (const float4*)(Q + ((size_t)h * SEQ + (size_t)qb * 128) * HD);
        __half* Qh = (__half*)smem_raw;
        for (int f = tid; f < 4096; f += 256) {
            int row = f >> 5, d0 = (f & 31) << 2;
            float4 q = Q4[f];
            int o = row * LDB + d0;
            *(__half2*)&Qh[o]     = __halves2half2(__float2half_rn(q.x),
                                                   __float2half_rn(q.y));
            *(__half2*)&Qh[o + 2] = __halves2half2(__float2half_rn(q.z),
                                                   __float2half_rn(q.w));
        }
    }

    const int a_row = wid * 16 + (lane & 15);
    const int a_col = (lane >> 4) << 3;
    const int kb_row = (lane & 7) + (((lane >> 4) & 1) << 3);
    const int kb_col = ((lane >> 3) & 1) << 3;
    const int v_row  = (lane & 7) + (((lane >> 3) & 1) << 3);
    const int v_col  = (lane >> 4) << 3;

    float o_[16][4];
    float m0 = -INFINITY, m1 = -INFINITY, l0 = 0.f, l1 = 0.f;
#pragma unroll
    for (int j = 0; j < 16; j++)
#pragma unroll
        for (int c = 0; c < 4; c++) o_[j][c] = 0.f;

    const float scale2 = 0.12751791437073365f;   // 1/sqrt(128) * log2(e)
    const int rl0 = wid * 16 + g;
    const int rl1 = rl0 + 8;

    for (int kb = 0; kb < nkb; kb++) {
        asm volatile("cp.async.wait_group 0;" ::: "memory");
        __syncthreads();                 // fill(kb) + Q store visible

        const int kofs = kb * 64 - qb * 128;
        if (kofs <= wid * 16 + 15) {
            const uint32_t khi_s = stg0;
            const uint32_t klo_s = stg0 + F_KT_B;
            const uint32_t vh_s  = stg0 + 2 * F_KT_B;

            float sc[8][4];
#pragma unroll
            for (int j = 0; j < 8; j++)
#pragma unroll
                for (int c = 0; c < 4; c++) sc[j][c] = 0.f;

#pragma unroll
            for (int ks = 0; ks < 8; ks++) {
                uint32_t ahf[4];
                uint32_t aoff = ((a_row * LDB) + (ks * 16 + a_col)) * 2;
                ldsm4(ahf, q_h + aoff);
#pragma unroll
                for (int jp = 0; jp < 4; jp++) {
                    uint32_t bh[4], bl[4];
                    uint32_t boff = (((jp * 16 + kb_row) * LDB)
                                     + (ks * 16 + kb_col)) * 2;
                    ldsm4(bh, khi_s + boff);
                    ldsm4(bl, klo_s + boff);
                    mma_f16(sc[2 * jp],     ahf, bh[0], bh[1]);
                    mma_f16(sc[2 * jp],     ahf, bl[0], bl[1]);
                    mma_f16(sc[2 * jp + 1], ahf, bh[2], bh[3]);
                    mma_f16(sc[2 * jp + 1], ahf, bl[2], bl[3]);
                }
            }

            const bool diag = (kofs + 63 > rl0);
            float tm0 = -INFINITY, tm1 = -INFINITY;
#pragma unroll
            for (int j = 0; j < 8; j++) {
                float v0 = sc[j][0] * scale2, v1 = sc[j][1] * scale2;
                float v2 = sc[j][2] * scale2, v3 = sc[j][3] * scale2;
                if (diag) {
                    int c0 = kofs + 8 * j + 2 * t;
                    if (c0     > rl0) v0 = -INFINITY;
                    if (c0 + 1 > rl0) v1 = -INFINITY;
                    if (c0     > rl1) v2 = -INFINITY;
                    if (c0 + 1 > rl1) v3 = -INFINITY;
                }
                sc[j][0] = v0; sc[j][1] = v1; sc[j][2] = v2; sc[j][3] = v3;
                tm0 = fmaxf(tm0, fmaxf(v0, v1));
                tm1 = fmaxf(tm1, fmaxf(v2, v3));
            }
            tm0 = fmaxf(tm0, __shfl_xor_sync(0xffffffffu, tm0, 1));
            tm0 = fmaxf(tm0, __shfl_xor_sync(0xffffffffu, tm0, 2));
            tm1 = fmaxf(tm1, __shfl_xor_sync(0xffffffffu, tm1, 1));
            tm1 = fmaxf(tm1, __shfl_xor_sync(0xffffffffu, tm1, 2));

            float mn0 = fmaxf(m0, tm0), mn1 = fmaxf(m1, tm1);
            float al0 = ex2a(m0 - mn0), al1 = ex2a(m1 - mn1);
            m0 = mn0; m1 = mn1;

            float rs0 = 0.f, rs1 = 0.f;
#pragma unroll
            for (int j = 0; j < 8; j++) {
                sc[j][0] = ex2a(sc[j][0] - mn0);
                sc[j][1] = ex2a(sc[j][1] - mn0);
                sc[j][2] = ex2a(sc[j][2] - mn1);
                sc[j][3] = ex2a(sc[j][3] - mn1);
                rs0 += sc[j][0] + sc[j][1];
                rs1 += sc[j][2] + sc[j][3];
            }
            rs0 += __shfl_xor_sync(0xffffffffu, rs0, 1);
            rs0 += __shfl_xor_sync(0xffffffffu, rs0, 2);
            rs1 += __shfl_xor_sync(0xffffffffu, rs1, 1);
            rs1 += __shfl_xor_sync(0xffffffffu, rs1, 2);
            l0 = l0 * al0 + rs0;
            l1 = l1 * al1 + rs1;

#pragma unroll
            for (int j = 0; j < 16; j++) {
                o_[j][0] *= al0; o_[j][1] *= al0;
                o_[j][2] *= al1; o_[j][3] *= al1;
            }

            uint32_t pa[4][4];
#pragma unroll
            for (int kc = 0; kc < 4; kc++) {
                int j0 = 2 * kc, j1 = j0 + 1;
                pa[kc][0] = pack_f16(sc[j0][0], sc[j0][1]);
                pa[kc][1] = pack_f16(sc[j0][2], sc[j0][3]);
                pa[kc][2] = pack_f16(sc[j1][0], sc[j1][1]);
                pa[kc][3] = pack_f16(sc[j1][2], sc[j1][3]);
            }

            // O += P V (single fp16 V term)
#pragma unroll
            for (int kc = 0; kc < 4; kc++) {
#pragma unroll
                for (int jp = 0; jp < 8; jp++) {
                    uint32_t vh[4];
                    uint32_t voff = (((kc * 16 + v_row) * LDB)
                                     + (jp * 16 + v_col)) * 2;
                    ldsm4t(vh, vh_s + voff);
                    mma_f16(o_[2 * jp],     pa[kc], vh[0], vh[1]);
                    mma_f16(o_[2 * jp + 1], pa[kc], vh[2], vh[3]);
                }
            }
        }

        __syncthreads();                 // compute done before refill
        if (kb + 1 < nkb)
            f_fill(stg0, Khi_g, Klo_g, Vh_g, kvh, kb + 1, tid);
    }

    // write out as fp16 (consumed by fp16 O-proj)
    float inv0 = rcpa(l0), inv1 = rcpa(l1);
    size_t r0 = (size_t)qb * 128 + wid * 16 + g;
    __half* base0 = Out + r0 * HID + (size_t)h * HD;
    __half* base1 = base0 + (size_t)8 * HID;
#pragma unroll
    for (int j = 0; j < 16; j++) {
        int col = 8 * j + 2 * t;
        *(__half2*)(base0 + col) =
            __halves2half2(__float2half_rn(o_[j][0] * inv0),
                           __float2half_rn(o_[j][1] * inv0));
        *(__half2*)(base1 + col) =
            __halves2half2(__float2half_rn(o_[j][2] * inv1),
                           __float2half_rn(o_[j][3] * inv1));
    }
}

// ---------------------------------------------------------------------------
extern "C" void kernel_launch(void* const* d_in, const int* in_sizes, int n_in,
                              void* d_out, int out_size)
{
    const float* Hs = (const float*)d_in[0];
    const float* Wq = (const float*)d_in[1];
    const float* Wk = (const float*)d_in[2];
    const float* Wv = (const float*)d_in[3];
    const float* Wo = (const float*)d_in[4];
    const int*  pos = (const int*)d_in[5];
    float* out = (float*)d_out;

    float *Qp, *KVp;
    __half *Ah, *hH, *hWq, *hWkv, *hWo, *Khi, *Klo, *Vh;
    cudaGetSymbolAddress((void**)&Qp,   g_Q);
    cudaGetSymbolAddress((void**)&KVp,  g_KV);
    cudaGetSymbolAddress((void**)&Ah,   g_Ah);
    cudaGetSymbolAddress((void**)&hH,   g_hH);
    cudaGetSymbolAddress((void**)&hWq,  g_hWq);
    cudaGetSymbolAddress((void**)&hWkv, g_hWkv);
    cudaGetSymbolAddress((void**)&hWo,  g_hWo);
    cudaGetSymbolAddress((void**)&Khi, g_Khi);
    cudaGetSymbolAddress((void**)&Klo, g_Klo);
    cudaGetSymbolAddress((void**)&Vh,  g_Vh);

    float* Kp = KVp;
    float* Vp = KVp + (size_t)NKV * SEQ * HD;

    cudaFuncSetAttribute(flash_v2, cudaFuncAttributeMaxDynamicSharedMemorySize,
                         F_SMEM);
    cudaFuncSetAttribute(gemm_f16, cudaFuncAttributeMaxDynamicSharedMemorySize,
                         G_SMEM);

    // fp16 pre-rounding
    const int nH4 = SEQ * HID / 4, nW4 = HID * HID / 4, nKV4 = NKV * HD * HID / 4;
    round_f16<<<nH4 / 256, 256>>>((const float4*)Hs, (__half2*)hH, nH4);
    round_f16<<<nW4 / 256, 256>>>((const float4*)Wq, (__half2*)hWq, nW4);
    round_f16<<<nKV4 / 256, 256>>>((const float4*)Wk, (__half2*)hWkv, nKV4);
    round_f16<<<nKV4 / 256, 256>>>((const float4*)Wv,
                                   (__half2*)(hWkv + (size_t)NKV * HD * HID), nKV4);
    round_f16<<<nW4 / 256, 256>>>((const float4*)Wo, (__half2*)hWo, nW4);

    // projections (fp16 mma), head-major scatter
    gemm_f16<<<dim3(HID / 256, SEQ / 128), 256, G_SMEM>>>(hH, hWq, Qp,
                                                          SEQ, HID, HID, 1);
    gemm_f16<<<dim3(2 * NKV * HD / 256, SEQ / 128), 256, G_SMEM>>>(
        hH, hWkv, KVp, SEQ, 2 * NKV * HD, HID, 1);

    rope_kernel<<<((NHEADS + NKV) * SEQ * 64) / 256, 256>>>(Qp, Kp, Khi, Klo, pos);

    // V -> fp16 (single term)
    const int nV4 = NKV * SEQ * HD / 4;
    round_f16<<<nV4 / 256, 256>>>((const float4*)Vp, (__half2*)Vh, nV4);

    flash_v2<<<dim3(SEQ / 128, NHEADS), 256, F_SMEM>>>(Qp, Khi, Klo, Vh, Ah);

    gemm_f16<<<dim3(HID / 256, SEQ / 128), 256, G_SMEM>>>(Ah, hWo, out,
                                                          SEQ, HID, HID, 0);
}

// round 15
// speedup vs baseline: 1.5617x; 1.0083x over previous
#include <cuda_runtime.h>
#include <cuda_bf16.h>
#include <cuda_fp16.h>
#include <math.h>
#include <stdint.h>

#define SEQ    4096
#define HID    4096
#define NHEADS 32
#define NKV    8
#define HD     128

// ---------------- device scratch (allocation-free rule) ----------------
__device__ float  g_Q[(size_t)NHEADS * SEQ * HD];     // [head][seq][128]
__device__ float  g_KV[(size_t)2 * NKV * SEQ * HD];   // K heads 0-7, V heads 8-15
__device__ __half g_Ah[(size_t)SEQ * HID];            // flash out (fp16)
__device__ __half g_hH[(size_t)SEQ * HID];            // fp16-rounded operands
__device__ __half g_hWq[(size_t)HID * HID];
__device__ __half g_hWkv[(size_t)2 * NKV * HD * HID]; // Wk rows 0-1023, Wv 1024-2047
__device__ __half g_hWo[(size_t)HID * HID];
__device__ __half g_Khi[(size_t)NKV * SEQ * HD];      // split K (post-rope), fp16
__device__ __half g_Klo[(size_t)NKV * SEQ * HD];
__device__ __half g_Vh[(size_t)NKV * SEQ * HD];       // V fp16 (single term)

__device__ __forceinline__ float ex2a(float x) {
    float y;
    asm("ex2.approx.f32 %0, %1;" : "=f"(y) : "f"(x));
    return y;
}
__device__ __forceinline__ uint32_t h2ex2(uint32_t x) {   // packed fp16x2 exp2
    uint32_t y;
    asm("ex2.approx.f16x2 %0, %1;" : "=r"(y) : "r"(x));
    return y;
}
__device__ __forceinline__ float rcpa(float x) {
    float y;
    asm("rcp.approx.f32 %0, %1;" : "=f"(y) : "f"(x));
    return y;
}
__device__ __forceinline__ void cp16(uint32_t dst, const void* src) {
    asm volatile("cp.async.cg.shared.global [%0], [%1], 16;"
                 :: "r"(dst), "l"(src) : "memory");
}
__device__ __forceinline__ void cp_commit() {
    asm volatile("cp.async.commit_group;" ::: "memory");
}
__device__ __forceinline__ void cvt_hl_h(float x, __half& h, __half& l) {
    h = __float2half_rn(x);
    l = __float2half_rn(x - __half2float(h));
}

// ---------------------------------------------------------------------------
// Pre-round fp32 -> fp16 (rn)
// ---------------------------------------------------------------------------
__global__ __launch_bounds__(256) void round_f16(const float4* __restrict__ in,
                                                 __half2* __restrict__ out, int n4)
{
    int i = blockIdx.x * blockDim.x + threadIdx.x;
    if (i >= n4) return;
    float4 v = in[i];
    out[2 * i]     = __halves2half2(__float2half_rn(v.x), __float2half_rn(v.y));
    out[2 * i + 1] = __halves2half2(__float2half_rn(v.z), __float2half_rn(v.w));
}

// ---------------------------------------------------------------------------
// ldmatrix / mma helpers (shared by GEMM and flash)
// ---------------------------------------------------------------------------
__device__ __forceinline__ void ldsm4(uint32_t a[4], uint32_t addr) {
    asm volatile("ldmatrix.sync.aligned.m8n8.x4.shared.b16 {%0,%1,%2,%3}, [%4];"
        : "=r"(a[0]), "=r"(a[1]), "=r"(a[2]), "=r"(a[3]) : "r"(addr));
}
__device__ __forceinline__ void ldsm4t(uint32_t a[4], uint32_t addr) {
    asm volatile("ldmatrix.sync.aligned.m8n8.x4.trans.shared.b16 {%0,%1,%2,%3}, [%4];"
        : "=r"(a[0]), "=r"(a[1]), "=r"(a[2]), "=r"(a[3]) : "r"(addr));
}
__device__ __forceinline__ void mma_f16(float c[4], const uint32_t a[4],
                                        uint32_t b0, uint32_t b1) {
    asm volatile(
        "mma.sync.aligned.m16n8k16.row.col.f32.f16.f16.f32 "
        "{%0,%1,%2,%3}, {%4,%5,%6,%7}, {%8,%9}, {%0,%1,%2,%3};"
        : "+f"(c[0]), "+f"(c[1]), "+f"(c[2]), "+f"(c[3])
        : "r"(a[0]), "r"(a[1]), "r"(a[2]), "r"(a[3]), "r"(b0), "r"(b1));
}
__device__ __forceinline__ uint32_t pack_f16(float lo, float hi) {
    uint32_t r;
    asm("cvt.rn.f16x2.f32 %0, %1, %2;" : "=r"(r) : "f"(hi), "f"(lo));
    return r;
}

// ---------------------------------------------------------------------------
// FP16 GEMM (unchanged from R12): C = A(MxK) * B(NxK)^T, fp32 accum.
// CTA 128x256, K-tile 64 (4 x k16), 3-stage cp.async, one sync per iter.
// ---------------------------------------------------------------------------
#define GH_A_B  (128 * 144)
#define GH_B_B  (256 * 144)
#define GH_ST   (GH_A_B + GH_B_B)         // 55296 B
#define G_SMEM  (3 * GH_ST)               // 165888 B

__device__ __forceinline__ void g_fill_h(uint32_t smb, int buf,
    const __half* __restrict__ A, const __half* __restrict__ B,
    int bm, int bn, int K, int kt, int tid)
{
    const uint32_t sa = smb + buf * GH_ST;
    const uint32_t sb = sa + GH_A_B;
    const size_t kof = (size_t)kt << 6;
    for (int i = tid; i < 1024; i += 256) {
        int row = i >> 3, ch = (i & 7) << 4;
        cp16(sa + row * 144 + ch,
             (const char*)(A + (size_t)(bm + row) * K + kof) + ch);
    }
    for (int i = tid; i < 2048; i += 256) {
        int row = i >> 3, ch = (i & 7) << 4;
        cp16(sb + row * 144 + ch,
             (const char*)(B + (size_t)(bn + row) * K + kof) + ch);
    }
    cp_commit();
}

__global__ __launch_bounds__(256, 1) void gemm_f16(
    const __half* __restrict__ A, const __half* __restrict__ B,
    float* __restrict__ C, int M, int N, int K, int mode)
{
    extern __shared__ __align__(16) char sm[];
    const uint32_t smb = (uint32_t)__cvta_generic_to_shared(sm);

    const int tid  = threadIdx.x;
    const int warp = tid >> 5;
    const int lane = tid & 31;
    const int wm   = warp & 1;
    const int wn   = warp >> 1;
    const int g    = lane >> 2;
    const int t4   = lane & 3;
    const int bm   = blockIdx.y * 128;
    const int bn   = blockIdx.x * 256;

    const int a_rl  = lane & 15;
    const int a_cl  = (lane >> 4) << 3;
    const int b_rl  = (lane & 7) + (((lane >> 4) & 1) << 3);
    const int b_cl  = ((lane >> 3) & 1) << 3;

    float acc[4][8][4];
#pragma unroll
    for (int mt = 0; mt < 4; mt++)
#pragma unroll
        for (int nt = 0; nt < 8; nt++)
#pragma unroll
            for (int c = 0; c < 4; c++) acc[mt][nt][c] = 0.f;

    const int KT = K >> 6;
    g_fill_h(smb, 0, A, B, bm, bn, K, 0, tid);
    g_fill_h(smb, 1, A, B, bm, bn, K, 1, tid);

    int buf = 0;
    for (int kt = 0; kt < KT; kt++) {
        if (kt < KT - 1) {
            asm volatile("cp.async.wait_group 1;" ::: "memory");
        } else {
            asm volatile("cp.async.wait_group 0;" ::: "memory");
        }
        __syncthreads();
        if (kt + 2 < KT) {
            int nb = buf + 2; if (nb >= 3) nb -= 3;
            g_fill_h(smb, nb, A, B, bm, bn, K, kt + 2, tid);
        }

        const uint32_t sa = smb + buf * GH_ST;
        const uint32_t sb = sa + GH_A_B;

#pragma unroll
        for (int ks = 0; ks < 4; ks++) {
            uint32_t af[4][4];
#pragma unroll
            for (int mt = 0; mt < 4; mt++) {
                uint32_t r = wm * 64 + mt * 16 + a_rl;
                ldsm4(af[mt], sa + (r * 72 + ks * 16 + a_cl) * 2);
            }
#pragma unroll
            for (int jp = 0; jp < 4; jp++) {
                uint32_t bf[4];
                uint32_t r = wn * 64 + jp * 16 + b_rl;
                ldsm4(bf, sb + (r * 72 + ks * 16 + b_cl) * 2);
#pragma unroll
                for (int mt = 0; mt < 4; mt++) {
                    mma_f16(acc[mt][2 * jp],     af[mt], bf[0], bf[1]);
                    mma_f16(acc[mt][2 * jp + 1], af[mt], bf[2], bf[3]);
                }
            }
        }
        if (++buf == 3) buf = 0;
    }

#pragma unroll
    for (int mt = 0; mt < 4; mt++) {
#pragma unroll
        for (int nt = 0; nt < 8; nt++) {
            int row = bm + wm * 64 + mt * 16 + g;
            int col = bn + wn * 64 + nt * 8 + 2 * t4;
            if (mode == 0) {
                *(float2*)(C + (size_t)row * N + col) =
                    make_float2(acc[mt][nt][0], acc[mt][nt][1]);
                *(float2*)(C + (size_t)(row + 8) * N + col) =
                    make_float2(acc[mt][nt][2], acc[mt][nt][3]);
            } else {
                int h = col >> 7, d = col & 127;
                *(float2*)(C + ((size_t)h * M + row) * HD + d) =
                    make_float2(acc[mt][nt][0], acc[mt][nt][1]);
                *(float2*)(C + ((size_t)h * M + row + 8) * HD + d) =
                    make_float2(acc[mt][nt][2], acc[mt][nt][3]);
            }
        }
    }
}

// ---------------------------------------------------------------------------
// RoPE: Q in place (fp32); K -> split hi/lo fp16 global
// ---------------------------------------------------------------------------
__global__ __launch_bounds__(256) void rope_kernel(float* __restrict__ Q,
                                                   const float* __restrict__ Kc,
                                                   __half* __restrict__ Khi,
                                                   __half* __restrict__ Klo,
                                                   const int* __restrict__ pos)
{
    int idx = blockIdx.x * blockDim.x + threadIdx.x;
    int d = idx & 63;
    int s = (idx >> 6) & (SEQ - 1);
    int h = idx >> 18;

    double ang = (double)pos[s] * exp(-(double)d * (9.210340371976184 / 64.0));
    float c  = (float)cos(ang);
    float si = (float)sin(ang);

    if (h < NHEADS) {
        float* base = Q + ((size_t)h * SEQ + s) * HD;
        float x1 = base[d], x2 = base[d + 64];
        base[d]      = x1 * c - x2 * si;
        base[d + 64] = x2 * c + x1 * si;
    } else {
        size_t o = ((size_t)(h - NHEADS) * SEQ + s) * HD;
        float x1 = Kc[o + d], x2 = Kc[o + d + 64];
        float r1 = x1 * c - x2 * si;
        float r2 = x2 * c + x1 * si;
        __half hh, ll;
        cvt_hl_h(r1, hh, ll); Khi[o + d] = hh;       Klo[o + d] = ll;
        cvt_hl_h(r2, hh, ll); Khi[o + d + 64] = hh;  Klo[o + d + 64] = ll;
    }
}

// ---------------------------------------------------------------------------
// flash: q-tile 128, kv-tile 64, 256 thr, 2 CTAs/SM.
// S = Qh*(Khi+Klo), O += Ph*Vh. Softmax: max in raw domain, probs via
// packed fp16x2 ex2.approx, row sums via ones-mma (exact fp32 accumulate
// of the SAME fp16 probs PV uses).
// ---------------------------------------------------------------------------
#define LDB 136
#define ONES16 0x3C003C00u

#define F_QT_B  (128 * LDB * 2)          // 34816
#define F_KT_B  (64 * LDB * 2)           // 17408
#define F_STG_B (3 * F_KT_B)             // 52224 (Khi,Klo,Vh)
#define F_SMEM  (F_QT_B + F_STG_B)       // 87040 -> 2 CTAs/SM

__device__ __forceinline__ void f_fill(uint32_t stg,
    const __half* Khi_g, const __half* Klo_g, const __half* Vh_g,
    int kvh, int kb, int tid)
{
    const size_t gof = ((size_t)kvh * SEQ + (size_t)kb * 64) * HD;
    const char* kh = (const char*)(Khi_g + gof);
    const char* kl = (const char*)(Klo_g + gof);
    const char* vh = (const char*)(Vh_g + gof);
    for (int i = tid; i < 1024; i += 256) {
        int row = i >> 4, ch = (i & 15) << 4;
        uint32_t dst = row * (LDB * 2) + ch;
        int src = row * 256 + ch;
        cp16(stg + dst,               kh + src);
        cp16(stg + F_KT_B + dst,      kl + src);
        cp16(stg + 2 * F_KT_B + dst,  vh + src);
    }
    cp_commit();
}

__global__ __launch_bounds__(256, 2) void flash_v2(
    const float* __restrict__ Q,
    const __half* __restrict__ Khi_g, const __half* __restrict__ Klo_g,
    const __half* __restrict__ Vh_g,
    __half* __restrict__ Out)
{
    extern __shared__ __align__(16) char smem_raw[];
    const uint32_t smb  = (uint32_t)__cvta_generic_to_shared(smem_raw);
    const uint32_t q_h  = smb;
    const uint32_t stg0 = smb + F_QT_B;

    const int tid  = threadIdx.x;
    const int wid  = tid >> 5;
    const int lane = tid & 31;
    const int g    = lane >> 2;
    const int t    = lane & 3;
    const int qb   = gridDim.x - 1 - blockIdx.x;
    const int h    = blockIdx.y;
    const int kvh  = h >> 2;

    const int nkb = 2 * qb + 2;
    f_fill(stg0, Khi_g, Klo_g, Vh_g, kvh, 0, tid);

    {
        const float4* Q4 = (const float4*)(Q + ((size_t)h * SEQ + (size_t)qb * 128) * HD);
        __half* Qh = (__half*)smem_raw;
        for (int f = tid; f < 4096; f += 256) {
            int row = f >> 5, d0 = (f & 31) << 2;
            float4 q = Q4[f];
            int o = row * LDB + d0;
            *(__half2*)&Qh[o]     = __halves2half2(__float2half_rn(q.x),
                                                   __float2half_rn(q.y));
            *(__half2*)&Qh[o + 2] = __halves2half2(__float2half_rn(q.z),
                                                   __float2half_rn(q.w));
        }
    }

    const int a_row = wid * 16 + (lane & 15);
    const int a_col = (lane >> 4) << 3;
    const int kb_row = (lane & 7) + (((lane >> 4) & 1) << 3);
    const int kb_col = ((lane >> 3) & 1) << 3;
    const int v_row  = (lane & 7) + (((lane >> 3) & 1) << 3);
    const int v_col  = (lane >> 4) << 3;

    float o_[16][4];
    float m0 = -INFINITY, m1 = -INFINITY, l0 = 0.f, l1 = 0.f;
#pragma unroll
    for (int j = 0; j < 16; j++)
#pragma unroll
        for (int c = 0; c < 4; c++) o_[j][c] = 0.f;

    const float scale2 = 0.12751791437073365f;   // 1/sqrt(128) * log2(e)
    const int rl0 = wid * 16 + g;
    const int rl1 = rl0 + 8;

    for (int kb = 0; kb < nkb; kb++) {
        asm volatile("cp.async.wait_group 0;" ::: "memory");
        __syncthreads();                 // fill(kb) + Q store visible

        const int kofs = kb * 64 - qb * 128;
        if (kofs <= wid * 16 + 15) {
            const uint32_t khi_s = stg0;
            const uint32_t klo_s = stg0 + F_KT_B;
            const uint32_t vh_s  = stg0 + 2 * F_KT_B;

            float sc[8][4];
#pragma unroll
            for (int j = 0; j < 8; j++)
#pragma unroll
                for (int c = 0; c < 4; c++) sc[j][c] = 0.f;

#pragma unroll
            for (int ks = 0; ks < 8; ks++) {
                uint32_t ahf[4];
                uint32_t aoff = ((a_row * LDB) + (ks * 16 + a_col)) * 2;
                ldsm4(ahf, q_h + aoff);
#pragma unroll
                for (int jp = 0; jp < 4; jp++) {
                    uint32_t bh[4], bl[4];
                    uint32_t boff = (((jp * 16 + kb_row) * LDB)
                                     + (ks * 16 + kb_col)) * 2;
                    ldsm4(bh, khi_s + boff);
                    ldsm4(bl, klo_s + boff);
                    mma_f16(sc[2 * jp],     ahf, bh[0], bh[1]);
                    mma_f16(sc[2 * jp],     ahf, bl[0], bl[1]);
                    mma_f16(sc[2 * jp + 1], ahf, bh[2], bh[3]);
                    mma_f16(sc[2 * jp + 1], ahf, bl[2], bl[3]);
                }
            }

            // ---- mask + running max (raw score domain) ----
            const bool diag = (kofs + 63 > rl0);
            float tm0 = -INFINITY, tm1 = -INFINITY;
#pragma unroll
            for (int j = 0; j < 8; j++) {
                float v0 = sc[j][0], v1 = sc[j][1];
                float v2 = sc[j][2], v3 = sc[j][3];
                if (diag) {
                    int c0 = kofs + 8 * j + 2 * t;
                    if (c0     > rl0) v0 = -INFINITY;
                    if (c0 + 1 > rl0) v1 = -INFINITY;
                    if (c0     > rl1) v2 = -INFINITY;
                    if (c0 + 1 > rl1) v3 = -INFINITY;
                }
                sc[j][0] = v0; sc[j][1] = v1; sc[j][2] = v2; sc[j][3] = v3;
                tm0 = fmaxf(tm0, fmaxf(v0, v1));
                tm1 = fmaxf(tm1, fmaxf(v2, v3));
            }
            tm0 = fmaxf(tm0, __shfl_xor_sync(0xffffffffu, tm0, 1));
            tm0 = fmaxf(tm0, __shfl_xor_sync(0xffffffffu, tm0, 2));
            tm1 = fmaxf(tm1, __shfl_xor_sync(0xffffffffu, tm1, 1));
            tm1 = fmaxf(tm1, __shfl_xor_sync(0xffffffffu, tm1, 2));

            float mn0 = fmaxf(m0, tm0), mn1 = fmaxf(m1, tm1);
            float al0 = ex2a((m0 - mn0) * scale2);
            float al1 = ex2a((m1 - mn1) * scale2);
            m0 = mn0; m1 = mn1;
            const float b0 = -mn0 * scale2;
            const float b1 = -mn1 * scale2;

            // ---- probs via packed fp16x2 exp2 (arg = s*scale2 - mn*scale2) ----
            uint32_t pa[4][4];
#pragma unroll
            for (int kc = 0; kc < 4; kc++) {
                int j0 = 2 * kc, j1 = j0 + 1;
                pa[kc][0] = h2ex2(pack_f16(fmaf(sc[j0][0], scale2, b0),
                                           fmaf(sc[j0][1], scale2, b0)));
                pa[kc][1] = h2ex2(pack_f16(fmaf(sc[j0][2], scale2, b1),
                                           fmaf(sc[j0][3], scale2, b1)));
                pa[kc][2] = h2ex2(pack_f16(fmaf(sc[j1][0], scale2, b0),
                                           fmaf(sc[j1][1], scale2, b0)));
                pa[kc][3] = h2ex2(pack_f16(fmaf(sc[j1][2], scale2, b1),
                                           fmaf(sc[j1][3], scale2, b1)));
            }

            // ---- row sums of the SAME fp16 probs via ones-mma ----
            float lsum[4] = {0.f, 0.f, 0.f, 0.f};
#pragma unroll
            for (int kc = 0; kc < 4; kc++)
                mma_f16(lsum, pa[kc], ONES16, ONES16);
            l0 = l0 * al0 + lsum[0];
            l1 = l1 * al1 + lsum[2];

#pragma unroll
            for (int j = 0; j < 16; j++) {
                o_[j][0] *= al0; o_[j][1] *= al0;
                o_[j][2] *= al1; o_[j][3] *= al1;
            }

            // ---- O += P V (single fp16 V term) ----
#pragma unroll
            for (int kc = 0; kc < 4; kc++) {
#pragma unroll
                for (int jp = 0; jp < 8; jp++) {
                    uint32_t vh[4];
                    uint32_t voff = (((kc * 16 + v_row) * LDB)
                                     + (jp * 16 + v_col)) * 2;
                    ldsm4t(vh, vh_s + voff);
                    mma_f16(o_[2 * jp],     pa[kc], vh[0], vh[1]);
                    mma_f16(o_[2 * jp + 1], pa[kc], vh[2], vh[3]);
                }
            }
        }

        __syncthreads();                 // compute done before refill
        if (kb + 1 < nkb)
            f_fill(stg0, Khi_g, Klo_g, Vh_g, kvh, kb + 1, tid);
    }

    // write out as fp16 (consumed by fp16 O-proj)
    float inv0 = rcpa(l0), inv1 = rcpa(l1);
    size_t r0 = (size_t)qb * 128 + wid * 16 + g;
    __half* base0 = Out + r0 * HID + (size_t)h * HD;
    __half* base1 = base0 + (size_t)8 * HID;
#pragma unroll
    for (int j = 0; j < 16; j++) {
        int col = 8 * j + 2 * t;
        *(__half2*)(base0 + col) =
            __halves2half2(__float2half_rn(o_[j][0] * inv0),
                           __float2half_rn(o_[j][1] * inv0));
        *(__half2*)(base1 + col) =
            __halves2half2(__float2half_rn(o_[j][2] * inv1),
                           __float2half_rn(o_[j][3] * inv1));
    }
}

// ---------------------------------------------------------------------------
extern "C" void kernel_launch(void* const* d_in, const int* in_sizes, int n_in,
                              void* d_out, int out_size)
{
    const float* Hs = (const float*)d_in[0];
    const float* Wq = (const float*)d_in[1];
    const float* Wk = (const float*)d_in[2];
    const float* Wv = (const float*)d_in[3];
    const float* Wo = (const float*)d_in[4];
    const int*  pos = (const int*)d_in[5];
    float* out = (float*)d_out;

    float *Qp, *KVp;
    __half *Ah, *hH, *hWq, *hWkv, *hWo, *Khi, *Klo, *Vh;
    cudaGetSymbolAddress((void**)&Qp,   g_Q);
    cudaGetSymbolAddress((void**)&KVp,  g_KV);
    cudaGetSymbolAddress((void**)&Ah,   g_Ah);
    cudaGetSymbolAddress((void**)&hH,   g_hH);
    cudaGetSymbolAddress((void**)&hWq,  g_hWq);
    cudaGetSymbolAddress((void**)&hWkv, g_hWkv);
    cudaGetSymbolAddress((void**)&hWo,  g_hWo);
    cudaGetSymbolAddress((void**)&Khi, g_Khi);
    cudaGetSymbolAddress((void**)&Klo, g_Klo);
    cudaGetSymbolAddress((void**)&Vh,  g_Vh);

    float* Kp = KVp;
    float* Vp = KVp + (size_t)NKV * SEQ * HD;

    cudaFuncSetAttribute(flash_v2, cudaFuncAttributeMaxDynamicSharedMemorySize,
                         F_SMEM);
    cudaFuncSetAttribute(gemm_f16, cudaFuncAttributeMaxDynamicSharedMemorySize,
                         G_SMEM);

    // fp16 pre-rounding
    const int nH4 = SEQ * HID / 4, nW4 = HID * HID / 4, nKV4 = NKV * HD * HID / 4;
    round_f16<<<nH4 / 256, 256>>>((const float4*)Hs, (__half2*)hH, nH4);
    round_f16<<<nW4 / 256, 256>>>((const float4*)Wq, (__half2*)hWq, nW4);
    round_f16<<<nKV4 / 256, 256>>>((const float4*)Wk, (__half2*)hWkv, nKV4);
    round_f16<<<nKV4 / 256, 256>>>((const float4*)Wv,
                                   (__half2*)(hWkv + (size_t)NKV * HD * HID), nKV4);
    round_f16<<<nW4 / 256, 256>>>((const float4*)Wo, (__half2*)hWo, nW4);

    // projections (fp16 mma), head-major scatter
    gemm_f16<<<dim3(HID / 256, SEQ / 128), 256, G_SMEM>>>(hH, hWq, Qp,
                                                          SEQ, HID, HID, 1);
    gemm_f16<<<dim3(2 * NKV * HD / 256, SEQ / 128), 256, G_SMEM>>>(
        hH, hWkv, KVp, SEQ, 2 * NKV * HD, HID, 1);

    rope_kernel<<<((NHEADS + NKV) * SEQ * 64) / 256, 256>>>(Qp, Kp, Khi, Klo, pos);

    // V -> fp16 (single term)
    const int nV4 = NKV * SEQ * HD / 4;
    round_f16<<<nV4 / 256, 256>>>((const float4*)Vp, (__half2*)Vh, nV4);

    flash_v2<<<dim3(SEQ / 128, NHEADS), 256, F_SMEM>>>(Qp, Khi, Klo, Vh, Ah);

    gemm_f16<<<dim3(HID / 256, SEQ / 128), 256, G_SMEM>>>(Ah, hWo, out,
                                                          SEQ, HID, HID, 0);
}

// round 16
// speedup vs baseline: 1.6643x; 1.0657x over previous
#include <cuda_runtime.h>
#include <cuda_bf16.h>
#include <cuda_fp16.h>
#include <math.h>
#include <stdint.h>

#define SEQ    4096
#define HID    4096
#define NHEADS 32
#define NKV    8
#define HD     128

// ---------------- device scratch (allocation-free rule) ----------------
__device__ float  g_Q[(size_t)NHEADS * SEQ * HD];     // [head][seq][128]
__device__ float  g_KV[(size_t)2 * NKV * SEQ * HD];   // K heads 0-7, V heads 8-15
__device__ __half g_Ah[(size_t)SEQ * HID];            // flash out (fp16)
__device__ __half g_hH[(size_t)SEQ * HID];            // fp16-rounded operands
__device__ __half g_hWq[(size_t)HID * HID];
__device__ __half g_hWkv[(size_t)2 * NKV * HD * HID]; // Wk rows 0-1023, Wv 1024-2047
__device__ __half g_hWo[(size_t)HID * HID];
__device__ __half g_Kh[(size_t)NKV * SEQ * HD];       // K fp16 (post-rope)
__device__ __half g_Vh[(size_t)NKV * SEQ * HD];       // V fp16

__device__ __forceinline__ float ex2a(float x) {
    float y;
    asm("ex2.approx.f32 %0, %1;" : "=f"(y) : "f"(x));
    return y;
}
__device__ __forceinline__ uint32_t h2ex2(uint32_t x) {   // packed fp16x2 exp2
    uint32_t y;
    asm("ex2.approx.f16x2 %0, %1;" : "=r"(y) : "r"(x));
    return y;
}
__device__ __forceinline__ float rcpa(float x) {
    float y;
    asm("rcp.approx.f32 %0, %1;" : "=f"(y) : "f"(x));
    return y;
}
__device__ __forceinline__ void cp16(uint32_t dst, const void* src) {
    asm volatile("cp.async.cg.shared.global [%0], [%1], 16;"
                 :: "r"(dst), "l"(src) : "memory");
}
__device__ __forceinline__ void cp_commit() {
    asm volatile("cp.async.commit_group;" ::: "memory");
}

// ---------------------------------------------------------------------------
// Pre-round fp32 -> fp16 (rn)
// ---------------------------------------------------------------------------
__global__ __launch_bounds__(256) void round_f16(const float4* __restrict__ in,
                                                 __half2* __restrict__ out, int n4)
{
    int i = blockIdx.x * blockDim.x + threadIdx.x;
    if (i >= n4) return;
    float4 v = in[i];
    out[2 * i]     = __halves2half2(__float2half_rn(v.x), __float2half_rn(v.y));
    out[2 * i + 1] = __halves2half2(__float2half_rn(v.z), __float2half_rn(v.w));
}

// ---------------------------------------------------------------------------
// ldmatrix / mma helpers (shared by GEMM and flash)
// ---------------------------------------------------------------------------
__device__ __forceinline__ void ldsm4(uint32_t a[4], uint32_t addr) {
    asm volatile("ldmatrix.sync.aligned.m8n8.x4.shared.b16 {%0,%1,%2,%3}, [%4];"
        : "=r"(a[0]), "=r"(a[1]), "=r"(a[2]), "=r"(a[3]) : "r"(addr));
}
__device__ __forceinline__ void ldsm4t(uint32_t a[4], uint32_t addr) {
    asm volatile("ldmatrix.sync.aligned.m8n8.x4.trans.shared.b16 {%0,%1,%2,%3}, [%4];"
        : "=r"(a[0]), "=r"(a[1]), "=r"(a[2]), "=r"(a[3]) : "r"(addr));
}
__device__ __forceinline__ void mma_f16(float c[4], const uint32_t a[4],
                                        uint32_t b0, uint32_t b1) {
    asm volatile(
        "mma.sync.aligned.m16n8k16.row.col.f32.f16.f16.f32 "
        "{%0,%1,%2,%3}, {%4,%5,%6,%7}, {%8,%9}, {%0,%1,%2,%3};"
        : "+f"(c[0]), "+f"(c[1]), "+f"(c[2]), "+f"(c[3])
        : "r"(a[0]), "r"(a[1]), "r"(a[2]), "r"(a[3]), "r"(b0), "r"(b1));
}
__device__ __forceinline__ uint32_t pack_f16(float lo, float hi) {
    uint32_t r;
    asm("cvt.rn.f16x2.f32 %0, %1, %2;" : "=r"(r) : "f"(hi), "f"(lo));
    return r;
}

// ---------------------------------------------------------------------------
// FP16 GEMM (unchanged from R12): C = A(MxK) * B(NxK)^T, fp32 accum.
// CTA 128x256, K-tile 64 (4 x k16), 3-stage cp.async, one sync per iter.
// ---------------------------------------------------------------------------
#define GH_A_B  (128 * 144)
#define GH_B_B  (256 * 144)
#define GH_ST   (GH_A_B + GH_B_B)         // 55296 B
#define G_SMEM  (3 * GH_ST)               // 165888 B

__device__ __forceinline__ void g_fill_h(uint32_t smb, int buf,
    const __half* __restrict__ A, const __half* __restrict__ B,
    int bm, int bn, int K, int kt, int tid)
{
    const uint32_t sa = smb + buf * GH_ST;
    const uint32_t sb = sa + GH_A_B;
    const size_t kof = (size_t)kt << 6;
    for (int i = tid; i < 1024; i += 256) {
        int row = i >> 3, ch = (i & 7) << 4;
        cp16(sa + row * 144 + ch,
             (const char*)(A + (size_t)(bm + row) * K + kof) + ch);
    }
    for (int i = tid; i < 2048; i += 256) {
        int row = i >> 3, ch = (i & 7) << 4;
        cp16(sb + row * 144 + ch,
             (const char*)(B + (size_t)(bn + row) * K + kof) + ch);
    }
    cp_commit();
}

__global__ __launch_bounds__(256, 1) void gemm_f16(
    const __half* __restrict__ A, const __half* __restrict__ B,
    float* __restrict__ C, int M, int N, int K, int mode)
{
    extern __shared__ __align__(16) char sm[];
    const uint32_t smb = (uint32_t)__cvta_generic_to_shared(sm);

    const int tid  = threadIdx.x;
    const int warp = tid >> 5;
    const int lane = tid & 31;
    const int wm   = warp & 1;
    const int wn   = warp >> 1;
    const int g    = lane >> 2;
    const int t4   = lane & 3;
    const int bm   = blockIdx.y * 128;
    const int bn   = blockIdx.x * 256;

    const int a_rl  = lane & 15;
    const int a_cl  = (lane >> 4) << 3;
    const int b_rl  = (lane & 7) + (((lane >> 4) & 1) << 3);
    const int b_cl  = ((lane >> 3) & 1) << 3;

    float acc[4][8][4];
#pragma unroll
    for (int mt = 0; mt < 4; mt++)
#pragma unroll
        for (int nt = 0; nt < 8; nt++)
#pragma unroll
            for (int c = 0; c < 4; c++) acc[mt][nt][c] = 0.f;

    const int KT = K >> 6;
    g_fill_h(smb, 0, A, B, bm, bn, K, 0, tid);
    g_fill_h(smb, 1, A, B, bm, bn, K, 1, tid);

    int buf = 0;
    for (int kt = 0; kt < KT; kt++) {
        if (kt < KT - 1) {
            asm volatile("cp.async.wait_group 1;" ::: "memory");
        } else {
            asm volatile("cp.async.wait_group 0;" ::: "memory");
        }
        __syncthreads();
        if (kt + 2 < KT) {
            int nb = buf + 2; if (nb >= 3) nb -= 3;
            g_fill_h(smb, nb, A, B, bm, bn, K, kt + 2, tid);
        }

        const uint32_t sa = smb + buf * GH_ST;
        const uint32_t sb = sa + GH_A_B;

#pragma unroll
        for (int ks = 0; ks < 4; ks++) {
            uint32_t af[4][4];
#pragma unroll
            for (int mt = 0; mt < 4; mt++) {
                uint32_t r = wm * 64 + mt * 16 + a_rl;
                ldsm4(af[mt], sa + (r * 72 + ks * 16 + a_cl) * 2);
            }
#pragma unroll
            for (int jp = 0; jp < 4; jp++) {
                uint32_t bf[4];
                uint32_t r = wn * 64 + jp * 16 + b_rl;
                ldsm4(bf, sb + (r * 72 + ks * 16 + b_cl) * 2);
#pragma unroll
                for (int mt = 0; mt < 4; mt++) {
                    mma_f16(acc[mt][2 * jp],     af[mt], bf[0], bf[1]);
                    mma_f16(acc[mt][2 * jp + 1], af[mt], bf[2], bf[3]);
                }
            }
        }
        if (++buf == 3) buf = 0;
    }

#pragma unroll
    for (int mt = 0; mt < 4; mt++) {
#pragma unroll
        for (int nt = 0; nt < 8; nt++) {
            int row = bm + wm * 64 + mt * 16 + g;
            int col = bn + wn * 64 + nt * 8 + 2 * t4;
            if (mode == 0) {
                *(float2*)(C + (size_t)row * N + col) =
                    make_float2(acc[mt][nt][0], acc[mt][nt][1]);
                *(float2*)(C + (size_t)(row + 8) * N + col) =
                    make_float2(acc[mt][nt][2], acc[mt][nt][3]);
            } else {
                int h = col >> 7, d = col & 127;
                *(float2*)(C + ((size_t)h * M + row) * HD + d) =
                    make_float2(acc[mt][nt][0], acc[mt][nt][1]);
                *(float2*)(C + ((size_t)h * M + row + 8) * HD + d) =
                    make_float2(acc[mt][nt][2], acc[mt][nt][3]);
            }
        }
    }
}

// ---------------------------------------------------------------------------
// RoPE: Q in place (fp32); K -> fp16 global (single term)
// ---------------------------------------------------------------------------
__global__ __launch_bounds__(256) void rope_kernel(float* __restrict__ Q,
                                                   const float* __restrict__ Kc,
                                                   __half* __restrict__ Kh,
                                                   const int* __restrict__ pos)
{
    int idx = blockIdx.x * blockDim.x + threadIdx.x;
    int d = idx & 63;
    int s = (idx >> 6) & (SEQ - 1);
    int h = idx >> 18;

    double ang = (double)pos[s] * exp(-(double)d * (9.210340371976184 / 64.0));
    float c  = (float)cos(ang);
    float si = (float)sin(ang);

    if (h < NHEADS) {
        float* base = Q + ((size_t)h * SEQ + s) * HD;
        float x1 = base[d], x2 = base[d + 64];
        base[d]      = x1 * c - x2 * si;
        base[d + 64] = x2 * c + x1 * si;
    } else {
        size_t o = ((size_t)(h - NHEADS) * SEQ + s) * HD;
        float x1 = Kc[o + d], x2 = Kc[o + d + 64];
        Kh[o + d]      = __float2half_rn(x1 * c - x2 * si);
        Kh[o + d + 64] = __float2half_rn(x2 * c + x1 * si);
    }
}

// ---------------------------------------------------------------------------
// flash: q-tile 128, kv-tile 64, 256 thr, 2 CTAs/SM, DOUBLE-BUFFERED KV
// (fill issued right after top sync -> latency hidden under compute).
// S = Qh*Kh (single term), O += Ph*Vh. Softmax via fp16x2 ex2 + ones-mma sums.
// ---------------------------------------------------------------------------
#define LDB 136
#define ONES16 0x3C003C00u

#define F_QT_B  (128 * LDB * 2)          // 34816
#define F_KT_B  (64 * LDB * 2)           // 17408
#define F_STG_B (2 * F_KT_B)             // 34816 (Kh, Vh)
#define F_SMEM  (F_QT_B + 2 * F_STG_B)   // 104448 -> 2 CTAs/SM

__device__ __forceinline__ void f_fill(uint32_t stg,
    const __half* Kh_g, const __half* Vh_g, int kvh, int kb, int tid)
{
    const size_t gof = ((size_t)kvh * SEQ + (size_t)kb * 64) * HD;
    const char* kh = (const char*)(Kh_g + gof);
    const char* vh = (const char*)(Vh_g + gof);
    for (int i = tid; i < 1024; i += 256) {
        int row = i >> 4, ch = (i & 15) << 4;
        uint32_t dst = row * (LDB * 2) + ch;
        int src = row * 256 + ch;
        cp16(stg + dst,           kh + src);
        cp16(stg + F_KT_B + dst,  vh + src);
    }
    cp_commit();
}

__global__ __launch_bounds__(256, 2) void flash_v2(
    const float* __restrict__ Q,
    const __half* __restrict__ Kh_g, const __half* __restrict__ Vh_g,
    __half* __restrict__ Out)
{
    extern __shared__ __align__(16) char smem_raw[];
    const uint32_t smb  = (uint32_t)__cvta_generic_to_shared(smem_raw);
    const uint32_t q_h  = smb;
    const uint32_t stg0 = smb + F_QT_B;

    const int tid  = threadIdx.x;
    const int wid  = tid >> 5;
    const int lane = tid & 31;
    const int g    = lane >> 2;
    const int t    = lane & 3;
    const int qb   = gridDim.x - 1 - blockIdx.x;
    const int h    = blockIdx.y;
    const int kvh  = h >> 2;

    const int nkb = 2 * qb + 2;
    f_fill(stg0, Kh_g, Vh_g, kvh, 0, tid);

    {
        const float4* Q4 = (const float4*)(Q + ((size_t)h * SEQ + (size_t)qb * 128) * HD);
        __half* Qh = (__half*)smem_raw;
        for (int f = tid; f < 4096; f += 256) {
            int row = f >> 5, d0 = (f & 31) << 2;
            float4 q = Q4[f];
            int o = row * LDB + d0;
            *(__half2*)&Qh[o]     = __halves2half2(__float2half_rn(q.x),
                                                   __float2half_rn(q.y));
            *(__half2*)&Qh[o + 2] = __halves2half2(__float2half_rn(q.z),
                                                   __float2half_rn(q.w));
        }
    }

    const int a_row = wid * 16 + (lane & 15);
    const int a_col = (lane >> 4) << 3;
    const int kb_row = (lane & 7) + (((lane >> 4) & 1) << 3);
    const int kb_col = ((lane >> 3) & 1) << 3;
    const int v_row  = (lane & 7) + (((lane >> 3) & 1) << 3);
    const int v_col  = (lane >> 4) << 3;

    float o_[16][4];
    float m0 = -INFINITY, m1 = -INFINITY, l0 = 0.f, l1 = 0.f;
#pragma unroll
    for (int j = 0; j < 16; j++)
#pragma unroll
        for (int c = 0; c < 4; c++) o_[j][c] = 0.f;

    const float scale2 = 0.12751791437073365f;   // 1/sqrt(128) * log2(e)
    const int rl0 = wid * 16 + g;
    const int rl1 = rl0 + 8;

    for (int kb = 0; kb < nkb; kb++) {
        const int buf = kb & 1;
        asm volatile("cp.async.wait_group 0;" ::: "memory");
        __syncthreads();                 // fill(kb) + prior compute done
        if (kb + 1 < nkb)
            f_fill(stg0 + (buf ^ 1) * F_STG_B, Kh_g, Vh_g, kvh, kb + 1, tid);

        const int kofs = kb * 64 - qb * 128;
        if (kofs <= wid * 16 + 15) {
            const uint32_t kh_s = stg0 + buf * F_STG_B;
            const uint32_t vh_s = kh_s + F_KT_B;

            float sc[8][4];
#pragma unroll
            for (int j = 0; j < 8; j++)
#pragma unroll
                for (int c = 0; c < 4; c++) sc[j][c] = 0.f;

#pragma unroll
            for (int ks = 0; ks < 8; ks++) {
                uint32_t ahf[4];
                uint32_t aoff = ((a_row * LDB) + (ks * 16 + a_col)) * 2;
                ldsm4(ahf, q_h + aoff);
#pragma unroll
                for (int jp = 0; jp < 4; jp++) {
                    uint32_t bh[4];
                    uint32_t boff = (((jp * 16 + kb_row) * LDB)
                                     + (ks * 16 + kb_col)) * 2;
                    ldsm4(bh, kh_s + boff);
                    mma_f16(sc[2 * jp],     ahf, bh[0], bh[1]);
                    mma_f16(sc[2 * jp + 1], ahf, bh[2], bh[3]);
                }
            }

            // ---- mask + running max (raw score domain) ----
            const bool diag = (kofs + 63 > rl0);
            float tm0 = -INFINITY, tm1 = -INFINITY;
#pragma unroll
            for (int j = 0; j < 8; j++) {
                float v0 = sc[j][0], v1 = sc[j][1];
                float v2 = sc[j][2], v3 = sc[j][3];
                if (diag) {
                    int c0 = kofs + 8 * j + 2 * t;
                    if (c0     > rl0) v0 = -INFINITY;
                    if (c0 + 1 > rl0) v1 = -INFINITY;
                    if (c0     > rl1) v2 = -INFINITY;
                    if (c0 + 1 > rl1) v3 = -INFINITY;
                }
                sc[j][0] = v0; sc[j][1] = v1; sc[j][2] = v2; sc[j][3] = v3;
                tm0 = fmaxf(tm0, fmaxf(v0, v1));
                tm1 = fmaxf(tm1, fmaxf(v2, v3));
            }
            tm0 = fmaxf(tm0, __shfl_xor_sync(0xffffffffu, tm0, 1));
            tm0 = fmaxf(tm0, __shfl_xor_sync(0xffffffffu, tm0, 2));
            tm1 = fmaxf(tm1, __shfl_xor_sync(0xffffffffu, tm1, 1));
            tm1 = fmaxf(tm1, __shfl_xor_sync(0xffffffffu, tm1, 2));

            float mn0 = fmaxf(m0, tm0), mn1 = fmaxf(m1, tm1);
            float al0 = ex2a((m0 - mn0) * scale2);
            float al1 = ex2a((m1 - mn1) * scale2);
            m0 = mn0; m1 = mn1;
            const float b0 = -mn0 * scale2;
            const float b1 = -mn1 * scale2;

            // ---- probs via packed fp16x2 exp2 ----
            uint32_t pa[4][4];
#pragma unroll
            for (int kc = 0; kc < 4; kc++) {
                int j0 = 2 * kc, j1 = j0 + 1;
                pa[kc][0] = h2ex2(pack_f16(fmaf(sc[j0][0], scale2, b0),
                                           fmaf(sc[j0][1], scale2, b0)));
                pa[kc][1] = h2ex2(pack_f16(fmaf(sc[j0][2], scale2, b1),
                                           fmaf(sc[j0][3], scale2, b1)));
                pa[kc][2] = h2ex2(pack_f16(fmaf(sc[j1][0], scale2, b0),
                                           fmaf(sc[j1][1], scale2, b0)));
                pa[kc][3] = h2ex2(pack_f16(fmaf(sc[j1][2], scale2, b1),
                                           fmaf(sc[j1][3], scale2, b1)));
            }

            // ---- row sums of the SAME fp16 probs via ones-mma ----
            float lsum[4] = {0.f, 0.f, 0.f, 0.f};
#pragma unroll
            for (int kc = 0; kc < 4; kc++)
                mma_f16(lsum, pa[kc], ONES16, ONES16);
            l0 = l0 * al0 + lsum[0];
            l1 = l1 * al1 + lsum[2];

#pragma unroll
            for (int j = 0; j < 16; j++) {
                o_[j][0] *= al0; o_[j][1] *= al0;
                o_[j][2] *= al1; o_[j][3] *= al1;
            }

            // ---- O += P V ----
#pragma unroll
            for (int kc = 0; kc < 4; kc++) {
#pragma unroll
                for (int jp = 0; jp < 8; jp++) {
                    uint32_t vh[4];
                    uint32_t voff = (((kc * 16 + v_row) * LDB)
                                     + (jp * 16 + v_col)) * 2;
                    ldsm4t(vh, vh_s + voff);
                    mma_f16(o_[2 * jp],     pa[kc], vh[0], vh[1]);
                    mma_f16(o_[2 * jp + 1], pa[kc], vh[2], vh[3]);
                }
            }
        }
    }

    // write out as fp16 (consumed by fp16 O-proj)
    float inv0 = rcpa(l0), inv1 = rcpa(l1);
    size_t r0 = (size_t)qb * 128 + wid * 16 + g;
    __half* base0 = Out + r0 * HID + (size_t)h * HD;
    __half* base1 = base0 + (size_t)8 * HID;
#pragma unroll
    for (int j = 0; j < 16; j++) {
        int col = 8 * j + 2 * t;
        *(__half2*)(base0 + col) =
            __halves2half2(__float2half_rn(o_[j][0] * inv0),
                           __float2half_rn(o_[j][1] * inv0));
        *(__half2*)(base1 + col) =
            __halves2half2(__float2half_rn(o_[j][2] * inv1),
                           __float2half_rn(o_[j][3] * inv1));
    }
}

// ---------------------------------------------------------------------------
extern "C" void kernel_launch(void* const* d_in, const int* in_sizes, int n_in,
                              void* d_out, int out_size)
{
    const float* Hs = (const float*)d_in[0];
    const float* Wq = (const float*)d_in[1];
    const float* Wk = (const float*)d_in[2];
    const float* Wv = (const float*)d_in[3];
    const float* Wo = (const float*)d_in[4];
    const int*  pos = (const int*)d_in[5];
    float* out = (float*)d_out;

    float *Qp, *KVp;
    __half *Ah, *hH, *hWq, *hWkv, *hWo, *Kh, *Vh;
    cudaGetSymbolAddress((void**)&Qp,   g_Q);
    cudaGetSymbolAddress((void**)&KVp,  g_KV);
    cudaGetSymbolAddress((void**)&Ah,   g_Ah);
    cudaGetSymbolAddress((void**)&hH,   g_hH);
    cudaGetSymbolAddress((void**)&hWq,  g_hWq);
    cudaGetSymbolAddress((void**)&hWkv, g_hWkv);
    cudaGetSymbolAddress((void**)&hWo,  g_hWo);
    cudaGetSymbolAddress((void**)&Kh,  g_Kh);
    cudaGetSymbolAddress((void**)&Vh,  g_Vh);

    float* Kp = KVp;
    float* Vp = KVp + (size_t)NKV * SEQ * HD;

    cudaFuncSetAttribute(flash_v2, cudaFuncAttributeMaxDynamicSharedMemorySize,
                         F_SMEM);
    cudaFuncSetAttribute(gemm_f16, cudaFuncAttributeMaxDynamicSharedMemorySize,
                         G_SMEM);

    // fp16 pre-rounding
    const int nH4 = SEQ * HID / 4, nW4 = HID * HID / 4, nKV4 = NKV * HD * HID / 4;
    round_f16<<<nH4 / 256, 256>>>((const float4*)Hs, (__half2*)hH, nH4);
    round_f16<<<nW4 / 256, 256>>>((const float4*)Wq, (__half2*)hWq, nW4);
    round_f16<<<nKV4 / 256, 256>>>((const float4*)Wk, (__half2*)hWkv, nKV4);
    round_f16<<<nKV4 / 256, 256>>>((const float4*)Wv,
                                   (__half2*)(hWkv + (size_t)NKV * HD * HID), nKV4);
    round_f16<<<nW4 / 256, 256>>>((const float4*)Wo, (__half2*)hWo, nW4);

    // projections (fp16 mma), head-major scatter
    gemm_f16<<<dim3(HID / 256, SEQ / 128), 256, G_SMEM>>>(hH, hWq, Qp,
                                                          SEQ, HID, HID, 1);
    gemm_f16<<<dim3(2 * NKV * HD / 256, SEQ / 128), 256, G_SMEM>>>(
        hH, hWkv, KVp, SEQ, 2 * NKV * HD, HID, 1);

    rope_kernel<<<((NHEADS + NKV) * SEQ * 64) / 256, 256>>>(Qp, Kp, Kh, pos);

    // V -> fp16
    const int nV4 = NKV * SEQ * HD / 4;
    round_f16<<<nV4 / 256, 256>>>((const float4*)Vp, (__half2*)Vh, nV4);

    flash_v2<<<dim3(SEQ / 128, NHEADS), 256, F_SMEM>>>(Qp, Kh, Vh, Ah);

    gemm_f16<<<dim3(HID / 256, SEQ / 128), 256, G_SMEM>>>(Ah, hWo, out,
                                                          SEQ, HID, HID, 0);
}